// round 3
// baseline (speedup 1.0000x reference)
#include <cuda_runtime.h>
#include <cuda_bf16.h>
#include <math.h>

// ---------------- problem constants ----------------
#define Bv   4
#define Tv   1024
#define Dv   2048
#define Hv   32
#define DHv  64
#define HKv  8
#define Rv   32
#define ROv  1024
#define RFv  1024
#define Iv   5632
#define BT   (Bv*Tv)     // 4096

// ---------------- scratch ----------------
__device__ float g_h1 [BT*Dv];
__device__ float g_qr [BT*(Hv*Rv)];
__device__ float g_kr [BT*(HKv*Rv)];
__device__ float g_vr [BT*(HKv*Rv)];
__device__ float g_q  [Bv*Hv*Tv*DHv];
__device__ float g_k  [Bv*HKv*Tv*DHv];
__device__ float g_v  [Bv*HKv*Tv*DHv];
__device__ float g_ctx[BT*Dv];
__device__ float g_or [BT*ROv];
__device__ float g_x1 [BT*Dv];
__device__ float g_h2 [BT*Dv];
__device__ float g_gr [BT*RFv];
__device__ float g_ur [BT*RFv];
__device__ float g_g  [BT*Iv];
__device__ float g_ff [BT*Iv];
__device__ float g_dr [BT*RFv];
__device__ float g_ropec[Tv*32];
__device__ float g_ropes[Tv*32];

// ---------------- rope table ----------------
__global__ void rope_table_kernel(float* __restrict__ rc, float* __restrict__ rs)
{
    int idx = blockIdx.x * blockDim.x + threadIdx.x;   // t*32 + d
    int t = idx >> 5, d = idx & 31;
    float invf = expf(-0.28782313662425572f * (float)d); // 10000^(-d/32)
    float ang = (float)t * invf;
    rc[idx] = cosf(ang);
    rs[idx] = sinf(ang);
}

// ---------------- RMSNorm ----------------
__global__ void __launch_bounds__(256) rms_kernel(const float* __restrict__ x,
                                                  const float* __restrict__ w,
                                                  float* __restrict__ out)
{
    int row = blockIdx.x;
    int tid = threadIdx.x;
    const float4* xr = (const float4*)(x + (size_t)row * Dv);
    float4 v0 = xr[tid];
    float4 v1 = xr[tid + 256];
    float ss = v0.x*v0.x + v0.y*v0.y + v0.z*v0.z + v0.w*v0.w
             + v1.x*v1.x + v1.y*v1.y + v1.z*v1.z + v1.w*v1.w;
    #pragma unroll
    for (int o = 16; o; o >>= 1) ss += __shfl_xor_sync(0xffffffffu, ss, o);
    __shared__ float red[8];
    if ((tid & 31) == 0) red[tid >> 5] = ss;
    __syncthreads();
    float tot = 0.f;
    #pragma unroll
    for (int i = 0; i < 8; i++) tot += red[i];
    float inv = rsqrtf(tot * (1.0f / Dv) + 1e-5f);
    const float4* wr = (const float4*)w;
    float4 w0 = wr[tid], w1 = wr[tid + 256];
    float4 o0 = { v0.x*inv*w0.x, v0.y*inv*w0.y, v0.z*inv*w0.z, v0.w*inv*w0.w };
    float4 o1 = { v1.x*inv*w1.x, v1.y*inv*w1.y, v1.z*inv*w1.z, v1.w*inv*w1.w };
    float4* orow = (float4*)(out + (size_t)row * Dv);
    orow[tid] = o0;
    orow[tid + 256] = o1;
}

// ---------------- tf32 tensor-core GEMM (4-stage, segmented) ----------------
// C[M,N] = A[M,K] @ B[N,K]^T ; mode 0 plain, 1: +aux, 2: silu(aux)*
#define STAGES 4

#define CP_ASYNC16(dst, src) asm volatile("cp.async.cg.shared.global [%0], [%1], 16;\n" :: "r"(dst), "l"(src))
#define CP_COMMIT() asm volatile("cp.async.commit_group;\n" ::)
#define CP_WAIT(n)  asm volatile("cp.async.wait_group %0;\n" :: "n"(n))

__device__ __forceinline__ unsigned tf32r(float x) {
    unsigned r;
    asm("cvt.rna.tf32.f32 %0, %1;" : "=r"(r) : "f"(x));
    return r;
}

#define MMA_TF32(d, a, b) \
    asm volatile("mma.sync.aligned.m16n8k8.row.col.f32.tf32.tf32.f32 " \
        "{%0,%1,%2,%3}, {%4,%5,%6,%7}, {%8,%9}, {%0,%1,%2,%3};" \
        : "+f"(d[0]), "+f"(d[1]), "+f"(d[2]), "+f"(d[3]) \
        : "r"(a[0]), "r"(a[1]), "r"(a[2]), "r"(a[3]), "r"(b[0]), "r"(b[1]))

__global__ void __launch_bounds__(256) gemm_tc(
    const float* __restrict__ A, int K, int mode, const float* __restrict__ aux,
    const float* __restrict__ B0, float* __restrict__ C0, int N0, int nb0,
    const float* __restrict__ B1, float* __restrict__ C1, int N1, int nb1,
    const float* __restrict__ B2, float* __restrict__ C2, int N2, int nb2)
{
    extern __shared__ float smem[];
    // stage st: As floats [st*4096, +4096), Bs floats [16384 + st*4096, +4096)
    unsigned sbase = (unsigned)__cvta_generic_to_shared(smem);

    int bx = blockIdx.x;
    const float* Bw; float* C; int N; int bnb;
    if (bx < nb0)            { Bw = B0; C = C0; N = N0; bnb = bx; }
    else if (bx < nb0 + nb1) { Bw = B1; C = C1; N = N1; bnb = bx - nb0; }
    else                     { Bw = B2; C = C2; N = N2; bnb = bx - nb0 - nb1; }

    int tid  = threadIdx.x;
    int bm = blockIdx.y * 128;
    int bn = bnb * 128;
    int lane = tid & 31, warp = tid >> 5;
    int wm = warp >> 1, wn = warp & 1;
    int g  = lane >> 2, tig = lane & 3;

    unsigned dstoff[4];
    const float* srcA[4];
    const float* srcB[4];
    #pragma unroll
    for (int i = 0; i < 4; i++) {
        int lin = tid + i * 256;
        int row = lin >> 3, c = lin & 7;
        dstoff[i] = (unsigned)((row * 32 + ((c ^ (row & 7)) << 2)) * 4);
        srcA[i] = A  + (size_t)(bm + row) * K + c * 4;
        srcB[i] = Bw + (size_t)(bn + row) * K + c * 4;
    }

    int ar0[2], ar1[2], a7[2];
    #pragma unroll
    for (int mi = 0; mi < 2; mi++) {
        int r0 = wm * 32 + mi * 16 + g;
        ar0[mi] = r0 * 32 + tig;
        ar1[mi] = (r0 + 8) * 32 + tig;
        a7[mi]  = r0 & 7;
    }
    int bbase[8], b7[8];
    #pragma unroll
    for (int ni = 0; ni < 8; ni++) {
        int n = wn * 64 + ni * 8 + g;
        bbase[ni] = n * 32 + tig;
        b7[ni] = n & 7;
    }

    float acc[2][8][4];
    #pragma unroll
    for (int mi = 0; mi < 2; mi++)
        #pragma unroll
        for (int ni = 0; ni < 8; ni++)
            #pragma unroll
            for (int q = 0; q < 4; q++) acc[mi][ni][q] = 0.f;

    const int NT = K >> 5;

    // prologue: stages 0..STAGES-2
    #pragma unroll
    for (int s = 0; s < STAGES - 1; s++) {
        unsigned da = sbase + (unsigned)s * 16384u;
        unsigned db = sbase + 65536u + (unsigned)s * 16384u;
        #pragma unroll
        for (int i = 0; i < 4; i++) {
            CP_ASYNC16(da + dstoff[i], srcA[i] + (size_t)s * 32);
            CP_ASYNC16(db + dstoff[i], srcB[i] + (size_t)s * 32);
        }
        CP_COMMIT();
    }

    for (int kt = 0; kt < NT; kt++) {
        int st = kt & (STAGES - 1);
        CP_WAIT(STAGES - 2);
        __syncthreads();

        int pf = kt + STAGES - 1;
        if (pf < NT) {
            int pst = pf & (STAGES - 1);
            unsigned da = sbase + (unsigned)pst * 16384u;
            unsigned db = sbase + 65536u + (unsigned)pst * 16384u;
            #pragma unroll
            for (int i = 0; i < 4; i++) {
                CP_ASYNC16(da + dstoff[i], srcA[i] + (size_t)pf * 32);
                CP_ASYNC16(db + dstoff[i], srcB[i] + (size_t)pf * 32);
            }
        }
        CP_COMMIT();

        const float* AsF = smem + st * 4096;
        const float* BsF = smem + 16384 + st * 4096;

        #pragma unroll
        for (int s = 0; s < 4; s++) {
            int c0 = 2 * s, c1 = 2 * s + 1;
            unsigned af[2][4];
            #pragma unroll
            for (int mi = 0; mi < 2; mi++) {
                int o0 = (c0 ^ a7[mi]) << 2;
                int o1 = (c1 ^ a7[mi]) << 2;
                af[mi][0] = tf32r(AsF[ar0[mi] + o0]);
                af[mi][1] = tf32r(AsF[ar1[mi] + o0]);
                af[mi][2] = tf32r(AsF[ar0[mi] + o1]);
                af[mi][3] = tf32r(AsF[ar1[mi] + o1]);
            }
            unsigned bf[8][2];
            #pragma unroll
            for (int ni = 0; ni < 8; ni++) {
                bf[ni][0] = tf32r(BsF[bbase[ni] + ((c0 ^ b7[ni]) << 2)]);
                bf[ni][1] = tf32r(BsF[bbase[ni] + ((c1 ^ b7[ni]) << 2)]);
            }
            #pragma unroll
            for (int mi = 0; mi < 2; mi++)
                #pragma unroll
                for (int ni = 0; ni < 8; ni++)
                    MMA_TF32(acc[mi][ni], af[mi], bf[ni]);
        }
    }

    // --- epilogue ---
    #pragma unroll
    for (int mi = 0; mi < 2; mi++) {
        int row0 = bm + wm * 32 + mi * 16 + g;
        #pragma unroll
        for (int half = 0; half < 2; half++) {
            int row = row0 + half * 8;
            size_t rowoff = (size_t)row * N;
            #pragma unroll
            for (int ni = 0; ni < 8; ni++) {
                int col = bn + wn * 64 + ni * 8 + 2 * tig;
                size_t idx = rowoff + col;
                float vx = acc[mi][ni][half * 2 + 0];
                float vy = acc[mi][ni][half * 2 + 1];
                if (mode == 1) {
                    float2 rsd = *(const float2*)(aux + idx);
                    vx += rsd.x; vy += rsd.y;
                } else if (mode == 2) {
                    float2 gg = *(const float2*)(aux + idx);
                    vx *= gg.x / (1.f + __expf(-gg.x));
                    vy *= gg.y / (1.f + __expf(-gg.y));
                }
                float2 o = { vx, vy };
                *(float2*)(C + idx) = o;
            }
        }
    }
}

// ---------------- per-head Us projection (+ optional RoPE) ----------------
__global__ void __launch_bounds__(256) usproj_kernel(const float* __restrict__ in,
                                                     const float* __restrict__ Us,
                                                     float* __restrict__ out,
                                                     const float* __restrict__ rc,
                                                     const float* __restrict__ rs,
                                                     int heads, int rope)
{
    __shared__ __align__(16) float inT[32][64];
    __shared__ __align__(16) float UsT[32][64];
    __shared__ __align__(16) float os [64][64];
    int h = blockIdx.y;
    int bt0 = blockIdx.x * 64;
    int tid = threadIdx.x;
    int ldin = heads * 32;

    {
        int d = tid >> 2; int r0 = (tid & 3) * 8;
        const float* p = Us + ((size_t)h * 64 + d) * 32 + r0;
        float4 u0 = *(const float4*)p;
        float4 u1 = *(const float4*)(p + 4);
        UsT[r0+0][d]=u0.x; UsT[r0+1][d]=u0.y; UsT[r0+2][d]=u0.z; UsT[r0+3][d]=u0.w;
        UsT[r0+4][d]=u1.x; UsT[r0+5][d]=u1.y; UsT[r0+6][d]=u1.z; UsT[r0+7][d]=u1.w;
    }
    {
        int i = tid >> 2; int r0 = (tid & 3) * 8;
        const float* p = in + (size_t)(bt0 + i) * ldin + h * 32 + r0;
        float4 a0 = *(const float4*)p;
        float4 a1 = *(const float4*)(p + 4);
        inT[r0+0][i]=a0.x; inT[r0+1][i]=a0.y; inT[r0+2][i]=a0.z; inT[r0+3][i]=a0.w;
        inT[r0+4][i]=a1.x; inT[r0+5][i]=a1.y; inT[r0+6][i]=a1.z; inT[r0+7][i]=a1.w;
    }
    __syncthreads();

    int tx = tid & 15, ty = tid >> 4;
    float acc[4][4] = {};
    #pragma unroll
    for (int r = 0; r < 32; r++) {
        float4 a = *(const float4*)&inT[r][ty*4];
        float4 b = *(const float4*)&UsT[r][tx*4];
        float av[4] = {a.x,a.y,a.z,a.w};
        float bv[4] = {b.x,b.y,b.z,b.w};
        #pragma unroll
        for (int rr = 0; rr < 4; rr++)
            #pragma unroll
            for (int cc = 0; cc < 4; cc++)
                acc[rr][cc] = fmaf(av[rr], bv[cc], acc[rr][cc]);
    }
    #pragma unroll
    for (int rr = 0; rr < 4; rr++)
        #pragma unroll
        for (int cc = 0; cc < 4; cc++)
            os[ty*4+rr][tx*4+cc] = acc[rr][cc];
    __syncthreads();

    if (!rope) {
        #pragma unroll
        for (int kk = 0; kk < 4; kk++) {
            int lin4 = tid + kk * 256;
            int i = lin4 >> 4; int d0 = (lin4 & 15) * 4;
            int bt = bt0 + i; int b = bt >> 10; int t = bt & 1023;
            float4 vv = *(const float4*)&os[i][d0];
            size_t addr = (((size_t)(b * heads + h)) * Tv + t) * 64 + d0;
            *(float4*)(out + addr) = vv;
        }
    } else {
        #pragma unroll
        for (int kk = 0; kk < 2; kk++) {
            int lin4 = tid + kk * 256;
            int i = lin4 >> 3; int d0 = (lin4 & 7) * 4;
            int bt = bt0 + i; int b = bt >> 10; int t = bt & 1023;
            float4 x1 = *(const float4*)&os[i][d0];
            float4 x2 = *(const float4*)&os[i][d0 + 32];
            float4 cc4 = *(const float4*)(rc + t * 32 + d0);
            float4 ss4 = *(const float4*)(rs + t * 32 + d0);
            float xx1[4] = {x1.x,x1.y,x1.z,x1.w};
            float xx2[4] = {x2.x,x2.y,x2.z,x2.w};
            float ca[4] = {cc4.x,cc4.y,cc4.z,cc4.w};
            float sa[4] = {ss4.x,ss4.y,ss4.z,ss4.w};
            float o1[4], o2[4];
            #pragma unroll
            for (int c = 0; c < 4; c++) {
                o1[c] = xx1[c] * ca[c] - xx2[c] * sa[c];
                o2[c] = xx2[c] * ca[c] + xx1[c] * sa[c];
            }
            size_t base = (((size_t)(b * heads + h)) * Tv + t) * 64;
            float4 w1 = {o1[0],o1[1],o1[2],o1[3]};
            float4 w2 = {o2[0],o2[1],o2[2],o2[3]};
            *(float4*)(out + base + d0)      = w1;
            *(float4*)(out + base + d0 + 32) = w2;
        }
    }
}

// ---------------- flash attention (causal, GQA 4:1), fp32 ----------------
__global__ void __launch_bounds__(256) attn_kernel(const float* __restrict__ q,
                                                   const float* __restrict__ k,
                                                   const float* __restrict__ v,
                                                   float* __restrict__ ctx)
{
    __shared__ __align__(16) float QsT[64][64];
    __shared__ __align__(16) float KsT[64][32];
    __shared__ __align__(16) float Vs [32][64];
    __shared__ __align__(16) float Ss [64][33];
    __shared__ float mrow[64], lrow[64], rsrow[64];

    int tid = threadIdx.x;
    int bh = blockIdx.y; int b = bh >> 5; int h = bh & 31; int hk = h >> 2;
    int q0 = blockIdx.x * 64;

    const float* qbase = q + (((size_t)(b * 32 + h)) * Tv + q0) * 64;
    #pragma unroll
    for (int kk = 0; kk < 4; kk++) {
        int lin4 = tid + kk * 256;
        int i = lin4 >> 4; int d0 = (lin4 & 15) * 4;
        float4 qv = *(const float4*)(qbase + (size_t)i * 64 + d0);
        QsT[d0+0][i] = qv.x * 0.125f;
        QsT[d0+1][i] = qv.y * 0.125f;
        QsT[d0+2][i] = qv.z * 0.125f;
        QsT[d0+3][i] = qv.w * 0.125f;
    }
    if (tid < 64) { mrow[tid] = -INFINITY; lrow[tid] = 0.f; }

    float acc[4][4] = {};
    int tx = tid & 15, ty = tid >> 4;
    int txs = tid & 7, tys = tid >> 3;
    const float* kbase0 = k + ((size_t)(b * 8 + hk)) * Tv * 64;
    const float* vbase0 = v + ((size_t)(b * 8 + hk)) * Tv * 64;

    int ntile = (q0 >> 5) + 2;
    for (int kt = 0; kt < ntile; kt++) {
        __syncthreads();
        #pragma unroll
        for (int kk = 0; kk < 2; kk++) {
            int lin4 = tid + kk * 256;
            int j = lin4 >> 4; int d0 = (lin4 & 15) * 4;
            size_t off = ((size_t)(kt * 32 + j)) * 64 + d0;
            float4 kv = *(const float4*)(kbase0 + off);
            KsT[d0+0][j] = kv.x; KsT[d0+1][j] = kv.y;
            KsT[d0+2][j] = kv.z; KsT[d0+3][j] = kv.w;
            float4 vv = *(const float4*)(vbase0 + off);
            *(float4*)&Vs[j][d0] = vv;
        }
        __syncthreads();

        float s[2][4] = {};
        int i0 = tys * 2;
        #pragma unroll
        for (int d = 0; d < 64; d++) {
            float a0 = QsT[d][i0], a1 = QsT[d][i0 + 1];
            float4 bb = *(const float4*)&KsT[d][txs * 4];
            s[0][0] = fmaf(a0, bb.x, s[0][0]); s[0][1] = fmaf(a0, bb.y, s[0][1]);
            s[0][2] = fmaf(a0, bb.z, s[0][2]); s[0][3] = fmaf(a0, bb.w, s[0][3]);
            s[1][0] = fmaf(a1, bb.x, s[1][0]); s[1][1] = fmaf(a1, bb.y, s[1][1]);
            s[1][2] = fmaf(a1, bb.z, s[1][2]); s[1][3] = fmaf(a1, bb.w, s[1][3]);
        }
        #pragma unroll
        for (int r = 0; r < 2; r++)
            #pragma unroll
            for (int c = 0; c < 4; c++) {
                int qi = q0 + i0 + r, ki = kt * 32 + txs * 4 + c;
                Ss[i0 + r][txs * 4 + c] = (ki <= qi) ? s[r][c] : -INFINITY;
            }
        __syncthreads();

        // parallel online-softmax: 4 lanes per row, 8 cols each
        {
            int row = tid >> 2, part = tid & 3;
            float* sr = &Ss[row][part * 8];
            float mo = mrow[row];
            float pv[8];
            float mx = mo;
            #pragma unroll
            for (int j = 0; j < 8; j++) { pv[j] = sr[j]; mx = fmaxf(mx, pv[j]); }
            mx = fmaxf(mx, __shfl_xor_sync(0xffffffffu, mx, 1));
            mx = fmaxf(mx, __shfl_xor_sync(0xffffffffu, mx, 2));
            float sum = 0.f;
            #pragma unroll
            for (int j = 0; j < 8; j++) {
                float p = __expf(pv[j] - mx);
                sr[j] = p; sum += p;
            }
            sum += __shfl_xor_sync(0xffffffffu, sum, 1);
            sum += __shfl_xor_sync(0xffffffffu, sum, 2);
            if (part == 0) {
                float rsc = __expf(mo - mx);
                mrow[row] = mx;
                lrow[row] = lrow[row] * rsc + sum;
                rsrow[row] = rsc;
            }
        }
        __syncthreads();

        #pragma unroll
        for (int r = 0; r < 4; r++) {
            float rr = rsrow[ty * 4 + r];
            #pragma unroll
            for (int c = 0; c < 4; c++) acc[r][c] *= rr;
        }
        #pragma unroll 4
        for (int j = 0; j < 32; j++) {
            float4 vv = *(const float4*)&Vs[j][tx * 4];
            #pragma unroll
            for (int r = 0; r < 4; r++) {
                float p = Ss[ty * 4 + r][j];
                acc[r][0] = fmaf(p, vv.x, acc[r][0]);
                acc[r][1] = fmaf(p, vv.y, acc[r][1]);
                acc[r][2] = fmaf(p, vv.z, acc[r][2]);
                acc[r][3] = fmaf(p, vv.w, acc[r][3]);
            }
        }
    }
    __syncthreads();

    #pragma unroll
    for (int r = 0; r < 4; r++) {
        int i = ty * 4 + r;
        float inv = 1.f / lrow[i];
        size_t addr = ((size_t)(b * Tv + q0 + i)) * Dv + h * 64 + tx * 4;
        float4 o = { acc[r][0]*inv, acc[r][1]*inv, acc[r][2]*inv, acc[r][3]*inv };
        *(float4*)(ctx + addr) = o;
    }
}

// ---------------- launch ----------------
extern "C" void kernel_launch(void* const* d_in, const int* in_sizes, int n_in,
                              void* d_out, int out_size)
{
    const float* x     = (const float*)d_in[0];
    const float* ln1_w = (const float*)d_in[1];
    const float* ln2_w = (const float*)d_in[2];
    const float* q_Us  = (const float*)d_in[3];
    const float* q_V   = (const float*)d_in[4];
    const float* k_Us  = (const float*)d_in[5];
    const float* k_V   = (const float*)d_in[6];
    const float* v_Us  = (const float*)d_in[7];
    const float* v_V   = (const float*)d_in[8];
    const float* o_Us  = (const float*)d_in[9];
    const float* o_V   = (const float*)d_in[10];
    const float* g_Usw = (const float*)d_in[11];
    const float* g_Vw  = (const float*)d_in[12];
    const float* u_Usw = (const float*)d_in[13];
    const float* u_Vw  = (const float*)d_in[14];
    const float* d_Usw = (const float*)d_in[15];
    const float* d_Vw  = (const float*)d_in[16];
    float* out = (float*)d_out;

    float *h1, *qr, *kr, *vr, *qb, *kb, *vb, *ctx, *orr, *x1, *h2, *gr, *ur, *gg, *ff, *dr, *rc, *rs;
    cudaGetSymbolAddress((void**)&h1,  g_h1);
    cudaGetSymbolAddress((void**)&qr,  g_qr);
    cudaGetSymbolAddress((void**)&kr,  g_kr);
    cudaGetSymbolAddress((void**)&vr,  g_vr);
    cudaGetSymbolAddress((void**)&qb,  g_q);
    cudaGetSymbolAddress((void**)&kb,  g_k);
    cudaGetSymbolAddress((void**)&vb,  g_v);
    cudaGetSymbolAddress((void**)&ctx, g_ctx);
    cudaGetSymbolAddress((void**)&orr, g_or);
    cudaGetSymbolAddress((void**)&x1,  g_x1);
    cudaGetSymbolAddress((void**)&h2,  g_h2);
    cudaGetSymbolAddress((void**)&gr,  g_gr);
    cudaGetSymbolAddress((void**)&ur,  g_ur);
    cudaGetSymbolAddress((void**)&gg,  g_g);
    cudaGetSymbolAddress((void**)&ff,  g_ff);
    cudaGetSymbolAddress((void**)&dr,  g_dr);
    cudaGetSymbolAddress((void**)&rc,  g_ropec);
    cudaGetSymbolAddress((void**)&rs,  g_ropes);

    static int smem_set = 0;
    if (!smem_set) {
        cudaFuncSetAttribute(gemm_tc, cudaFuncAttributeMaxDynamicSharedMemorySize, 131072);
        smem_set = 1;
    }
    const int SM = 131072;
    dim3 blk(256);

    rope_table_kernel<<<Tv*32/256, 256>>>(rc, rs);
    rms_kernel<<<BT, blk>>>(x, ln1_w, h1);

    // fused q/k/v rank projections: N segs 1024/256/256 -> 12 x 32 blocks
    gemm_tc<<<dim3(12, 32), blk, SM>>>(h1, Dv, 0, nullptr,
        q_V, qr, Hv*Rv, 8,  k_V, kr, HKv*Rv, 2,  v_V, vr, HKv*Rv, 2);

    usproj_kernel<<<dim3(BT/64, Hv),  blk>>>(qr, q_Us, qb, rc, rs, Hv, 1);
    usproj_kernel<<<dim3(BT/64, HKv), blk>>>(kr, k_Us, kb, rc, rs, HKv, 1);
    usproj_kernel<<<dim3(BT/64, HKv), blk>>>(vr, v_Us, vb, rc, rs, HKv, 0);

    attn_kernel<<<dim3(Tv/64, Bv*Hv), blk>>>(qb, kb, vb, ctx);

    gemm_tc<<<dim3(8, 32), blk, SM>>>(ctx, Dv, 0, nullptr,
        o_V, orr, ROv, 8,  nullptr, nullptr, 0, 0,  nullptr, nullptr, 0, 0);
    gemm_tc<<<dim3(16, 32), blk, SM>>>(orr, ROv, 1, x,
        o_Us, x1, Dv, 16,  nullptr, nullptr, 0, 0,  nullptr, nullptr, 0, 0);

    rms_kernel<<<BT, blk>>>(x1, ln2_w, h2);

    // fused g/u rank projections
    gemm_tc<<<dim3(16, 32), blk, SM>>>(h2, Dv, 0, nullptr,
        g_Vw, gr, RFv, 8,  u_Vw, ur, RFv, 8,  nullptr, nullptr, 0, 0);

    gemm_tc<<<dim3(44, 32), blk, SM>>>(gr, RFv, 0, nullptr,
        g_Usw, gg, Iv, 44,  nullptr, nullptr, 0, 0,  nullptr, nullptr, 0, 0);
    gemm_tc<<<dim3(44, 32), blk, SM>>>(ur, RFv, 2, gg,
        u_Usw, ff, Iv, 44,  nullptr, nullptr, 0, 0,  nullptr, nullptr, 0, 0);

    gemm_tc<<<dim3(8, 32), blk, SM>>>(ff, Iv, 0, nullptr,
        d_Vw, dr, RFv, 8,  nullptr, nullptr, 0, 0,  nullptr, nullptr, 0, 0);
    gemm_tc<<<dim3(16, 32), blk, SM>>>(dr, RFv, 1, x1,
        d_Usw, out, Dv, 16,  nullptr, nullptr, 0, 0,  nullptr, nullptr, 0, 0);
}

// round 4
// speedup vs baseline: 1.1866x; 1.1866x over previous
#include <cuda_runtime.h>
#include <cuda_bf16.h>
#include <math.h>

// ---------------- problem constants ----------------
#define Bv   4
#define Tv   1024
#define Dv   2048
#define Hv   32
#define DHv  64
#define HKv  8
#define Rv   32
#define ROv  1024
#define RFv  1024
#define Iv   5632
#define BT   (Bv*Tv)     // 4096

// ---------------- scratch ----------------
__device__ float g_h1 [BT*Dv];
__device__ float g_qr [BT*(Hv*Rv)];
__device__ float g_kr [BT*(HKv*Rv)];
__device__ float g_vr [BT*(HKv*Rv)];
__device__ float g_q  [Bv*Hv*Tv*DHv];
__device__ float g_k  [Bv*HKv*Tv*DHv];
__device__ float g_v  [Bv*HKv*Tv*DHv];
__device__ float g_ctx[BT*Dv];
__device__ float g_or [BT*ROv];
__device__ float g_x1 [BT*Dv];
__device__ float g_h2 [BT*Dv];
__device__ float g_gr [BT*RFv];
__device__ float g_ur [BT*RFv];
__device__ float g_g  [BT*Iv];
__device__ float g_ff [BT*Iv];
__device__ float g_dr [BT*RFv];
__device__ float g_ropec[Tv*32];
__device__ float g_ropes[Tv*32];
// rounded weights (concatenated)
#define W_QV   0
#define W_KV   2097152
#define W_VV   2621440
#define W_OV   3145728
#define W_OUS  5242880
#define W_GV   7340032
#define W_UV   9437184
#define W_GUS  11534336
#define W_UUS  17301504
#define W_DV   23068672
#define W_DUS  28835840
#define W_TOT  30932992
__device__ float g_wts[W_TOT];

// ---------------- tf32 rounding helpers ----------------
__device__ __forceinline__ float tf32f(float x) {
    unsigned u;
    asm("cvt.rna.tf32.f32 %0, %1;" : "=r"(u) : "f"(x));
    return __uint_as_float(u);
}

__global__ void __launch_bounds__(256) tf32_round_kernel(const float* __restrict__ src,
                                                         float* __restrict__ dst)
{
    int i = (blockIdx.x * 256 + threadIdx.x) * 4;
    float4 v = *(const float4*)(src + i);
    v.x = tf32f(v.x); v.y = tf32f(v.y); v.z = tf32f(v.z); v.w = tf32f(v.w);
    *(float4*)(dst + i) = v;
}

// ---------------- rope table ----------------
__global__ void rope_table_kernel(float* __restrict__ rc, float* __restrict__ rs)
{
    int idx = blockIdx.x * blockDim.x + threadIdx.x;
    int t = idx >> 5, d = idx & 31;
    float invf = expf(-0.28782313662425572f * (float)d);
    float ang = (float)t * invf;
    rc[idx] = cosf(ang);
    rs[idx] = sinf(ang);
}

// ---------------- RMSNorm (tf32-rounded output) ----------------
__global__ void __launch_bounds__(256) rms_kernel(const float* __restrict__ x,
                                                  const float* __restrict__ w,
                                                  float* __restrict__ out)
{
    int row = blockIdx.x;
    int tid = threadIdx.x;
    const float4* xr = (const float4*)(x + (size_t)row * Dv);
    float4 v0 = xr[tid];
    float4 v1 = xr[tid + 256];
    float ss = v0.x*v0.x + v0.y*v0.y + v0.z*v0.z + v0.w*v0.w
             + v1.x*v1.x + v1.y*v1.y + v1.z*v1.z + v1.w*v1.w;
    #pragma unroll
    for (int o = 16; o; o >>= 1) ss += __shfl_xor_sync(0xffffffffu, ss, o);
    __shared__ float red[8];
    if ((tid & 31) == 0) red[tid >> 5] = ss;
    __syncthreads();
    float tot = 0.f;
    #pragma unroll
    for (int i = 0; i < 8; i++) tot += red[i];
    float inv = rsqrtf(tot * (1.0f / Dv) + 1e-5f);
    const float4* wr = (const float4*)w;
    float4 w0 = wr[tid], w1 = wr[tid + 256];
    float4 o0 = { tf32f(v0.x*inv*w0.x), tf32f(v0.y*inv*w0.y), tf32f(v0.z*inv*w0.z), tf32f(v0.w*inv*w0.w) };
    float4 o1 = { tf32f(v1.x*inv*w1.x), tf32f(v1.y*inv*w1.y), tf32f(v1.z*inv*w1.z), tf32f(v1.w*inv*w1.w) };
    float4* orow = (float4*)(out + (size_t)row * Dv);
    orow[tid] = o0;
    orow[tid + 256] = o1;
}

// ---------------- tf32 tensor-core GEMM (3-stage, segmented) ----------------
// C[M,N] = A[M,K] @ B[N,K]^T
// mode&3: 0 plain, 1: +aux, 2: silu(aux)*  ;  mode&4: round output to tf32
#define STAGES 3

#define CP_ASYNC16(dst, src) asm volatile("cp.async.cg.shared.global [%0], [%1], 16;\n" :: "r"(dst), "l"(src))
#define CP_COMMIT() asm volatile("cp.async.commit_group;\n" ::)
#define CP_WAIT(n)  asm volatile("cp.async.wait_group %0;\n" :: "n"(n))

#define MMA_TF32(d, a, b) \
    asm volatile("mma.sync.aligned.m16n8k8.row.col.f32.tf32.tf32.f32 " \
        "{%0,%1,%2,%3}, {%4,%5,%6,%7}, {%8,%9}, {%0,%1,%2,%3};" \
        : "+f"(d[0]), "+f"(d[1]), "+f"(d[2]), "+f"(d[3]) \
        : "r"(a[0]), "r"(a[1]), "r"(a[2]), "r"(a[3]), "r"(b[0]), "r"(b[1]))

__global__ void __launch_bounds__(256, 2) gemm_tc(
    const float* __restrict__ A, int K, int mode, const float* __restrict__ aux,
    const float* __restrict__ B0, float* __restrict__ C0, int N0, int nb0,
    const float* __restrict__ B1, float* __restrict__ C1, int N1, int nb1,
    const float* __restrict__ B2, float* __restrict__ C2, int N2, int nb2)
{
    extern __shared__ float smem[];
    // stage st: As floats [st*8192, +4096), Bs floats [st*8192+4096, +4096)
    unsigned sbase = (unsigned)__cvta_generic_to_shared(smem);

    int bx = blockIdx.x;
    const float* Bw; float* C; int N; int bnb;
    if (bx < nb0)            { Bw = B0; C = C0; N = N0; bnb = bx; }
    else if (bx < nb0 + nb1) { Bw = B1; C = C1; N = N1; bnb = bx - nb0; }
    else                     { Bw = B2; C = C2; N = N2; bnb = bx - nb0 - nb1; }

    int tid  = threadIdx.x;
    int bm = blockIdx.y * 128;
    int bn = bnb * 128;
    int lane = tid & 31, warp = tid >> 5;
    int wm = warp >> 1, wn = warp & 1;
    int g  = lane >> 2, tig = lane & 3;

    unsigned dstoff[4];
    const float* srcA[4];
    const float* srcB[4];
    #pragma unroll
    for (int i = 0; i < 4; i++) {
        int lin = tid + i * 256;
        int row = lin >> 3, c = lin & 7;
        dstoff[i] = (unsigned)((row * 32 + ((c ^ (row & 7)) << 2)) * 4);
        srcA[i] = A  + (size_t)(bm + row) * K + c * 4;
        srcB[i] = Bw + (size_t)(bn + row) * K + c * 4;
    }

    int ar0[2], ar1[2], a7[2];
    #pragma unroll
    for (int mi = 0; mi < 2; mi++) {
        int r0 = wm * 32 + mi * 16 + g;
        ar0[mi] = r0 * 32 + tig;
        ar1[mi] = (r0 + 8) * 32 + tig;
        a7[mi]  = r0 & 7;
    }
    int bbase[8], b7[8];
    #pragma unroll
    for (int ni = 0; ni < 8; ni++) {
        int n = wn * 64 + ni * 8 + g;
        bbase[ni] = n * 32 + tig;
        b7[ni] = n & 7;
    }

    float acc[2][8][4];
    #pragma unroll
    for (int mi = 0; mi < 2; mi++)
        #pragma unroll
        for (int ni = 0; ni < 8; ni++)
            #pragma unroll
            for (int q = 0; q < 4; q++) acc[mi][ni][q] = 0.f;

    const int NT = K >> 5;

    // prologue: stages 0..1
    #pragma unroll
    for (int s = 0; s < STAGES - 1; s++) {
        unsigned da = sbase + (unsigned)s * 32768u;
        unsigned db = da + 16384u;
        #pragma unroll
        for (int i = 0; i < 4; i++) {
            CP_ASYNC16(da + dstoff[i], srcA[i] + (size_t)s * 32);
            CP_ASYNC16(db + dstoff[i], srcB[i] + (size_t)s * 32);
        }
        CP_COMMIT();
    }

    for (int kt = 0; kt < NT; kt++) {
        int st = kt % STAGES;
        CP_WAIT(STAGES - 2);
        __syncthreads();

        int pf = kt + STAGES - 1;
        if (pf < NT) {
            int pst = pf % STAGES;
            unsigned da = sbase + (unsigned)pst * 32768u;
            unsigned db = da + 16384u;
            #pragma unroll
            for (int i = 0; i < 4; i++) {
                CP_ASYNC16(da + dstoff[i], srcA[i] + (size_t)pf * 32);
                CP_ASYNC16(db + dstoff[i], srcB[i] + (size_t)pf * 32);
            }
        }
        CP_COMMIT();

        const unsigned* AsU = (const unsigned*)smem + st * 8192;
        const unsigned* BsU = AsU + 4096;

        #pragma unroll
        for (int s = 0; s < 4; s++) {
            int c0 = 2 * s, c1 = 2 * s + 1;
            unsigned af[2][4];
            #pragma unroll
            for (int mi = 0; mi < 2; mi++) {
                int o0 = (c0 ^ a7[mi]) << 2;
                int o1 = (c1 ^ a7[mi]) << 2;
                af[mi][0] = AsU[ar0[mi] + o0];
                af[mi][1] = AsU[ar1[mi] + o0];
                af[mi][2] = AsU[ar0[mi] + o1];
                af[mi][3] = AsU[ar1[mi] + o1];
            }
            unsigned bf[8][2];
            #pragma unroll
            for (int ni = 0; ni < 8; ni++) {
                bf[ni][0] = BsU[bbase[ni] + ((c0 ^ b7[ni]) << 2)];
                bf[ni][1] = BsU[bbase[ni] + ((c1 ^ b7[ni]) << 2)];
            }
            #pragma unroll
            for (int mi = 0; mi < 2; mi++)
                #pragma unroll
                for (int ni = 0; ni < 8; ni++)
                    MMA_TF32(acc[mi][ni], af[mi], bf[ni]);
        }
    }

    // --- epilogue ---
    int emode = mode & 3;
    int rnd = mode & 4;
    #pragma unroll
    for (int mi = 0; mi < 2; mi++) {
        int row0 = bm + wm * 32 + mi * 16 + g;
        #pragma unroll
        for (int half = 0; half < 2; half++) {
            int row = row0 + half * 8;
            size_t rowoff = (size_t)row * N;
            #pragma unroll
            for (int ni = 0; ni < 8; ni++) {
                int col = bn + wn * 64 + ni * 8 + 2 * tig;
                size_t idx = rowoff + col;
                float vx = acc[mi][ni][half * 2 + 0];
                float vy = acc[mi][ni][half * 2 + 1];
                if (emode == 1) {
                    float2 rsd = *(const float2*)(aux + idx);
                    vx += rsd.x; vy += rsd.y;
                } else if (emode == 2) {
                    float2 gg = *(const float2*)(aux + idx);
                    vx *= gg.x / (1.f + __expf(-gg.x));
                    vy *= gg.y / (1.f + __expf(-gg.y));
                }
                if (rnd) { vx = tf32f(vx); vy = tf32f(vy); }
                float2 o = { vx, vy };
                *(float2*)(C + idx) = o;
            }
        }
    }
}

// ---------------- fused per-head Us projection (+ optional RoPE) ----------------
// y<32: q (heads=32, rope) ; 32..39: k (heads=8, rope) ; 40..47: v (heads=8)
__global__ void __launch_bounds__(256) usproj_fused(
    const float* __restrict__ qr, const float* __restrict__ kr, const float* __restrict__ vr,
    const float* __restrict__ qUs, const float* __restrict__ kUs, const float* __restrict__ vUs,
    float* __restrict__ qb, float* __restrict__ kb, float* __restrict__ vb,
    const float* __restrict__ rc, const float* __restrict__ rs)
{
    __shared__ __align__(16) float inT[32][64];
    __shared__ __align__(16) float UsT[32][64];
    __shared__ __align__(16) float os [64][64];
    int y = blockIdx.y;
    const float* in; const float* Us; float* out; int heads, h, rope;
    if (y < 32)      { in = qr; Us = qUs; out = qb; heads = 32; h = y;      rope = 1; }
    else if (y < 40) { in = kr; Us = kUs; out = kb; heads = 8;  h = y - 32; rope = 1; }
    else             { in = vr; Us = vUs; out = vb; heads = 8;  h = y - 40; rope = 0; }

    int bt0 = blockIdx.x * 64;
    int tid = threadIdx.x;
    int ldin = heads * 32;

    {
        int d = tid >> 2; int r0 = (tid & 3) * 8;
        const float* p = Us + ((size_t)h * 64 + d) * 32 + r0;
        float4 u0 = *(const float4*)p;
        float4 u1 = *(const float4*)(p + 4);
        UsT[r0+0][d]=u0.x; UsT[r0+1][d]=u0.y; UsT[r0+2][d]=u0.z; UsT[r0+3][d]=u0.w;
        UsT[r0+4][d]=u1.x; UsT[r0+5][d]=u1.y; UsT[r0+6][d]=u1.z; UsT[r0+7][d]=u1.w;
    }
    {
        int i = tid >> 2; int r0 = (tid & 3) * 8;
        const float* p = in + (size_t)(bt0 + i) * ldin + h * 32 + r0;
        float4 a0 = *(const float4*)p;
        float4 a1 = *(const float4*)(p + 4);
        inT[r0+0][i]=a0.x; inT[r0+1][i]=a0.y; inT[r0+2][i]=a0.z; inT[r0+3][i]=a0.w;
        inT[r0+4][i]=a1.x; inT[r0+5][i]=a1.y; inT[r0+6][i]=a1.z; inT[r0+7][i]=a1.w;
    }
    __syncthreads();

    int tx = tid & 15, ty = tid >> 4;
    float acc[4][4] = {};
    #pragma unroll
    for (int r = 0; r < 32; r++) {
        float4 a = *(const float4*)&inT[r][ty*4];
        float4 b = *(const float4*)&UsT[r][tx*4];
        float av[4] = {a.x,a.y,a.z,a.w};
        float bv[4] = {b.x,b.y,b.z,b.w};
        #pragma unroll
        for (int rr = 0; rr < 4; rr++)
            #pragma unroll
            for (int cc = 0; cc < 4; cc++)
                acc[rr][cc] = fmaf(av[rr], bv[cc], acc[rr][cc]);
    }
    #pragma unroll
    for (int rr = 0; rr < 4; rr++)
        #pragma unroll
        for (int cc = 0; cc < 4; cc++)
            os[ty*4+rr][tx*4+cc] = acc[rr][cc];
    __syncthreads();

    if (!rope) {
        #pragma unroll
        for (int kk = 0; kk < 4; kk++) {
            int lin4 = tid + kk * 256;
            int i = lin4 >> 4; int d0 = (lin4 & 15) * 4;
            int bt = bt0 + i; int b = bt >> 10; int t = bt & 1023;
            float4 vv = *(const float4*)&os[i][d0];
            size_t addr = (((size_t)(b * heads + h)) * Tv + t) * 64 + d0;
            *(float4*)(out + addr) = vv;
        }
    } else {
        #pragma unroll
        for (int kk = 0; kk < 2; kk++) {
            int lin4 = tid + kk * 256;
            int i = lin4 >> 3; int d0 = (lin4 & 7) * 4;
            int bt = bt0 + i; int b = bt >> 10; int t = bt & 1023;
            float4 x1 = *(const float4*)&os[i][d0];
            float4 x2 = *(const float4*)&os[i][d0 + 32];
            float4 cc4 = *(const float4*)(rc + t * 32 + d0);
            float4 ss4 = *(const float4*)(rs + t * 32 + d0);
            float xx1[4] = {x1.x,x1.y,x1.z,x1.w};
            float xx2[4] = {x2.x,x2.y,x2.z,x2.w};
            float ca[4] = {cc4.x,cc4.y,cc4.z,cc4.w};
            float sa[4] = {ss4.x,ss4.y,ss4.z,ss4.w};
            float o1[4], o2[4];
            #pragma unroll
            for (int c = 0; c < 4; c++) {
                o1[c] = xx1[c] * ca[c] - xx2[c] * sa[c];
                o2[c] = xx2[c] * ca[c] + xx1[c] * sa[c];
            }
            size_t base = (((size_t)(b * heads + h)) * Tv + t) * 64;
            float4 w1 = {o1[0],o1[1],o1[2],o1[3]};
            float4 w2 = {o2[0],o2[1],o2[2],o2[3]};
            *(float4*)(out + base + d0)      = w1;
            *(float4*)(out + base + d0 + 32) = w2;
        }
    }
}

// ---------------- flash attention (causal, GQA 4:1), fp32 ----------------
__global__ void __launch_bounds__(256) attn_kernel(const float* __restrict__ q,
                                                   const float* __restrict__ k,
                                                   const float* __restrict__ v,
                                                   float* __restrict__ ctx)
{
    __shared__ __align__(16) float QsT[64][64];
    __shared__ __align__(16) float KsT[64][32];
    __shared__ __align__(16) float Vs [32][64];
    __shared__ __align__(16) float Ss [64][33];
    __shared__ float mrow[64], lrow[64], rsrow[64];

    int tid = threadIdx.x;
    int bh = blockIdx.y; int b = bh >> 5; int h = bh & 31; int hk = h >> 2;
    int q0 = blockIdx.x * 64;

    const float* qbase = q + (((size_t)(b * 32 + h)) * Tv + q0) * 64;
    #pragma unroll
    for (int kk = 0; kk < 4; kk++) {
        int lin4 = tid + kk * 256;
        int i = lin4 >> 4; int d0 = (lin4 & 15) * 4;
        float4 qv = *(const float4*)(qbase + (size_t)i * 64 + d0);
        QsT[d0+0][i] = qv.x * 0.125f;
        QsT[d0+1][i] = qv.y * 0.125f;
        QsT[d0+2][i] = qv.z * 0.125f;
        QsT[d0+3][i] = qv.w * 0.125f;
    }
    if (tid < 64) { mrow[tid] = -INFINITY; lrow[tid] = 0.f; }

    float acc[4][4] = {};
    int tx = tid & 15, ty = tid >> 4;
    int txs = tid & 7, tys = tid >> 3;
    const float* kbase0 = k + ((size_t)(b * 8 + hk)) * Tv * 64;
    const float* vbase0 = v + ((size_t)(b * 8 + hk)) * Tv * 64;

    int ntile = (q0 >> 5) + 2;
    for (int kt = 0; kt < ntile; kt++) {
        __syncthreads();
        #pragma unroll
        for (int kk = 0; kk < 2; kk++) {
            int lin4 = tid + kk * 256;
            int j = lin4 >> 4; int d0 = (lin4 & 15) * 4;
            size_t off = ((size_t)(kt * 32 + j)) * 64 + d0;
            float4 kv = *(const float4*)(kbase0 + off);
            KsT[d0+0][j] = kv.x; KsT[d0+1][j] = kv.y;
            KsT[d0+2][j] = kv.z; KsT[d0+3][j] = kv.w;
            float4 vv = *(const float4*)(vbase0 + off);
            *(float4*)&Vs[j][d0] = vv;
        }
        __syncthreads();

        float s[2][4] = {};
        int i0 = tys * 2;
        #pragma unroll
        for (int d = 0; d < 64; d++) {
            float a0 = QsT[d][i0], a1 = QsT[d][i0 + 1];
            float4 bb = *(const float4*)&KsT[d][txs * 4];
            s[0][0] = fmaf(a0, bb.x, s[0][0]); s[0][1] = fmaf(a0, bb.y, s[0][1]);
            s[0][2] = fmaf(a0, bb.z, s[0][2]); s[0][3] = fmaf(a0, bb.w, s[0][3]);
            s[1][0] = fmaf(a1, bb.x, s[1][0]); s[1][1] = fmaf(a1, bb.y, s[1][1]);
            s[1][2] = fmaf(a1, bb.z, s[1][2]); s[1][3] = fmaf(a1, bb.w, s[1][3]);
        }
        #pragma unroll
        for (int r = 0; r < 2; r++)
            #pragma unroll
            for (int c = 0; c < 4; c++) {
                int qi = q0 + i0 + r, ki = kt * 32 + txs * 4 + c;
                Ss[i0 + r][txs * 4 + c] = (ki <= qi) ? s[r][c] : -INFINITY;
            }
        __syncthreads();

        {
            int row = tid >> 2, part = tid & 3;
            float* sr = &Ss[row][part * 8];
            float mo = mrow[row];
            float pv[8];
            float mx = mo;
            #pragma unroll
            for (int j = 0; j < 8; j++) { pv[j] = sr[j]; mx = fmaxf(mx, pv[j]); }
            mx = fmaxf(mx, __shfl_xor_sync(0xffffffffu, mx, 1));
            mx = fmaxf(mx, __shfl_xor_sync(0xffffffffu, mx, 2));
            float sum = 0.f;
            #pragma unroll
            for (int j = 0; j < 8; j++) {
                float p = __expf(pv[j] - mx);
                sr[j] = p; sum += p;
            }
            sum += __shfl_xor_sync(0xffffffffu, sum, 1);
            sum += __shfl_xor_sync(0xffffffffu, sum, 2);
            if (part == 0) {
                float rsc = __expf(mo - mx);
                mrow[row] = mx;
                lrow[row] = lrow[row] * rsc + sum;
                rsrow[row] = rsc;
            }
        }
        __syncthreads();

        #pragma unroll
        for (int r = 0; r < 4; r++) {
            float rr = rsrow[ty * 4 + r];
            #pragma unroll
            for (int c = 0; c < 4; c++) acc[r][c] *= rr;
        }
        #pragma unroll 4
        for (int j = 0; j < 32; j++) {
            float4 vv = *(const float4*)&Vs[j][tx * 4];
            #pragma unroll
            for (int r = 0; r < 4; r++) {
                float p = Ss[ty * 4 + r][j];
                acc[r][0] = fmaf(p, vv.x, acc[r][0]);
                acc[r][1] = fmaf(p, vv.y, acc[r][1]);
                acc[r][2] = fmaf(p, vv.z, acc[r][2]);
                acc[r][3] = fmaf(p, vv.w, acc[r][3]);
            }
        }
    }
    __syncthreads();

    #pragma unroll
    for (int r = 0; r < 4; r++) {
        int i = ty * 4 + r;
        float inv = 1.f / lrow[i];
        size_t addr = ((size_t)(b * Tv + q0 + i)) * Dv + h * 64 + tx * 4;
        float4 o = { tf32f(acc[r][0]*inv), tf32f(acc[r][1]*inv),
                     tf32f(acc[r][2]*inv), tf32f(acc[r][3]*inv) };
        *(float4*)(ctx + addr) = o;
    }
}

// ---------------- launch ----------------
extern "C" void kernel_launch(void* const* d_in, const int* in_sizes, int n_in,
                              void* d_out, int out_size)
{
    const float* x     = (const float*)d_in[0];
    const float* ln1_w = (const float*)d_in[1];
    const float* ln2_w = (const float*)d_in[2];
    const float* q_Us  = (const float*)d_in[3];
    const float* q_V   = (const float*)d_in[4];
    const float* k_Us  = (const float*)d_in[5];
    const float* k_V   = (const float*)d_in[6];
    const float* v_Us  = (const float*)d_in[7];
    const float* v_V   = (const float*)d_in[8];
    const float* o_Us  = (const float*)d_in[9];
    const float* o_V   = (const float*)d_in[10];
    const float* g_Usw = (const float*)d_in[11];
    const float* g_Vw  = (const float*)d_in[12];
    const float* u_Usw = (const float*)d_in[13];
    const float* u_Vw  = (const float*)d_in[14];
    const float* d_Usw = (const float*)d_in[15];
    const float* d_Vw  = (const float*)d_in[16];
    float* out = (float*)d_out;

    float *h1, *qr, *kr, *vr, *qb, *kb, *vb, *ctx, *orr, *x1, *h2, *gr, *ur, *gg, *ff, *dr, *rc, *rs, *wts;
    cudaGetSymbolAddress((void**)&h1,  g_h1);
    cudaGetSymbolAddress((void**)&qr,  g_qr);
    cudaGetSymbolAddress((void**)&kr,  g_kr);
    cudaGetSymbolAddress((void**)&vr,  g_vr);
    cudaGetSymbolAddress((void**)&qb,  g_q);
    cudaGetSymbolAddress((void**)&kb,  g_k);
    cudaGetSymbolAddress((void**)&vb,  g_v);
    cudaGetSymbolAddress((void**)&ctx, g_ctx);
    cudaGetSymbolAddress((void**)&orr, g_or);
    cudaGetSymbolAddress((void**)&x1,  g_x1);
    cudaGetSymbolAddress((void**)&h2,  g_h2);
    cudaGetSymbolAddress((void**)&gr,  g_gr);
    cudaGetSymbolAddress((void**)&ur,  g_ur);
    cudaGetSymbolAddress((void**)&gg,  g_g);
    cudaGetSymbolAddress((void**)&ff,  g_ff);
    cudaGetSymbolAddress((void**)&dr,  g_dr);
    cudaGetSymbolAddress((void**)&rc,  g_ropec);
    cudaGetSymbolAddress((void**)&rs,  g_ropes);
    cudaGetSymbolAddress((void**)&wts, g_wts);

    static int smem_set = 0;
    if (!smem_set) {
        cudaFuncSetAttribute(gemm_tc, cudaFuncAttributeMaxDynamicSharedMemorySize, 98304);
        smem_set = 1;
    }
    const int SM = 98304;
    dim3 blk(256);

    // pre-round weights to tf32 (exact under MMA truncation)
    tf32_round_kernel<<<2097152/1024, blk>>>(q_V,   wts + W_QV);
    tf32_round_kernel<<< 524288/1024, blk>>>(k_V,   wts + W_KV);
    tf32_round_kernel<<< 524288/1024, blk>>>(v_V,   wts + W_VV);
    tf32_round_kernel<<<2097152/1024, blk>>>(o_V,   wts + W_OV);
    tf32_round_kernel<<<2097152/1024, blk>>>(o_Us,  wts + W_OUS);
    tf32_round_kernel<<<2097152/1024, blk>>>(g_Vw,  wts + W_GV);
    tf32_round_kernel<<<2097152/1024, blk>>>(u_Vw,  wts + W_UV);
    tf32_round_kernel<<<5767168/1024, blk>>>(g_Usw, wts + W_GUS);
    tf32_round_kernel<<<5767168/1024, blk>>>(u_Usw, wts + W_UUS);
    tf32_round_kernel<<<5767168/1024, blk>>>(d_Vw,  wts + W_DV);
    tf32_round_kernel<<<2097152/1024, blk>>>(d_Usw, wts + W_DUS);

    rope_table_kernel<<<Tv*32/256, 256>>>(rc, rs);
    rms_kernel<<<BT, blk>>>(x, ln1_w, h1);

    // fused q/k/v rank projections
    gemm_tc<<<dim3(12, 32), blk, SM>>>(h1, Dv, 0, nullptr,
        wts + W_QV, qr, Hv*Rv, 8,  wts + W_KV, kr, HKv*Rv, 2,  wts + W_VV, vr, HKv*Rv, 2);

    usproj_fused<<<dim3(BT/64, 48), blk>>>(qr, kr, vr, q_Us, k_Us, v_Us, qb, kb, vb, rc, rs);

    attn_kernel<<<dim3(Tv/64, Bv*Hv), blk>>>(qb, kb, vb, ctx);

    gemm_tc<<<dim3(8, 32), blk, SM>>>(ctx, Dv, 0|4, nullptr,
        wts + W_OV, orr, ROv, 8,  nullptr, nullptr, 0, 0,  nullptr, nullptr, 0, 0);
    gemm_tc<<<dim3(16, 32), blk, SM>>>(orr, ROv, 1, x,
        wts + W_OUS, x1, Dv, 16,  nullptr, nullptr, 0, 0,  nullptr, nullptr, 0, 0);

    rms_kernel<<<BT, blk>>>(x1, ln2_w, h2);

    gemm_tc<<<dim3(16, 32), blk, SM>>>(h2, Dv, 0|4, nullptr,
        wts + W_GV, gr, RFv, 8,  wts + W_UV, ur, RFv, 8,  nullptr, nullptr, 0, 0);

    gemm_tc<<<dim3(44, 32), blk, SM>>>(gr, RFv, 0, nullptr,
        wts + W_GUS, gg, Iv, 44,  nullptr, nullptr, 0, 0,  nullptr, nullptr, 0, 0);
    gemm_tc<<<dim3(44, 32), blk, SM>>>(ur, RFv, 2|4, gg,
        wts + W_UUS, ff, Iv, 44,  nullptr, nullptr, 0, 0,  nullptr, nullptr, 0, 0);

    gemm_tc<<<dim3(8, 32), blk, SM>>>(ff, Iv, 0|4, nullptr,
        wts + W_DV, dr, RFv, 8,  nullptr, nullptr, 0, 0,  nullptr, nullptr, 0, 0);
    gemm_tc<<<dim3(16, 32), blk, SM>>>(dr, RFv, 1, x1,
        wts + W_DUS, out, Dv, 16,  nullptr, nullptr, 0, 0,  nullptr, nullptr, 0, 0);
}

// round 5
// speedup vs baseline: 1.5544x; 1.3100x over previous
#include <cuda_runtime.h>
#include <cuda_bf16.h>
#include <math.h>

// ---------------- problem constants ----------------
#define Bv   4
#define Tv   1024
#define Dv   2048
#define Hv   32
#define DHv  64
#define HKv  8
#define Rv   32
#define ROv  1024
#define RFv  1024
#define Iv   5632
#define BT   (Bv*Tv)     // 4096

// ---------------- scratch ----------------
__device__ float g_h1 [BT*Dv];
__device__ float g_qr [BT*(Hv*Rv)];
__device__ float g_kr [BT*(HKv*Rv)];
__device__ float g_vr [BT*(HKv*Rv)];
__device__ float g_q  [Bv*Hv*Tv*DHv];
__device__ float g_k  [Bv*HKv*Tv*DHv];
__device__ float g_v  [Bv*HKv*Tv*DHv];
__device__ float g_ctx[BT*Dv];
__device__ float g_or [BT*ROv];
__device__ float g_x1 [BT*Dv];
__device__ float g_h2 [BT*Dv];
__device__ float g_gr [BT*RFv];
__device__ float g_ur [BT*RFv];
__device__ float g_g  [BT*Iv];
__device__ float g_ff [BT*Iv];
__device__ float g_dr [BT*RFv];
__device__ float g_ropec[Tv*32];
__device__ float g_ropes[Tv*32];
// rounded weights (concatenated)
#define W_QV   0
#define W_KV   2097152
#define W_VV   2621440
#define W_OV   3145728
#define W_OUS  5242880
#define W_GV   7340032
#define W_UV   9437184
#define W_GUS  11534336
#define W_UUS  17301504
#define W_DV   23068672
#define W_DUS  28835840
#define W_TOT  30932992
__device__ float g_wts[W_TOT];

// ---------------- tf32 rounding helper ----------------
__device__ __forceinline__ float tf32f(float x) {
    unsigned u;
    asm("cvt.rna.tf32.f32 %0, %1;" : "=r"(u) : "f"(x));
    return __uint_as_float(u);
}

// ---------------- fused weight prep: round all weights in ONE launch ----------------
__global__ void __launch_bounds__(256) prep_weights(
    float* __restrict__ dst,
    const float* __restrict__ s0, const float* __restrict__ s1, const float* __restrict__ s2,
    const float* __restrict__ s3, const float* __restrict__ s4, const float* __restrict__ s5,
    const float* __restrict__ s6, const float* __restrict__ s7, const float* __restrict__ s8,
    const float* __restrict__ s9, const float* __restrict__ s10)
{
    long i = ((long)blockIdx.x * 256 + threadIdx.x) * 4;
    const float* src; long base;
    if (i < W_GUS) {
        if (i < W_OV) {
            if (i < W_KV)        { src = s0; base = W_QV; }
            else if (i < W_VV)   { src = s1; base = W_KV; }
            else                 { src = s2; base = W_VV; }
        } else {
            if (i < W_OUS)       { src = s3; base = W_OV; }
            else if (i < W_GV)   { src = s4; base = W_OUS; }
            else if (i < W_UV)   { src = s5; base = W_GV; }
            else                 { src = s6; base = W_UV; }
        }
    } else {
        if (i < W_UUS)           { src = s7; base = W_GUS; }
        else if (i < W_DV)       { src = s8; base = W_UUS; }
        else if (i < W_DUS)      { src = s9; base = W_DV; }
        else                     { src = s10; base = W_DUS; }
    }
    float4 v = *(const float4*)(src + (i - base));
    v.x = tf32f(v.x); v.y = tf32f(v.y); v.z = tf32f(v.z); v.w = tf32f(v.w);
    *(float4*)(dst + i) = v;
}

// ---------------- rope table ----------------
__global__ void rope_table_kernel(float* __restrict__ rc, float* __restrict__ rs)
{
    int idx = blockIdx.x * blockDim.x + threadIdx.x;
    int t = idx >> 5, d = idx & 31;
    float invf = expf(-0.28782313662425572f * (float)d);
    float ang = (float)t * invf;
    rc[idx] = cosf(ang);
    rs[idx] = sinf(ang);
}

// ---------------- RMSNorm (tf32-rounded output) ----------------
__global__ void __launch_bounds__(256) rms_kernel(const float* __restrict__ x,
                                                  const float* __restrict__ w,
                                                  float* __restrict__ out)
{
    int row = blockIdx.x;
    int tid = threadIdx.x;
    const float4* xr = (const float4*)(x + (size_t)row * Dv);
    float4 v0 = xr[tid];
    float4 v1 = xr[tid + 256];
    float ss = v0.x*v0.x + v0.y*v0.y + v0.z*v0.z + v0.w*v0.w
             + v1.x*v1.x + v1.y*v1.y + v1.z*v1.z + v1.w*v1.w;
    #pragma unroll
    for (int o = 16; o; o >>= 1) ss += __shfl_xor_sync(0xffffffffu, ss, o);
    __shared__ float red[8];
    if ((tid & 31) == 0) red[tid >> 5] = ss;
    __syncthreads();
    float tot = 0.f;
    #pragma unroll
    for (int i = 0; i < 8; i++) tot += red[i];
    float inv = rsqrtf(tot * (1.0f / Dv) + 1e-5f);
    const float4* wr = (const float4*)w;
    float4 w0 = wr[tid], w1 = wr[tid + 256];
    float4 o0 = { tf32f(v0.x*inv*w0.x), tf32f(v0.y*inv*w0.y), tf32f(v0.z*inv*w0.z), tf32f(v0.w*inv*w0.w) };
    float4 o1 = { tf32f(v1.x*inv*w1.x), tf32f(v1.y*inv*w1.y), tf32f(v1.z*inv*w1.z), tf32f(v1.w*inv*w1.w) };
    float4* orow = (float4*)(out + (size_t)row * Dv);
    orow[tid] = o0;
    orow[tid + 256] = o1;
}

// ---------------- tf32 tensor-core GEMM (3-stage, segmented) ----------------
#define STAGES 3

#define CP_ASYNC16(dst, src) asm volatile("cp.async.cg.shared.global [%0], [%1], 16;\n" :: "r"(dst), "l"(src))
#define CP_COMMIT() asm volatile("cp.async.commit_group;\n" ::)
#define CP_WAIT(n)  asm volatile("cp.async.wait_group %0;\n" :: "n"(n))

#define MMA_TF32(d, a, b) \
    asm volatile("mma.sync.aligned.m16n8k8.row.col.f32.tf32.tf32.f32 " \
        "{%0,%1,%2,%3}, {%4,%5,%6,%7}, {%8,%9}, {%0,%1,%2,%3};" \
        : "+f"(d[0]), "+f"(d[1]), "+f"(d[2]), "+f"(d[3]) \
        : "r"(a[0]), "r"(a[1]), "r"(a[2]), "r"(a[3]), "r"(b[0]), "r"(b[1]))

__global__ void __launch_bounds__(256, 2) gemm_tc(
    const float* __restrict__ A, int K, int mode, const float* __restrict__ aux,
    const float* __restrict__ B0, float* __restrict__ C0, int N0, int nb0,
    const float* __restrict__ B1, float* __restrict__ C1, int N1, int nb1,
    const float* __restrict__ B2, float* __restrict__ C2, int N2, int nb2)
{
    extern __shared__ float smem[];
    unsigned sbase = (unsigned)__cvta_generic_to_shared(smem);

    int bx = blockIdx.x;
    const float* Bw; float* C; int N; int bnb;
    if (bx < nb0)            { Bw = B0; C = C0; N = N0; bnb = bx; }
    else if (bx < nb0 + nb1) { Bw = B1; C = C1; N = N1; bnb = bx - nb0; }
    else                     { Bw = B2; C = C2; N = N2; bnb = bx - nb0 - nb1; }

    int tid  = threadIdx.x;
    int bm = blockIdx.y * 128;
    int bn = bnb * 128;
    int lane = tid & 31, warp = tid >> 5;
    int wm = warp >> 1, wn = warp & 1;
    int g  = lane >> 2, tig = lane & 3;

    unsigned dstoff[4];
    const float* srcA[4];
    const float* srcB[4];
    #pragma unroll
    for (int i = 0; i < 4; i++) {
        int lin = tid + i * 256;
        int row = lin >> 3, c = lin & 7;
        dstoff[i] = (unsigned)((row * 32 + ((c ^ (row & 7)) << 2)) * 4);
        srcA[i] = A  + (size_t)(bm + row) * K + c * 4;
        srcB[i] = Bw + (size_t)(bn + row) * K + c * 4;
    }

    int ar0[2], ar1[2], a7[2];
    #pragma unroll
    for (int mi = 0; mi < 2; mi++) {
        int r0 = wm * 32 + mi * 16 + g;
        ar0[mi] = r0 * 32 + tig;
        ar1[mi] = (r0 + 8) * 32 + tig;
        a7[mi]  = r0 & 7;
    }
    int bbase[8], b7[8];
    #pragma unroll
    for (int ni = 0; ni < 8; ni++) {
        int n = wn * 64 + ni * 8 + g;
        bbase[ni] = n * 32 + tig;
        b7[ni] = n & 7;
    }

    float acc[2][8][4];
    #pragma unroll
    for (int mi = 0; mi < 2; mi++)
        #pragma unroll
        for (int ni = 0; ni < 8; ni++)
            #pragma unroll
            for (int q = 0; q < 4; q++) acc[mi][ni][q] = 0.f;

    const int NT = K >> 5;

    #pragma unroll
    for (int s = 0; s < STAGES - 1; s++) {
        unsigned da = sbase + (unsigned)s * 32768u;
        unsigned db = da + 16384u;
        #pragma unroll
        for (int i = 0; i < 4; i++) {
            CP_ASYNC16(da + dstoff[i], srcA[i] + (size_t)s * 32);
            CP_ASYNC16(db + dstoff[i], srcB[i] + (size_t)s * 32);
        }
        CP_COMMIT();
    }

    for (int kt = 0; kt < NT; kt++) {
        int st = kt % STAGES;
        CP_WAIT(STAGES - 2);
        __syncthreads();

        int pf = kt + STAGES - 1;
        if (pf < NT) {
            int pst = pf % STAGES;
            unsigned da = sbase + (unsigned)pst * 32768u;
            unsigned db = da + 16384u;
            #pragma unroll
            for (int i = 0; i < 4; i++) {
                CP_ASYNC16(da + dstoff[i], srcA[i] + (size_t)pf * 32);
                CP_ASYNC16(db + dstoff[i], srcB[i] + (size_t)pf * 32);
            }
        }
        CP_COMMIT();

        const unsigned* AsU = (const unsigned*)smem + st * 8192;
        const unsigned* BsU = AsU + 4096;

        #pragma unroll
        for (int s = 0; s < 4; s++) {
            int c0 = 2 * s, c1 = 2 * s + 1;
            unsigned af[2][4];
            #pragma unroll
            for (int mi = 0; mi < 2; mi++) {
                int o0 = (c0 ^ a7[mi]) << 2;
                int o1 = (c1 ^ a7[mi]) << 2;
                af[mi][0] = AsU[ar0[mi] + o0];
                af[mi][1] = AsU[ar1[mi] + o0];
                af[mi][2] = AsU[ar0[mi] + o1];
                af[mi][3] = AsU[ar1[mi] + o1];
            }
            unsigned bf[8][2];
            #pragma unroll
            for (int ni = 0; ni < 8; ni++) {
                bf[ni][0] = BsU[bbase[ni] + ((c0 ^ b7[ni]) << 2)];
                bf[ni][1] = BsU[bbase[ni] + ((c1 ^ b7[ni]) << 2)];
            }
            #pragma unroll
            for (int mi = 0; mi < 2; mi++)
                #pragma unroll
                for (int ni = 0; ni < 8; ni++)
                    MMA_TF32(acc[mi][ni], af[mi], bf[ni]);
        }
    }

    int emode = mode & 3;
    int rnd = mode & 4;
    #pragma unroll
    for (int mi = 0; mi < 2; mi++) {
        int row0 = bm + wm * 32 + mi * 16 + g;
        #pragma unroll
        for (int half = 0; half < 2; half++) {
            int row = row0 + half * 8;
            size_t rowoff = (size_t)row * N;
            #pragma unroll
            for (int ni = 0; ni < 8; ni++) {
                int col = bn + wn * 64 + ni * 8 + 2 * tig;
                size_t idx = rowoff + col;
                float vx = acc[mi][ni][half * 2 + 0];
                float vy = acc[mi][ni][half * 2 + 1];
                if (emode == 1) {
                    float2 rsd = *(const float2*)(aux + idx);
                    vx += rsd.x; vy += rsd.y;
                } else if (emode == 2) {
                    float2 gg = *(const float2*)(aux + idx);
                    vx *= gg.x / (1.f + __expf(-gg.x));
                    vy *= gg.y / (1.f + __expf(-gg.y));
                }
                if (rnd) { vx = tf32f(vx); vy = tf32f(vy); }
                float2 o = { vx, vy };
                *(float2*)(C + idx) = o;
            }
        }
    }
}

// ---------------- fused per-head Us projection (+ optional RoPE; tf32-rounded out) ----------------
__global__ void __launch_bounds__(256) usproj_fused(
    const float* __restrict__ qr, const float* __restrict__ kr, const float* __restrict__ vr,
    const float* __restrict__ qUs, const float* __restrict__ kUs, const float* __restrict__ vUs,
    float* __restrict__ qb, float* __restrict__ kb, float* __restrict__ vb,
    const float* __restrict__ rc, const float* __restrict__ rs)
{
    __shared__ __align__(16) float inT[32][64];
    __shared__ __align__(16) float UsT[32][64];
    __shared__ __align__(16) float os [64][64];
    int y = blockIdx.y;
    const float* in; const float* Us; float* out; int heads, h, rope;
    if (y < 32)      { in = qr; Us = qUs; out = qb; heads = 32; h = y;      rope = 1; }
    else if (y < 40) { in = kr; Us = kUs; out = kb; heads = 8;  h = y - 32; rope = 1; }
    else             { in = vr; Us = vUs; out = vb; heads = 8;  h = y - 40; rope = 0; }

    int bt0 = blockIdx.x * 64;
    int tid = threadIdx.x;
    int ldin = heads * 32;

    {
        int d = tid >> 2; int r0 = (tid & 3) * 8;
        const float* p = Us + ((size_t)h * 64 + d) * 32 + r0;
        float4 u0 = *(const float4*)p;
        float4 u1 = *(const float4*)(p + 4);
        UsT[r0+0][d]=u0.x; UsT[r0+1][d]=u0.y; UsT[r0+2][d]=u0.z; UsT[r0+3][d]=u0.w;
        UsT[r0+4][d]=u1.x; UsT[r0+5][d]=u1.y; UsT[r0+6][d]=u1.z; UsT[r0+7][d]=u1.w;
    }
    {
        int i = tid >> 2; int r0 = (tid & 3) * 8;
        const float* p = in + (size_t)(bt0 + i) * ldin + h * 32 + r0;
        float4 a0 = *(const float4*)p;
        float4 a1 = *(const float4*)(p + 4);
        inT[r0+0][i]=a0.x; inT[r0+1][i]=a0.y; inT[r0+2][i]=a0.z; inT[r0+3][i]=a0.w;
        inT[r0+4][i]=a1.x; inT[r0+5][i]=a1.y; inT[r0+6][i]=a1.z; inT[r0+7][i]=a1.w;
    }
    __syncthreads();

    int tx = tid & 15, ty = tid >> 4;
    float acc[4][4] = {};
    #pragma unroll
    for (int r = 0; r < 32; r++) {
        float4 a = *(const float4*)&inT[r][ty*4];
        float4 b = *(const float4*)&UsT[r][tx*4];
        float av[4] = {a.x,a.y,a.z,a.w};
        float bv[4] = {b.x,b.y,b.z,b.w};
        #pragma unroll
        for (int rr = 0; rr < 4; rr++)
            #pragma unroll
            for (int cc = 0; cc < 4; cc++)
                acc[rr][cc] = fmaf(av[rr], bv[cc], acc[rr][cc]);
    }
    #pragma unroll
    for (int rr = 0; rr < 4; rr++)
        #pragma unroll
        for (int cc = 0; cc < 4; cc++)
            os[ty*4+rr][tx*4+cc] = acc[rr][cc];
    __syncthreads();

    if (!rope) {
        #pragma unroll
        for (int kk = 0; kk < 4; kk++) {
            int lin4 = tid + kk * 256;
            int i = lin4 >> 4; int d0 = (lin4 & 15) * 4;
            int bt = bt0 + i; int b = bt >> 10; int t = bt & 1023;
            float4 vv = *(const float4*)&os[i][d0];
            vv.x = tf32f(vv.x); vv.y = tf32f(vv.y); vv.z = tf32f(vv.z); vv.w = tf32f(vv.w);
            size_t addr = (((size_t)(b * heads + h)) * Tv + t) * 64 + d0;
            *(float4*)(out + addr) = vv;
        }
    } else {
        #pragma unroll
        for (int kk = 0; kk < 2; kk++) {
            int lin4 = tid + kk * 256;
            int i = lin4 >> 3; int d0 = (lin4 & 7) * 4;
            int bt = bt0 + i; int b = bt >> 10; int t = bt & 1023;
            float4 x1 = *(const float4*)&os[i][d0];
            float4 x2 = *(const float4*)&os[i][d0 + 32];
            float4 cc4 = *(const float4*)(rc + t * 32 + d0);
            float4 ss4 = *(const float4*)(rs + t * 32 + d0);
            float xx1[4] = {x1.x,x1.y,x1.z,x1.w};
            float xx2[4] = {x2.x,x2.y,x2.z,x2.w};
            float ca[4] = {cc4.x,cc4.y,cc4.z,cc4.w};
            float sa[4] = {ss4.x,ss4.y,ss4.z,ss4.w};
            float o1[4], o2[4];
            #pragma unroll
            for (int c = 0; c < 4; c++) {
                o1[c] = tf32f(xx1[c] * ca[c] - xx2[c] * sa[c]);
                o2[c] = tf32f(xx2[c] * ca[c] + xx1[c] * sa[c]);
            }
            size_t base = (((size_t)(b * heads + h)) * Tv + t) * 64;
            float4 w1 = {o1[0],o1[1],o1[2],o1[3]};
            float4 w2 = {o2[0],o2[1],o2[2],o2[3]};
            *(float4*)(out + base + d0)      = w1;
            *(float4*)(out + base + d0 + 32) = w2;
        }
    }
}

// ---------------- flash attention via tf32 MMA (causal, GQA 4:1) ----------------
__global__ void __launch_bounds__(256) attn_kernel(const float* __restrict__ q,
                                                   const float* __restrict__ k,
                                                   const float* __restrict__ v,
                                                   float* __restrict__ ctx)
{
    __shared__ __align__(16) float Qs[64][68];
    __shared__ __align__(16) float Ks[32][68];
    __shared__ __align__(16) float Vs[32][72];
    __shared__ __align__(16) float Ss[64][36];
    __shared__ float mrow[64], lrow[64], rsrow[64];

    int tid = threadIdx.x;
    int bh = blockIdx.y; int b = bh >> 5; int h = bh & 31; int hk = h >> 2;
    int q0 = blockIdx.x * 64;
    int lane = tid & 31, warp = tid >> 5;
    int g = lane >> 2, tig = lane & 3;
    int wq = warp >> 1;   // q-row block (16 rows)
    int wn = warp & 1;    // S: key block (16); PV: d block (32)

    const float* qbase = q + (((size_t)(b * 32 + h)) * Tv + q0) * 64;
    #pragma unroll
    for (int kk = 0; kk < 4; kk++) {
        int lin = tid + kk * 256;
        int i = lin >> 4, d0 = (lin & 15) * 4;
        float4 qv = *(const float4*)(qbase + (size_t)i * 64 + d0);
        qv.x *= 0.125f; qv.y *= 0.125f; qv.z *= 0.125f; qv.w *= 0.125f;
        *(float4*)&Qs[i][d0] = qv;
    }
    if (tid < 64) { mrow[tid] = -INFINITY; lrow[tid] = 0.f; }

    float cacc[4][4];
    #pragma unroll
    for (int ni = 0; ni < 4; ni++)
        #pragma unroll
        for (int c = 0; c < 4; c++) cacc[ni][c] = 0.f;

    const float* kb0 = k + ((size_t)(b * 8 + hk)) * Tv * 64;
    const float* vb0 = v + ((size_t)(b * 8 + hk)) * Tv * 64;

    int qr0 = wq * 16 + g;          // first owned q-row
    int ntile = (q0 >> 5) + 2;
    for (int kt = 0; kt < ntile; kt++) {
        __syncthreads();
        #pragma unroll
        for (int kk = 0; kk < 2; kk++) {
            int lin = tid + kk * 256;
            int j = lin >> 4, d0 = (lin & 15) * 4;
            size_t off = ((size_t)(kt * 32 + j)) * 64 + d0;
            *(float4*)&Ks[j][d0] = *(const float4*)(kb0 + off);
            *(float4*)&Vs[j][d0] = *(const float4*)(vb0 + off);
        }
        __syncthreads();

        // ---- S = Qs @ Ks^T (warp: rows wq*16..+15, keys wn*16..+15) ----
        float sacc[2][4] = {};
        #pragma unroll
        for (int ks = 0; ks < 8; ks++) {
            int kc = ks * 8;
            unsigned af[4];
            af[0] = __float_as_uint(Qs[qr0][kc + tig]);
            af[1] = __float_as_uint(Qs[qr0 + 8][kc + tig]);
            af[2] = __float_as_uint(Qs[qr0][kc + tig + 4]);
            af[3] = __float_as_uint(Qs[qr0 + 8][kc + tig + 4]);
            #pragma unroll
            for (int ni = 0; ni < 2; ni++) {
                unsigned bf[2];
                int krow = wn * 16 + ni * 8 + g;
                bf[0] = __float_as_uint(Ks[krow][kc + tig]);
                bf[1] = __float_as_uint(Ks[krow][kc + tig + 4]);
                MMA_TF32(sacc[ni], af, bf);
            }
        }
        #pragma unroll
        for (int ni = 0; ni < 2; ni++)
            #pragma unroll
            for (int c = 0; c < 4; c++) {
                int row = qr0 + ((c >> 1) << 3);
                int col = wn * 16 + ni * 8 + 2 * tig + (c & 1);
                int qi = q0 + row, ki = kt * 32 + col;
                Ss[row][col] = (ki <= qi) ? sacc[ni][c] : -INFINITY;
            }
        __syncthreads();

        // ---- online softmax (4 lanes per row) ----
        {
            int row = tid >> 2, part = tid & 3;
            float* sr = &Ss[row][part * 8];
            float mo = mrow[row];
            float pv[8];
            float mx = mo;
            #pragma unroll
            for (int j = 0; j < 8; j++) { pv[j] = sr[j]; mx = fmaxf(mx, pv[j]); }
            mx = fmaxf(mx, __shfl_xor_sync(0xffffffffu, mx, 1));
            mx = fmaxf(mx, __shfl_xor_sync(0xffffffffu, mx, 2));
            float sum = 0.f;
            #pragma unroll
            for (int j = 0; j < 8; j++) {
                float p = __expf(pv[j] - mx);
                sr[j] = p; sum += p;
            }
            sum += __shfl_xor_sync(0xffffffffu, sum, 1);
            sum += __shfl_xor_sync(0xffffffffu, sum, 2);
            if (part == 0) {
                float rsc = __expf(mo - mx);
                mrow[row] = mx;
                lrow[row] = lrow[row] * rsc + sum;
                rsrow[row] = rsc;
            }
        }
        __syncthreads();

        // ---- rescale + PV (warp: rows wq*16..+15, d cols wn*32..+31) ----
        float r0s = rsrow[qr0], r1s = rsrow[qr0 + 8];
        #pragma unroll
        for (int ni = 0; ni < 4; ni++) {
            cacc[ni][0] *= r0s; cacc[ni][1] *= r0s;
            cacc[ni][2] *= r1s; cacc[ni][3] *= r1s;
        }
        #pragma unroll
        for (int ks = 0; ks < 4; ks++) {
            int kc = ks * 8;
            unsigned af[4];
            af[0] = __float_as_uint(Ss[qr0][kc + tig]);
            af[1] = __float_as_uint(Ss[qr0 + 8][kc + tig]);
            af[2] = __float_as_uint(Ss[qr0][kc + tig + 4]);
            af[3] = __float_as_uint(Ss[qr0 + 8][kc + tig + 4]);
            #pragma unroll
            for (int ni = 0; ni < 4; ni++) {
                unsigned bf[2];
                int vcol = wn * 32 + ni * 8 + g;
                bf[0] = __float_as_uint(Vs[kc + tig][vcol]);
                bf[1] = __float_as_uint(Vs[kc + tig + 4][vcol]);
                MMA_TF32(cacc[ni], af, bf);
            }
        }
    }

    // ---- epilogue ----
    float inv0 = 1.f / lrow[qr0];
    float inv1 = 1.f / lrow[qr0 + 8];
    #pragma unroll
    for (int ni = 0; ni < 4; ni++) {
        #pragma unroll
        for (int half = 0; half < 2; half++) {
            int row = qr0 + half * 8;
            float inv = half ? inv1 : inv0;
            int col = wn * 32 + ni * 8 + 2 * tig;
            size_t addr = ((size_t)(b * Tv + q0 + row)) * Dv + h * 64 + col;
            float2 o = { tf32f(cacc[ni][half * 2 + 0] * inv),
                         tf32f(cacc[ni][half * 2 + 1] * inv) };
            *(float2*)(ctx + addr) = o;
        }
    }
}

// ---------------- launch ----------------
extern "C" void kernel_launch(void* const* d_in, const int* in_sizes, int n_in,
                              void* d_out, int out_size)
{
    const float* x     = (const float*)d_in[0];
    const float* ln1_w = (const float*)d_in[1];
    const float* ln2_w = (const float*)d_in[2];
    const float* q_Us  = (const float*)d_in[3];
    const float* q_V   = (const float*)d_in[4];
    const float* k_Us  = (const float*)d_in[5];
    const float* k_V   = (const float*)d_in[6];
    const float* v_Us  = (const float*)d_in[7];
    const float* v_V   = (const float*)d_in[8];
    const float* o_Us  = (const float*)d_in[9];
    const float* o_V   = (const float*)d_in[10];
    const float* g_Usw = (const float*)d_in[11];
    const float* g_Vw  = (const float*)d_in[12];
    const float* u_Usw = (const float*)d_in[13];
    const float* u_Vw  = (const float*)d_in[14];
    const float* d_Usw = (const float*)d_in[15];
    const float* d_Vw  = (const float*)d_in[16];
    float* out = (float*)d_out;

    float *h1, *qr, *kr, *vr, *qb, *kb, *vb, *ctx, *orr, *x1, *h2, *gr, *ur, *gg, *ff, *dr, *rc, *rs, *wts;
    cudaGetSymbolAddress((void**)&h1,  g_h1);
    cudaGetSymbolAddress((void**)&qr,  g_qr);
    cudaGetSymbolAddress((void**)&kr,  g_kr);
    cudaGetSymbolAddress((void**)&vr,  g_vr);
    cudaGetSymbolAddress((void**)&qb,  g_q);
    cudaGetSymbolAddress((void**)&kb,  g_k);
    cudaGetSymbolAddress((void**)&vb,  g_v);
    cudaGetSymbolAddress((void**)&ctx, g_ctx);
    cudaGetSymbolAddress((void**)&orr, g_or);
    cudaGetSymbolAddress((void**)&x1,  g_x1);
    cudaGetSymbolAddress((void**)&h2,  g_h2);
    cudaGetSymbolAddress((void**)&gr,  g_gr);
    cudaGetSymbolAddress((void**)&ur,  g_ur);
    cudaGetSymbolAddress((void**)&gg,  g_g);
    cudaGetSymbolAddress((void**)&ff,  g_ff);
    cudaGetSymbolAddress((void**)&dr,  g_dr);
    cudaGetSymbolAddress((void**)&rc,  g_ropec);
    cudaGetSymbolAddress((void**)&rs,  g_ropes);
    cudaGetSymbolAddress((void**)&wts, g_wts);

    static int smem_set = 0;
    if (!smem_set) {
        cudaFuncSetAttribute(gemm_tc, cudaFuncAttributeMaxDynamicSharedMemorySize, 98304);
        smem_set = 1;
    }
    const int SM = 98304;
    dim3 blk(256);

    // single fused weight-prep launch
    prep_weights<<<W_TOT/1024, blk>>>(wts, q_V, k_V, v_V, o_V, o_Us,
                                      g_Vw, u_Vw, g_Usw, u_Usw, d_Vw, d_Usw);

    rope_table_kernel<<<Tv*32/256, 256>>>(rc, rs);
    rms_kernel<<<BT, blk>>>(x, ln1_w, h1);

    gemm_tc<<<dim3(12, 32), blk, SM>>>(h1, Dv, 0, nullptr,
        wts + W_QV, qr, Hv*Rv, 8,  wts + W_KV, kr, HKv*Rv, 2,  wts + W_VV, vr, HKv*Rv, 2);

    usproj_fused<<<dim3(BT/64, 48), blk>>>(qr, kr, vr, q_Us, k_Us, v_Us, qb, kb, vb, rc, rs);

    attn_kernel<<<dim3(Tv/64, Bv*Hv), blk>>>(qb, kb, vb, ctx);

    gemm_tc<<<dim3(8, 32), blk, SM>>>(ctx, Dv, 0|4, nullptr,
        wts + W_OV, orr, ROv, 8,  nullptr, nullptr, 0, 0,  nullptr, nullptr, 0, 0);
    gemm_tc<<<dim3(16, 32), blk, SM>>>(orr, ROv, 1, x,
        wts + W_OUS, x1, Dv, 16,  nullptr, nullptr, 0, 0,  nullptr, nullptr, 0, 0);

    rms_kernel<<<BT, blk>>>(x1, ln2_w, h2);

    gemm_tc<<<dim3(16, 32), blk, SM>>>(h2, Dv, 0|4, nullptr,
        wts + W_GV, gr, RFv, 8,  wts + W_UV, ur, RFv, 8,  nullptr, nullptr, 0, 0);

    gemm_tc<<<dim3(44, 32), blk, SM>>>(gr, RFv, 0, nullptr,
        wts + W_GUS, gg, Iv, 44,  nullptr, nullptr, 0, 0,  nullptr, nullptr, 0, 0);
    gemm_tc<<<dim3(44, 32), blk, SM>>>(ur, RFv, 2|4, gg,
        wts + W_UUS, ff, Iv, 44,  nullptr, nullptr, 0, 0,  nullptr, nullptr, 0, 0);

    gemm_tc<<<dim3(8, 32), blk, SM>>>(ff, Iv, 0|4, nullptr,
        wts + W_DV, dr, RFv, 8,  nullptr, nullptr, 0, 0,  nullptr, nullptr, 0, 0);
    gemm_tc<<<dim3(16, 32), blk, SM>>>(dr, RFv, 1, x1,
        wts + W_DUS, out, Dv, 16,  nullptr, nullptr, 0, 0,  nullptr, nullptr, 0, 0);
}

// round 6
// speedup vs baseline: 2.8129x; 1.8096x over previous
#include <cuda_runtime.h>
#include <cuda_fp16.h>
#include <math.h>

// ---------------- problem constants ----------------
#define Bv   4
#define Tv   1024
#define Dv   2048
#define Hv   32
#define DHv  64
#define HKv  8
#define Rv   32
#define ROv  1024
#define RFv  1024
#define Iv   5632
#define BT   (Bv*Tv)     // 4096

// ---------------- scratch ----------------
__device__ __half g_h1 [BT*Dv];
__device__ __half g_qr [BT*(Hv*Rv)];
__device__ __half g_kr [BT*(HKv*Rv)];
__device__ __half g_vr [BT*(HKv*Rv)];
__device__ float  g_q  [Bv*Hv*Tv*DHv];
__device__ float  g_k  [Bv*HKv*Tv*DHv];
__device__ float  g_v  [Bv*HKv*Tv*DHv];
__device__ __half g_ctx[BT*Dv];
__device__ __half g_or [BT*ROv];
__device__ float  g_x1 [BT*Dv];
__device__ __half g_h2 [BT*Dv];
__device__ __half g_gr [BT*RFv];
__device__ __half g_ur [BT*RFv];
__device__ __half g_g  [BT*Iv];
__device__ __half g_ff [BT*Iv];
__device__ __half g_dr [BT*RFv];
__device__ float  g_ropec[Tv*32];
__device__ float  g_ropes[Tv*32];
// converted (half) weights, concatenated; offsets in elements
#define W_QV   0
#define W_KV   2097152
#define W_VV   2621440
#define W_OV   3145728
#define W_OUS  5242880
#define W_GV   7340032
#define W_UV   9437184
#define W_GUS  11534336
#define W_UUS  17301504
#define W_DV   23068672
#define W_DUS  28835840
#define W_TOT  30932992
__device__ __half g_wts[W_TOT];

// ---------------- helpers ----------------
__device__ __forceinline__ float tf32f(float x) {
    unsigned u;
    asm("cvt.rna.tf32.f32 %0, %1;" : "=r"(u) : "f"(x));
    return __uint_as_float(u);
}
__device__ __forceinline__ uint2 pack4h(float4 v) {
    __half2 a = __floats2half2_rn(v.x, v.y);
    __half2 b = __floats2half2_rn(v.z, v.w);
    uint2 r;
    r.x = *(unsigned*)&a;
    r.y = *(unsigned*)&b;
    return r;
}

// ---------------- fused weight prep: f32 -> f16 in ONE launch ----------------
__global__ void __launch_bounds__(256) prep_weights(
    __half* __restrict__ dst,
    const float* __restrict__ s0, const float* __restrict__ s1, const float* __restrict__ s2,
    const float* __restrict__ s3, const float* __restrict__ s4, const float* __restrict__ s5,
    const float* __restrict__ s6, const float* __restrict__ s7, const float* __restrict__ s8,
    const float* __restrict__ s9, const float* __restrict__ s10)
{
    long i = ((long)blockIdx.x * 256 + threadIdx.x) * 4;
    const float* src; long base;
    if (i < W_GUS) {
        if (i < W_OV) {
            if (i < W_KV)        { src = s0; base = W_QV; }
            else if (i < W_VV)   { src = s1; base = W_KV; }
            else                 { src = s2; base = W_VV; }
        } else {
            if (i < W_OUS)       { src = s3; base = W_OV; }
            else if (i < W_GV)   { src = s4; base = W_OUS; }
            else if (i < W_UV)   { src = s5; base = W_GV; }
            else                 { src = s6; base = W_UV; }
        }
    } else {
        if (i < W_UUS)           { src = s7; base = W_GUS; }
        else if (i < W_DV)       { src = s8; base = W_UUS; }
        else if (i < W_DUS)      { src = s9; base = W_DV; }
        else                     { src = s10; base = W_DUS; }
    }
    float4 v = *(const float4*)(src + (i - base));
    *(uint2*)(dst + i) = pack4h(v);
}

// ---------------- rope table ----------------
__global__ void rope_table_kernel(float* __restrict__ rc, float* __restrict__ rs)
{
    int idx = blockIdx.x * blockDim.x + threadIdx.x;
    int t = idx >> 5, d = idx & 31;
    float invf = expf(-0.28782313662425572f * (float)d);
    float ang = (float)t * invf;
    rc[idx] = cosf(ang);
    rs[idx] = sinf(ang);
}

// ---------------- RMSNorm (fp32 in, fp16 out) ----------------
__global__ void __launch_bounds__(256) rms_kernel(const float* __restrict__ x,
                                                  const float* __restrict__ w,
                                                  __half* __restrict__ out)
{
    int row = blockIdx.x;
    int tid = threadIdx.x;
    const float4* xr = (const float4*)(x + (size_t)row * Dv);
    float4 v0 = xr[tid];
    float4 v1 = xr[tid + 256];
    float ss = v0.x*v0.x + v0.y*v0.y + v0.z*v0.z + v0.w*v0.w
             + v1.x*v1.x + v1.y*v1.y + v1.z*v1.z + v1.w*v1.w;
    #pragma unroll
    for (int o = 16; o; o >>= 1) ss += __shfl_xor_sync(0xffffffffu, ss, o);
    __shared__ float red[8];
    if ((tid & 31) == 0) red[tid >> 5] = ss;
    __syncthreads();
    float tot = 0.f;
    #pragma unroll
    for (int i = 0; i < 8; i++) tot += red[i];
    float inv = rsqrtf(tot * (1.0f / Dv) + 1e-5f);
    const float4* wr = (const float4*)w;
    float4 w0 = wr[tid], w1 = wr[tid + 256];
    float4 o0 = { v0.x*inv*w0.x, v0.y*inv*w0.y, v0.z*inv*w0.z, v0.w*inv*w0.w };
    float4 o1 = { v1.x*inv*w1.x, v1.y*inv*w1.y, v1.z*inv*w1.z, v1.w*inv*w1.w };
    __half* orow = out + (size_t)row * Dv;
    *(uint2*)(orow + tid * 4)         = pack4h(o0);
    *(uint2*)(orow + (tid + 256) * 4) = pack4h(o1);
}

// ---------------- fp16 tensor-core GEMM (3-stage, TBK=64, ldmatrix) ----------------
// C[M,N] = A[M,K] @ B[N,K]^T, all operands fp16, accumulate fp32.
// mode 0: C(half) = acc ; mode 1: C(float) = acc + auxF(float)
// mode 2: C(half) = silu(auxH) * acc
#define STAGES 3

#define CP_ASYNC16(dst, src) asm volatile("cp.async.cg.shared.global [%0], [%1], 16;\n" :: "r"(dst), "l"(src))
#define CP_COMMIT() asm volatile("cp.async.commit_group;\n" ::)
#define CP_WAIT(n)  asm volatile("cp.async.wait_group %0;\n" :: "n"(n))

#define LDSM4(r0, r1, r2, r3, addr) \
    asm volatile("ldmatrix.sync.aligned.m8n8.x4.shared.b16 {%0,%1,%2,%3}, [%4];" \
        : "=r"(r0), "=r"(r1), "=r"(r2), "=r"(r3) : "r"(addr))

#define MMA_F16(d, a, b) \
    asm volatile("mma.sync.aligned.m16n8k16.row.col.f32.f16.f16.f32 " \
        "{%0,%1,%2,%3}, {%4,%5,%6,%7}, {%8,%9}, {%0,%1,%2,%3};" \
        : "+f"(d[0]), "+f"(d[1]), "+f"(d[2]), "+f"(d[3]) \
        : "r"(a[0]), "r"(a[1]), "r"(a[2]), "r"(a[3]), "r"(b[0]), "r"(b[1]))

__global__ void __launch_bounds__(256, 2) gemm_h(
    const __half* __restrict__ A, int K, int mode, const void* __restrict__ aux,
    const __half* __restrict__ B0, void* __restrict__ C0, int N0, int nb0,
    const __half* __restrict__ B1, void* __restrict__ C1, int N1, int nb1,
    const __half* __restrict__ B2, void* __restrict__ C2, int N2, int nb2)
{
    extern __shared__ __half smem[];
    // per stage: As 128 rows x 64 halves (16KB), Bs same; stage stride 32KB
    unsigned sbase = (unsigned)__cvta_generic_to_shared(smem);

    int bx = blockIdx.x;
    const __half* Bw; void* C; int N; int bnb;
    if (bx < nb0)            { Bw = B0; C = C0; N = N0; bnb = bx; }
    else if (bx < nb0 + nb1) { Bw = B1; C = C1; N = N1; bnb = bx - nb0; }
    else                     { Bw = B2; C = C2; N = N2; bnb = bx - nb0 - nb1; }

    int tid  = threadIdx.x;
    int bm = blockIdx.y * 128;
    int bn = bnb * 128;
    int lane = tid & 31, warp = tid >> 5;
    int wm = warp >> 1, wn = warp & 1;
    int g  = lane >> 2, tig = lane & 3;

    // --- cp.async descriptors: 4 x 16B per thread per operand per ktile ---
    unsigned dstoff[4];
    const __half* srcA[4];
    const __half* srcB[4];
    #pragma unroll
    for (int i = 0; i < 4; i++) {
        int lin = tid + i * 256;
        int row = lin >> 3, c = lin & 7;
        dstoff[i] = (unsigned)(row * 128 + ((c ^ (row & 7)) << 4));   // bytes
        srcA[i] = A  + (size_t)(bm + row) * K + c * 8;
        srcB[i] = Bw + (size_t)(bn + row) * K + c * 8;
    }

    // --- ldmatrix lane offsets (bytes, relative to stage operand base) ---
    // A: x4 tiles (t = lane>>3): rows +8 if (t&1), k-chunk +1 if (t>>1)
    int t4 = lane >> 3;
    unsigned aoff[2][4], boff[4][4];
    #pragma unroll
    for (int mi = 0; mi < 2; mi++) {
        int row = wm * 32 + mi * 16 + (lane & 7) + (t4 & 1) * 8;
        #pragma unroll
        for (int ks = 0; ks < 4; ks++) {
            int chunk = 2 * ks + (t4 >> 1);
            aoff[mi][ks] = (unsigned)(row * 128 + ((chunk ^ (row & 7)) << 4));
        }
    }
    // B: rows = n, +8 if (t>>1), k-chunk +1 if (t&1)
    #pragma unroll
    for (int np = 0; np < 4; np++) {
        int row = wn * 64 + np * 16 + (lane & 7) + (t4 >> 1) * 8;
        #pragma unroll
        for (int ks = 0; ks < 4; ks++) {
            int chunk = 2 * ks + (t4 & 1);
            boff[np][ks] = (unsigned)(row * 128 + ((chunk ^ (row & 7)) << 4));
        }
    }

    float acc[2][8][4];
    #pragma unroll
    for (int mi = 0; mi < 2; mi++)
        #pragma unroll
        for (int ni = 0; ni < 8; ni++)
            #pragma unroll
            for (int q = 0; q < 4; q++) acc[mi][ni][q] = 0.f;

    const int NT = K >> 6;   // TBK = 64

    #pragma unroll
    for (int s = 0; s < STAGES - 1; s++) {
        unsigned da = sbase + (unsigned)s * 32768u;
        unsigned db = da + 16384u;
        #pragma unroll
        for (int i = 0; i < 4; i++) {
            CP_ASYNC16(da + dstoff[i], srcA[i] + (size_t)s * 64);
            CP_ASYNC16(db + dstoff[i], srcB[i] + (size_t)s * 64);
        }
        CP_COMMIT();
    }

    for (int kt = 0; kt < NT; kt++) {
        int st = kt % STAGES;
        CP_WAIT(STAGES - 2);
        __syncthreads();

        int pf = kt + STAGES - 1;
        if (pf < NT) {
            int pst = pf % STAGES;
            unsigned da = sbase + (unsigned)pst * 32768u;
            unsigned db = da + 16384u;
            #pragma unroll
            for (int i = 0; i < 4; i++) {
                CP_ASYNC16(da + dstoff[i], srcA[i] + (size_t)pf * 64);
                CP_ASYNC16(db + dstoff[i], srcB[i] + (size_t)pf * 64);
            }
        }
        CP_COMMIT();

        unsigned AsB = sbase + (unsigned)st * 32768u;
        unsigned BsB = AsB + 16384u;

        #pragma unroll
        for (int ks = 0; ks < 4; ks++) {
            unsigned af[2][4];
            LDSM4(af[0][0], af[0][1], af[0][2], af[0][3], AsB + aoff[0][ks]);
            LDSM4(af[1][0], af[1][1], af[1][2], af[1][3], AsB + aoff[1][ks]);
            unsigned bf[8][2];
            #pragma unroll
            for (int np = 0; np < 4; np++)
                LDSM4(bf[2*np][0], bf[2*np][1], bf[2*np+1][0], bf[2*np+1][1],
                      BsB + boff[np][ks]);
            #pragma unroll
            for (int mi = 0; mi < 2; mi++)
                #pragma unroll
                for (int ni = 0; ni < 8; ni++)
                    MMA_F16(acc[mi][ni], af[mi], bf[ni]);
        }
    }

    // --- epilogue ---
    #pragma unroll
    for (int mi = 0; mi < 2; mi++) {
        int row0 = bm + wm * 32 + mi * 16 + g;
        #pragma unroll
        for (int half = 0; half < 2; half++) {
            int row = row0 + half * 8;
            size_t rowoff = (size_t)row * N;
            #pragma unroll
            for (int ni = 0; ni < 8; ni++) {
                int col = bn + wn * 64 + ni * 8 + 2 * tig;
                size_t idx = rowoff + col;
                float vx = acc[mi][ni][half * 2 + 0];
                float vy = acc[mi][ni][half * 2 + 1];
                if (mode == 1) {
                    float2 rsd = *(const float2*)((const float*)aux + idx);
                    vx += rsd.x; vy += rsd.y;
                    float2 o = { vx, vy };
                    *(float2*)((float*)C + idx) = o;
                } else {
                    if (mode == 2) {
                        __half2 gh = *(const __half2*)((const __half*)aux + idx);
                        float2 gf = __half22float2(gh);
                        vx *= gf.x / (1.f + __expf(-gf.x));
                        vy *= gf.y / (1.f + __expf(-gf.y));
                    }
                    __half2 o = __floats2half2_rn(vx, vy);
                    *(__half2*)((__half*)C + idx) = o;
                }
            }
        }
    }
}

// ---------------- fused per-head Us projection (+ optional RoPE) ----------------
// reads half rank activations, fp32 Us weights; writes fp32 (tf32-rounded) q/k/v
__global__ void __launch_bounds__(256) usproj_fused(
    const __half* __restrict__ qr, const __half* __restrict__ kr, const __half* __restrict__ vr,
    const float* __restrict__ qUs, const float* __restrict__ kUs, const float* __restrict__ vUs,
    float* __restrict__ qb, float* __restrict__ kb, float* __restrict__ vb,
    const float* __restrict__ rc, const float* __restrict__ rs)
{
    __shared__ __align__(16) float inT[32][64];
    __shared__ __align__(16) float UsT[32][64];
    __shared__ __align__(16) float os [64][64];
    int y = blockIdx.y;
    const __half* in; const float* Us; float* out; int heads, h, rope;
    if (y < 32)      { in = qr; Us = qUs; out = qb; heads = 32; h = y;      rope = 1; }
    else if (y < 40) { in = kr; Us = kUs; out = kb; heads = 8;  h = y - 32; rope = 1; }
    else             { in = vr; Us = vUs; out = vb; heads = 8;  h = y - 40; rope = 0; }

    int bt0 = blockIdx.x * 64;
    int tid = threadIdx.x;
    int ldin = heads * 32;

    {
        int d = tid >> 2; int r0 = (tid & 3) * 8;
        const float* p = Us + ((size_t)h * 64 + d) * 32 + r0;
        float4 u0 = *(const float4*)p;
        float4 u1 = *(const float4*)(p + 4);
        UsT[r0+0][d]=u0.x; UsT[r0+1][d]=u0.y; UsT[r0+2][d]=u0.z; UsT[r0+3][d]=u0.w;
        UsT[r0+4][d]=u1.x; UsT[r0+5][d]=u1.y; UsT[r0+6][d]=u1.z; UsT[r0+7][d]=u1.w;
    }
    {
        int i = tid >> 2; int r0 = (tid & 3) * 8;
        const __half* p = in + (size_t)(bt0 + i) * ldin + h * 32 + r0;
        uint4 u = *(const uint4*)p;
        float2 f0 = __half22float2(*(__half2*)&u.x);
        float2 f1 = __half22float2(*(__half2*)&u.y);
        float2 f2 = __half22float2(*(__half2*)&u.z);
        float2 f3 = __half22float2(*(__half2*)&u.w);
        inT[r0+0][i]=f0.x; inT[r0+1][i]=f0.y; inT[r0+2][i]=f1.x; inT[r0+3][i]=f1.y;
        inT[r0+4][i]=f2.x; inT[r0+5][i]=f2.y; inT[r0+6][i]=f3.x; inT[r0+7][i]=f3.y;
    }
    __syncthreads();

    int tx = tid & 15, ty = tid >> 4;
    float acc[4][4] = {};
    #pragma unroll
    for (int r = 0; r < 32; r++) {
        float4 a = *(const float4*)&inT[r][ty*4];
        float4 b = *(const float4*)&UsT[r][tx*4];
        float av[4] = {a.x,a.y,a.z,a.w};
        float bv[4] = {b.x,b.y,b.z,b.w};
        #pragma unroll
        for (int rr = 0; rr < 4; rr++)
            #pragma unroll
            for (int cc = 0; cc < 4; cc++)
                acc[rr][cc] = fmaf(av[rr], bv[cc], acc[rr][cc]);
    }
    #pragma unroll
    for (int rr = 0; rr < 4; rr++)
        #pragma unroll
        for (int cc = 0; cc < 4; cc++)
            os[ty*4+rr][tx*4+cc] = acc[rr][cc];
    __syncthreads();

    if (!rope) {
        #pragma unroll
        for (int kk = 0; kk < 4; kk++) {
            int lin4 = tid + kk * 256;
            int i = lin4 >> 4; int d0 = (lin4 & 15) * 4;
            int bt = bt0 + i; int b = bt >> 10; int t = bt & 1023;
            float4 vv = *(const float4*)&os[i][d0];
            vv.x = tf32f(vv.x); vv.y = tf32f(vv.y); vv.z = tf32f(vv.z); vv.w = tf32f(vv.w);
            size_t addr = (((size_t)(b * heads + h)) * Tv + t) * 64 + d0;
            *(float4*)(out + addr) = vv;
        }
    } else {
        #pragma unroll
        for (int kk = 0; kk < 2; kk++) {
            int lin4 = tid + kk * 256;
            int i = lin4 >> 3; int d0 = (lin4 & 7) * 4;
            int bt = bt0 + i; int b = bt >> 10; int t = bt & 1023;
            float4 x1 = *(const float4*)&os[i][d0];
            float4 x2 = *(const float4*)&os[i][d0 + 32];
            float4 cc4 = *(const float4*)(rc + t * 32 + d0);
            float4 ss4 = *(const float4*)(rs + t * 32 + d0);
            float xx1[4] = {x1.x,x1.y,x1.z,x1.w};
            float xx2[4] = {x2.x,x2.y,x2.z,x2.w};
            float ca[4] = {cc4.x,cc4.y,cc4.z,cc4.w};
            float sa[4] = {ss4.x,ss4.y,ss4.z,ss4.w};
            float o1[4], o2[4];
            #pragma unroll
            for (int c = 0; c < 4; c++) {
                o1[c] = tf32f(xx1[c] * ca[c] - xx2[c] * sa[c]);
                o2[c] = tf32f(xx2[c] * ca[c] + xx1[c] * sa[c]);
            }
            size_t base = (((size_t)(b * heads + h)) * Tv + t) * 64;
            float4 w1 = {o1[0],o1[1],o1[2],o1[3]};
            float4 w2 = {o2[0],o2[1],o2[2],o2[3]};
            *(float4*)(out + base + d0)      = w1;
            *(float4*)(out + base + d0 + 32) = w2;
        }
    }
}

#define MMA_TF32(d, a, b) \
    asm volatile("mma.sync.aligned.m16n8k8.row.col.f32.tf32.tf32.f32 " \
        "{%0,%1,%2,%3}, {%4,%5,%6,%7}, {%8,%9}, {%0,%1,%2,%3};" \
        : "+f"(d[0]), "+f"(d[1]), "+f"(d[2]), "+f"(d[3]) \
        : "r"(a[0]), "r"(a[1]), "r"(a[2]), "r"(a[3]), "r"(b[0]), "r"(b[1]))

// ---------------- flash attention via tf32 MMA (causal, GQA 4:1); half ctx out ----------------
__global__ void __launch_bounds__(256) attn_kernel(const float* __restrict__ q,
                                                   const float* __restrict__ k,
                                                   const float* __restrict__ v,
                                                   __half* __restrict__ ctx)
{
    __shared__ __align__(16) float Qs[64][68];
    __shared__ __align__(16) float Ks[32][68];
    __shared__ __align__(16) float Vs[32][72];
    __shared__ __align__(16) float Ss[64][36];
    __shared__ float mrow[64], lrow[64], rsrow[64];

    int tid = threadIdx.x;
    int bh = blockIdx.y; int b = bh >> 5; int h = bh & 31; int hk = h >> 2;
    int q0 = blockIdx.x * 64;
    int lane = tid & 31, warp = tid >> 5;
    int g = lane >> 2, tig = lane & 3;
    int wq = warp >> 1;
    int wn = warp & 1;

    const float* qbase = q + (((size_t)(b * 32 + h)) * Tv + q0) * 64;
    #pragma unroll
    for (int kk = 0; kk < 4; kk++) {
        int lin = tid + kk * 256;
        int i = lin >> 4, d0 = (lin & 15) * 4;
        float4 qv = *(const float4*)(qbase + (size_t)i * 64 + d0);
        qv.x *= 0.125f; qv.y *= 0.125f; qv.z *= 0.125f; qv.w *= 0.125f;
        *(float4*)&Qs[i][d0] = qv;
    }
    if (tid < 64) { mrow[tid] = -INFINITY; lrow[tid] = 0.f; }

    float cacc[4][4];
    #pragma unroll
    for (int ni = 0; ni < 4; ni++)
        #pragma unroll
        for (int c = 0; c < 4; c++) cacc[ni][c] = 0.f;

    const float* kb0 = k + ((size_t)(b * 8 + hk)) * Tv * 64;
    const float* vb0 = v + ((size_t)(b * 8 + hk)) * Tv * 64;

    int qr0 = wq * 16 + g;
    int ntile = (q0 >> 5) + 2;
    for (int kt = 0; kt < ntile; kt++) {
        __syncthreads();
        #pragma unroll
        for (int kk = 0; kk < 2; kk++) {
            int lin = tid + kk * 256;
            int j = lin >> 4, d0 = (lin & 15) * 4;
            size_t off = ((size_t)(kt * 32 + j)) * 64 + d0;
            *(float4*)&Ks[j][d0] = *(const float4*)(kb0 + off);
            *(float4*)&Vs[j][d0] = *(const float4*)(vb0 + off);
        }
        __syncthreads();

        float sacc[2][4] = {};
        #pragma unroll
        for (int ks = 0; ks < 8; ks++) {
            int kc = ks * 8;
            unsigned af[4];
            af[0] = __float_as_uint(Qs[qr0][kc + tig]);
            af[1] = __float_as_uint(Qs[qr0 + 8][kc + tig]);
            af[2] = __float_as_uint(Qs[qr0][kc + tig + 4]);
            af[3] = __float_as_uint(Qs[qr0 + 8][kc + tig + 4]);
            #pragma unroll
            for (int ni = 0; ni < 2; ni++) {
                unsigned bf[2];
                int krow = wn * 16 + ni * 8 + g;
                bf[0] = __float_as_uint(Ks[krow][kc + tig]);
                bf[1] = __float_as_uint(Ks[krow][kc + tig + 4]);
                MMA_TF32(sacc[ni], af, bf);
            }
        }
        #pragma unroll
        for (int ni = 0; ni < 2; ni++)
            #pragma unroll
            for (int c = 0; c < 4; c++) {
                int row = qr0 + ((c >> 1) << 3);
                int col = wn * 16 + ni * 8 + 2 * tig + (c & 1);
                int qi = q0 + row, ki = kt * 32 + col;
                Ss[row][col] = (ki <= qi) ? sacc[ni][c] : -INFINITY;
            }
        __syncthreads();

        {
            int row = tid >> 2, part = tid & 3;
            float* sr = &Ss[row][part * 8];
            float mo = mrow[row];
            float pv[8];
            float mx = mo;
            #pragma unroll
            for (int j = 0; j < 8; j++) { pv[j] = sr[j]; mx = fmaxf(mx, pv[j]); }
            mx = fmaxf(mx, __shfl_xor_sync(0xffffffffu, mx, 1));
            mx = fmaxf(mx, __shfl_xor_sync(0xffffffffu, mx, 2));
            float sum = 0.f;
            #pragma unroll
            for (int j = 0; j < 8; j++) {
                float p = __expf(pv[j] - mx);
                sr[j] = p; sum += p;
            }
            sum += __shfl_xor_sync(0xffffffffu, sum, 1);
            sum += __shfl_xor_sync(0xffffffffu, sum, 2);
            if (part == 0) {
                float rsc = __expf(mo - mx);
                mrow[row] = mx;
                lrow[row] = lrow[row] * rsc + sum;
                rsrow[row] = rsc;
            }
        }
        __syncthreads();

        float r0s = rsrow[qr0], r1s = rsrow[qr0 + 8];
        #pragma unroll
        for (int ni = 0; ni < 4; ni++) {
            cacc[ni][0] *= r0s; cacc[ni][1] *= r0s;
            cacc[ni][2] *= r1s; cacc[ni][3] *= r1s;
        }
        #pragma unroll
        for (int ks = 0; ks < 4; ks++) {
            int kc = ks * 8;
            unsigned af[4];
            af[0] = __float_as_uint(Ss[qr0][kc + tig]);
            af[1] = __float_as_uint(Ss[qr0 + 8][kc + tig]);
            af[2] = __float_as_uint(Ss[qr0][kc + tig + 4]);
            af[3] = __float_as_uint(Ss[qr0 + 8][kc + tig + 4]);
            #pragma unroll
            for (int ni = 0; ni < 4; ni++) {
                unsigned bf[2];
                int vcol = wn * 32 + ni * 8 + g;
                bf[0] = __float_as_uint(Vs[kc + tig][vcol]);
                bf[1] = __float_as_uint(Vs[kc + tig + 4][vcol]);
                MMA_TF32(cacc[ni], af, bf);
            }
        }
    }

    float inv0 = 1.f / lrow[qr0];
    float inv1 = 1.f / lrow[qr0 + 8];
    #pragma unroll
    for (int ni = 0; ni < 4; ni++) {
        #pragma unroll
        for (int half = 0; half < 2; half++) {
            int row = qr0 + half * 8;
            float inv = half ? inv1 : inv0;
            int col = wn * 32 + ni * 8 + 2 * tig;
            size_t addr = ((size_t)(b * Tv + q0 + row)) * Dv + h * 64 + col;
            __half2 o = __floats2half2_rn(cacc[ni][half * 2 + 0] * inv,
                                          cacc[ni][half * 2 + 1] * inv);
            *(__half2*)(ctx + addr) = o;
        }
    }
}

// ---------------- launch ----------------
extern "C" void kernel_launch(void* const* d_in, const int* in_sizes, int n_in,
                              void* d_out, int out_size)
{
    const float* x     = (const float*)d_in[0];
    const float* ln1_w = (const float*)d_in[1];
    const float* ln2_w = (const float*)d_in[2];
    const float* q_Us  = (const float*)d_in[3];
    const float* q_V   = (const float*)d_in[4];
    const float* k_Us  = (const float*)d_in[5];
    const float* k_V   = (const float*)d_in[6];
    const float* v_Us  = (const float*)d_in[7];
    const float* v_V   = (const float*)d_in[8];
    const float* o_Us  = (const float*)d_in[9];
    const float* o_V   = (const float*)d_in[10];
    const float* g_Usw = (const float*)d_in[11];
    const float* g_Vw  = (const float*)d_in[12];
    const float* u_Usw = (const float*)d_in[13];
    const float* u_Vw  = (const float*)d_in[14];
    const float* d_Usw = (const float*)d_in[15];
    const float* d_Vw  = (const float*)d_in[16];
    float* out = (float*)d_out;

    __half *h1, *qr, *kr, *vr, *ctx, *orr, *h2, *gr, *ur, *gg, *ff, *dr, *wts;
    float *qb, *kb, *vb, *x1, *rc, *rs;
    cudaGetSymbolAddress((void**)&h1,  g_h1);
    cudaGetSymbolAddress((void**)&qr,  g_qr);
    cudaGetSymbolAddress((void**)&kr,  g_kr);
    cudaGetSymbolAddress((void**)&vr,  g_vr);
    cudaGetSymbolAddress((void**)&qb,  g_q);
    cudaGetSymbolAddress((void**)&kb,  g_k);
    cudaGetSymbolAddress((void**)&vb,  g_v);
    cudaGetSymbolAddress((void**)&ctx, g_ctx);
    cudaGetSymbolAddress((void**)&orr, g_or);
    cudaGetSymbolAddress((void**)&x1,  g_x1);
    cudaGetSymbolAddress((void**)&h2,  g_h2);
    cudaGetSymbolAddress((void**)&gr,  g_gr);
    cudaGetSymbolAddress((void**)&ur,  g_ur);
    cudaGetSymbolAddress((void**)&gg,  g_g);
    cudaGetSymbolAddress((void**)&ff,  g_ff);
    cudaGetSymbolAddress((void**)&dr,  g_dr);
    cudaGetSymbolAddress((void**)&rc,  g_ropec);
    cudaGetSymbolAddress((void**)&rs,  g_ropes);
    cudaGetSymbolAddress((void**)&wts, g_wts);

    static int smem_set = 0;
    if (!smem_set) {
        cudaFuncSetAttribute(gemm_h, cudaFuncAttributeMaxDynamicSharedMemorySize, 98304);
        smem_set = 1;
    }
    const int SM = 98304;
    dim3 blk(256);

    prep_weights<<<W_TOT/1024, blk>>>(wts, q_V, k_V, v_V, o_V, o_Us,
                                      g_Vw, u_Vw, g_Usw, u_Usw, d_Vw, d_Usw);

    rope_table_kernel<<<Tv*32/256, 256>>>(rc, rs);
    rms_kernel<<<BT, blk>>>(x, ln1_w, h1);

    // fused q/k/v rank projections
    gemm_h<<<dim3(12, 32), blk, SM>>>(h1, Dv, 0, nullptr,
        wts + W_QV, qr, Hv*Rv, 8,  wts + W_KV, kr, HKv*Rv, 2,  wts + W_VV, vr, HKv*Rv, 2);

    usproj_fused<<<dim3(BT/64, 48), blk>>>(qr, kr, vr, q_Us, k_Us, v_Us, qb, kb, vb, rc, rs);

    attn_kernel<<<dim3(Tv/64, Bv*Hv), blk>>>(qb, kb, vb, ctx);

    gemm_h<<<dim3(8, 32), blk, SM>>>(ctx, Dv, 0, nullptr,
        wts + W_OV, orr, ROv, 8,  nullptr, nullptr, 0, 0,  nullptr, nullptr, 0, 0);
    gemm_h<<<dim3(16, 32), blk, SM>>>(orr, ROv, 1, x,
        wts + W_OUS, x1, Dv, 16,  nullptr, nullptr, 0, 0,  nullptr, nullptr, 0, 0);

    rms_kernel<<<BT, blk>>>(x1, ln2_w, h2);

    gemm_h<<<dim3(16, 32), blk, SM>>>(h2, Dv, 0, nullptr,
        wts + W_GV, gr, RFv, 8,  wts + W_UV, ur, RFv, 8,  nullptr, nullptr, 0, 0);

    gemm_h<<<dim3(44, 32), blk, SM>>>(gr, RFv, 0, nullptr,
        wts + W_GUS, gg, Iv, 44,  nullptr, nullptr, 0, 0,  nullptr, nullptr, 0, 0);
    gemm_h<<<dim3(44, 32), blk, SM>>>(ur, RFv, 2, gg,
        wts + W_UUS, ff, Iv, 44,  nullptr, nullptr, 0, 0,  nullptr, nullptr, 0, 0);

    gemm_h<<<dim3(8, 32), blk, SM>>>(ff, Iv, 0, nullptr,
        wts + W_DV, dr, RFv, 8,  nullptr, nullptr, 0, 0,  nullptr, nullptr, 0, 0);
    gemm_h<<<dim3(16, 32), blk, SM>>>(dr, RFv, 1, x1,
        wts + W_DUS, out, Dv, 16,  nullptr, nullptr, 0, 0,  nullptr, nullptr, 0, 0);
}

// round 7
// speedup vs baseline: 3.0787x; 1.0945x over previous
#include <cuda_runtime.h>
#include <cuda_fp16.h>
#include <math.h>

// ---------------- problem constants ----------------
#define Bv   4
#define Tv   1024
#define Dv   2048
#define Hv   32
#define DHv  64
#define HKv  8
#define Rv   32
#define ROv  1024
#define RFv  1024
#define Iv   5632
#define BT   (Bv*Tv)     // 4096

// ---------------- scratch ----------------
__device__ __half g_h1 [BT*Dv];
__device__ __half g_qr [BT*(Hv*Rv)];
__device__ __half g_kr [BT*(HKv*Rv)];
__device__ __half g_vr [BT*(HKv*Rv)];
__device__ __half g_q  [Bv*Hv*Tv*DHv];
__device__ __half g_k  [Bv*HKv*Tv*DHv];
__device__ __half g_v  [Bv*HKv*Tv*DHv];
__device__ __half g_ctx[BT*Dv];
__device__ __half g_or [BT*ROv];
__device__ float  g_x1 [BT*Dv];
__device__ __half g_h2 [BT*Dv];
__device__ __half g_gr [BT*RFv];
__device__ __half g_ur [BT*RFv];
__device__ __half g_g  [BT*Iv];
__device__ __half g_ff [BT*Iv];
__device__ __half g_dr [BT*RFv];
__device__ float  g_ropec[Tv*32];
__device__ float  g_ropes[Tv*32];
// converted (half) weights, concatenated; offsets in elements
#define W_QV   0
#define W_KV   2097152
#define W_VV   2621440
#define W_OV   3145728
#define W_OUS  5242880
#define W_GV   7340032
#define W_UV   9437184
#define W_GUS  11534336
#define W_UUS  17301504
#define W_DV   23068672
#define W_DUS  28835840
#define W_TOT  30932992
__device__ __half g_wts[W_TOT];

// ---------------- helpers ----------------
__device__ __forceinline__ uint2 pack4h(float4 v) {
    __half2 a = __floats2half2_rn(v.x, v.y);
    __half2 b = __floats2half2_rn(v.z, v.w);
    uint2 r;
    r.x = *(unsigned*)&a;
    r.y = *(unsigned*)&b;
    return r;
}

// ---------------- fused weight prep: f32 -> f16 in ONE launch ----------------
__global__ void __launch_bounds__(256) prep_weights(
    __half* __restrict__ dst,
    const float* __restrict__ s0, const float* __restrict__ s1, const float* __restrict__ s2,
    const float* __restrict__ s3, const float* __restrict__ s4, const float* __restrict__ s5,
    const float* __restrict__ s6, const float* __restrict__ s7, const float* __restrict__ s8,
    const float* __restrict__ s9, const float* __restrict__ s10)
{
    long i = ((long)blockIdx.x * 256 + threadIdx.x) * 4;
    const float* src; long base;
    if (i < W_GUS) {
        if (i < W_OV) {
            if (i < W_KV)        { src = s0; base = W_QV; }
            else if (i < W_VV)   { src = s1; base = W_KV; }
            else                 { src = s2; base = W_VV; }
        } else {
            if (i < W_OUS)       { src = s3; base = W_OV; }
            else if (i < W_GV)   { src = s4; base = W_OUS; }
            else if (i < W_UV)   { src = s5; base = W_GV; }
            else                 { src = s6; base = W_UV; }
        }
    } else {
        if (i < W_UUS)           { src = s7; base = W_GUS; }
        else if (i < W_DV)       { src = s8; base = W_UUS; }
        else if (i < W_DUS)      { src = s9; base = W_DV; }
        else                     { src = s10; base = W_DUS; }
    }
    float4 v = *(const float4*)(src + (i - base));
    *(uint2*)(dst + i) = pack4h(v);
}

// ---------------- rope table ----------------
__global__ void rope_table_kernel(float* __restrict__ rc, float* __restrict__ rs)
{
    int idx = blockIdx.x * blockDim.x + threadIdx.x;
    int t = idx >> 5, d = idx & 31;
    float invf = expf(-0.28782313662425572f * (float)d);
    float ang = (float)t * invf;
    rc[idx] = cosf(ang);
    rs[idx] = sinf(ang);
}

// ---------------- RMSNorm (fp32 in, fp16 out) ----------------
__global__ void __launch_bounds__(256) rms_kernel(const float* __restrict__ x,
                                                  const float* __restrict__ w,
                                                  __half* __restrict__ out)
{
    int row = blockIdx.x;
    int tid = threadIdx.x;
    const float4* xr = (const float4*)(x + (size_t)row * Dv);
    float4 v0 = xr[tid];
    float4 v1 = xr[tid + 256];
    float ss = v0.x*v0.x + v0.y*v0.y + v0.z*v0.z + v0.w*v0.w
             + v1.x*v1.x + v1.y*v1.y + v1.z*v1.z + v1.w*v1.w;
    #pragma unroll
    for (int o = 16; o; o >>= 1) ss += __shfl_xor_sync(0xffffffffu, ss, o);
    __shared__ float red[8];
    if ((tid & 31) == 0) red[tid >> 5] = ss;
    __syncthreads();
    float tot = 0.f;
    #pragma unroll
    for (int i = 0; i < 8; i++) tot += red[i];
    float inv = rsqrtf(tot * (1.0f / Dv) + 1e-5f);
    const float4* wr = (const float4*)w;
    float4 w0 = wr[tid], w1 = wr[tid + 256];
    float4 o0 = { v0.x*inv*w0.x, v0.y*inv*w0.y, v0.z*inv*w0.z, v0.w*inv*w0.w };
    float4 o1 = { v1.x*inv*w1.x, v1.y*inv*w1.y, v1.z*inv*w1.z, v1.w*inv*w1.w };
    __half* orow = out + (size_t)row * Dv;
    *(uint2*)(orow + tid * 4)         = pack4h(o0);
    *(uint2*)(orow + (tid + 256) * 4) = pack4h(o1);
}

// ---------------- fp16 tensor-core GEMM (3-stage, TBK=64, ldmatrix) ----------------
#define STAGES 3

#define CP_ASYNC16(dst, src) asm volatile("cp.async.cg.shared.global [%0], [%1], 16;\n" :: "r"(dst), "l"(src))
#define CP_COMMIT() asm volatile("cp.async.commit_group;\n" ::)
#define CP_WAIT(n)  asm volatile("cp.async.wait_group %0;\n" :: "n"(n))

#define LDSM4(r0, r1, r2, r3, addr) \
    asm volatile("ldmatrix.sync.aligned.m8n8.x4.shared.b16 {%0,%1,%2,%3}, [%4];" \
        : "=r"(r0), "=r"(r1), "=r"(r2), "=r"(r3) : "r"(addr))

#define LDSM4T(r0, r1, r2, r3, addr) \
    asm volatile("ldmatrix.sync.aligned.m8n8.x4.trans.shared.b16 {%0,%1,%2,%3}, [%4];" \
        : "=r"(r0), "=r"(r1), "=r"(r2), "=r"(r3) : "r"(addr))

#define MMA_F16(d, a, b) \
    asm volatile("mma.sync.aligned.m16n8k16.row.col.f32.f16.f16.f32 " \
        "{%0,%1,%2,%3}, {%4,%5,%6,%7}, {%8,%9}, {%0,%1,%2,%3};" \
        : "+f"(d[0]), "+f"(d[1]), "+f"(d[2]), "+f"(d[3]) \
        : "r"(a[0]), "r"(a[1]), "r"(a[2]), "r"(a[3]), "r"(b[0]), "r"(b[1]))

__global__ void __launch_bounds__(256, 2) gemm_h(
    const __half* __restrict__ A, int K, int mode, const void* __restrict__ aux,
    const __half* __restrict__ B0, void* __restrict__ C0, int N0, int nb0,
    const __half* __restrict__ B1, void* __restrict__ C1, int N1, int nb1,
    const __half* __restrict__ B2, void* __restrict__ C2, int N2, int nb2)
{
    extern __shared__ __half smem[];
    unsigned sbase = (unsigned)__cvta_generic_to_shared(smem);

    int bx = blockIdx.x;
    const __half* Bw; void* C; int N; int bnb;
    if (bx < nb0)            { Bw = B0; C = C0; N = N0; bnb = bx; }
    else if (bx < nb0 + nb1) { Bw = B1; C = C1; N = N1; bnb = bx - nb0; }
    else                     { Bw = B2; C = C2; N = N2; bnb = bx - nb0 - nb1; }

    int tid  = threadIdx.x;
    int bm = blockIdx.y * 128;
    int bn = bnb * 128;
    int lane = tid & 31, warp = tid >> 5;
    int wm = warp >> 1, wn = warp & 1;
    int g  = lane >> 2, tig = lane & 3;

    unsigned dstoff[4];
    const __half* srcA[4];
    const __half* srcB[4];
    #pragma unroll
    for (int i = 0; i < 4; i++) {
        int lin = tid + i * 256;
        int row = lin >> 3, c = lin & 7;
        dstoff[i] = (unsigned)(row * 128 + ((c ^ (row & 7)) << 4));
        srcA[i] = A  + (size_t)(bm + row) * K + c * 8;
        srcB[i] = Bw + (size_t)(bn + row) * K + c * 8;
    }

    int t4 = lane >> 3;
    unsigned aoff[2][4], boff[4][4];
    #pragma unroll
    for (int mi = 0; mi < 2; mi++) {
        int row = wm * 32 + mi * 16 + (lane & 7) + (t4 & 1) * 8;
        #pragma unroll
        for (int ks = 0; ks < 4; ks++) {
            int chunk = 2 * ks + (t4 >> 1);
            aoff[mi][ks] = (unsigned)(row * 128 + ((chunk ^ (row & 7)) << 4));
        }
    }
    #pragma unroll
    for (int np = 0; np < 4; np++) {
        int row = wn * 64 + np * 16 + (lane & 7) + (t4 >> 1) * 8;
        #pragma unroll
        for (int ks = 0; ks < 4; ks++) {
            int chunk = 2 * ks + (t4 & 1);
            boff[np][ks] = (unsigned)(row * 128 + ((chunk ^ (row & 7)) << 4));
        }
    }

    float acc[2][8][4];
    #pragma unroll
    for (int mi = 0; mi < 2; mi++)
        #pragma unroll
        for (int ni = 0; ni < 8; ni++)
            #pragma unroll
            for (int q = 0; q < 4; q++) acc[mi][ni][q] = 0.f;

    const int NT = K >> 6;

    #pragma unroll
    for (int s = 0; s < STAGES - 1; s++) {
        unsigned da = sbase + (unsigned)s * 32768u;
        unsigned db = da + 16384u;
        #pragma unroll
        for (int i = 0; i < 4; i++) {
            CP_ASYNC16(da + dstoff[i], srcA[i] + (size_t)s * 64);
            CP_ASYNC16(db + dstoff[i], srcB[i] + (size_t)s * 64);
        }
        CP_COMMIT();
    }

    for (int kt = 0; kt < NT; kt++) {
        int st = kt % STAGES;
        CP_WAIT(STAGES - 2);
        __syncthreads();

        int pf = kt + STAGES - 1;
        if (pf < NT) {
            int pst = pf % STAGES;
            unsigned da = sbase + (unsigned)pst * 32768u;
            unsigned db = da + 16384u;
            #pragma unroll
            for (int i = 0; i < 4; i++) {
                CP_ASYNC16(da + dstoff[i], srcA[i] + (size_t)pf * 64);
                CP_ASYNC16(db + dstoff[i], srcB[i] + (size_t)pf * 64);
            }
        }
        CP_COMMIT();

        unsigned AsB = sbase + (unsigned)st * 32768u;
        unsigned BsB = AsB + 16384u;

        #pragma unroll
        for (int ks = 0; ks < 4; ks++) {
            unsigned af[2][4];
            LDSM4(af[0][0], af[0][1], af[0][2], af[0][3], AsB + aoff[0][ks]);
            LDSM4(af[1][0], af[1][1], af[1][2], af[1][3], AsB + aoff[1][ks]);
            unsigned bf[8][2];
            #pragma unroll
            for (int np = 0; np < 4; np++)
                LDSM4(bf[2*np][0], bf[2*np][1], bf[2*np+1][0], bf[2*np+1][1],
                      BsB + boff[np][ks]);
            #pragma unroll
            for (int mi = 0; mi < 2; mi++)
                #pragma unroll
                for (int ni = 0; ni < 8; ni++)
                    MMA_F16(acc[mi][ni], af[mi], bf[ni]);
        }
    }

    #pragma unroll
    for (int mi = 0; mi < 2; mi++) {
        int row0 = bm + wm * 32 + mi * 16 + g;
        #pragma unroll
        for (int half = 0; half < 2; half++) {
            int row = row0 + half * 8;
            size_t rowoff = (size_t)row * N;
            #pragma unroll
            for (int ni = 0; ni < 8; ni++) {
                int col = bn + wn * 64 + ni * 8 + 2 * tig;
                size_t idx = rowoff + col;
                float vx = acc[mi][ni][half * 2 + 0];
                float vy = acc[mi][ni][half * 2 + 1];
                if (mode == 1) {
                    float2 rsd = *(const float2*)((const float*)aux + idx);
                    vx += rsd.x; vy += rsd.y;
                    float2 o = { vx, vy };
                    *(float2*)((float*)C + idx) = o;
                } else {
                    if (mode == 2) {
                        __half2 gh = *(const __half2*)((const __half*)aux + idx);
                        float2 gf = __half22float2(gh);
                        vx *= gf.x / (1.f + __expf(-gf.x));
                        vy *= gf.y / (1.f + __expf(-gf.y));
                    }
                    __half2 o = __floats2half2_rn(vx, vy);
                    *(__half2*)((__half*)C + idx) = o;
                }
            }
        }
    }
}

// ---------------- fused per-head Us projection (+ RoPE); half out; q pre-scaled ----------------
__global__ void __launch_bounds__(256) usproj_fused(
    const __half* __restrict__ qr, const __half* __restrict__ kr, const __half* __restrict__ vr,
    const float* __restrict__ qUs, const float* __restrict__ kUs, const float* __restrict__ vUs,
    __half* __restrict__ qb, __half* __restrict__ kb, __half* __restrict__ vb,
    const float* __restrict__ rc, const float* __restrict__ rs)
{
    __shared__ __align__(16) float inT[32][64];
    __shared__ __align__(16) float UsT[32][64];
    __shared__ __align__(16) float os [64][64];
    int y = blockIdx.y;
    const __half* in; const float* Us; __half* out; int heads, h, rope;
    float osc = 1.0f;
    if (y < 32)      { in = qr; Us = qUs; out = qb; heads = 32; h = y;      rope = 1; osc = 0.125f; }
    else if (y < 40) { in = kr; Us = kUs; out = kb; heads = 8;  h = y - 32; rope = 1; }
    else             { in = vr; Us = vUs; out = vb; heads = 8;  h = y - 40; rope = 0; }

    int bt0 = blockIdx.x * 64;
    int tid = threadIdx.x;
    int ldin = heads * 32;

    {
        int d = tid >> 2; int r0 = (tid & 3) * 8;
        const float* p = Us + ((size_t)h * 64 + d) * 32 + r0;
        float4 u0 = *(const float4*)p;
        float4 u1 = *(const float4*)(p + 4);
        UsT[r0+0][d]=u0.x; UsT[r0+1][d]=u0.y; UsT[r0+2][d]=u0.z; UsT[r0+3][d]=u0.w;
        UsT[r0+4][d]=u1.x; UsT[r0+5][d]=u1.y; UsT[r0+6][d]=u1.z; UsT[r0+7][d]=u1.w;
    }
    {
        int i = tid >> 2; int r0 = (tid & 3) * 8;
        const __half* p = in + (size_t)(bt0 + i) * ldin + h * 32 + r0;
        uint4 u = *(const uint4*)p;
        float2 f0 = __half22float2(*(__half2*)&u.x);
        float2 f1 = __half22float2(*(__half2*)&u.y);
        float2 f2 = __half22float2(*(__half2*)&u.z);
        float2 f3 = __half22float2(*(__half2*)&u.w);
        inT[r0+0][i]=f0.x; inT[r0+1][i]=f0.y; inT[r0+2][i]=f1.x; inT[r0+3][i]=f1.y;
        inT[r0+4][i]=f2.x; inT[r0+5][i]=f2.y; inT[r0+6][i]=f3.x; inT[r0+7][i]=f3.y;
    }
    __syncthreads();

    int tx = tid & 15, ty = tid >> 4;
    float acc[4][4] = {};
    #pragma unroll
    for (int r = 0; r < 32; r++) {
        float4 a = *(const float4*)&inT[r][ty*4];
        float4 b = *(const float4*)&UsT[r][tx*4];
        float av[4] = {a.x,a.y,a.z,a.w};
        float bv[4] = {b.x,b.y,b.z,b.w};
        #pragma unroll
        for (int rr = 0; rr < 4; rr++)
            #pragma unroll
            for (int cc = 0; cc < 4; cc++)
                acc[rr][cc] = fmaf(av[rr], bv[cc], acc[rr][cc]);
    }
    #pragma unroll
    for (int rr = 0; rr < 4; rr++)
        #pragma unroll
        for (int cc = 0; cc < 4; cc++)
            os[ty*4+rr][tx*4+cc] = acc[rr][cc];
    __syncthreads();

    if (!rope) {
        #pragma unroll
        for (int kk = 0; kk < 4; kk++) {
            int lin4 = tid + kk * 256;
            int i = lin4 >> 4; int d0 = (lin4 & 15) * 4;
            int bt = bt0 + i; int b = bt >> 10; int t = bt & 1023;
            float4 vv = *(const float4*)&os[i][d0];
            size_t addr = (((size_t)(b * heads + h)) * Tv + t) * 64 + d0;
            *(uint2*)(out + addr) = pack4h(vv);
        }
    } else {
        #pragma unroll
        for (int kk = 0; kk < 2; kk++) {
            int lin4 = tid + kk * 256;
            int i = lin4 >> 3; int d0 = (lin4 & 7) * 4;
            int bt = bt0 + i; int b = bt >> 10; int t = bt & 1023;
            float4 x1 = *(const float4*)&os[i][d0];
            float4 x2 = *(const float4*)&os[i][d0 + 32];
            float4 cc4 = *(const float4*)(rc + t * 32 + d0);
            float4 ss4 = *(const float4*)(rs + t * 32 + d0);
            float xx1[4] = {x1.x,x1.y,x1.z,x1.w};
            float xx2[4] = {x2.x,x2.y,x2.z,x2.w};
            float ca[4] = {cc4.x,cc4.y,cc4.z,cc4.w};
            float sa[4] = {ss4.x,ss4.y,ss4.z,ss4.w};
            float4 w1, w2;
            float* o1 = &w1.x; float* o2 = &w2.x;
            #pragma unroll
            for (int c = 0; c < 4; c++) {
                o1[c] = (xx1[c] * ca[c] - xx2[c] * sa[c]) * osc;
                o2[c] = (xx2[c] * ca[c] + xx1[c] * sa[c]) * osc;
            }
            size_t base = (((size_t)(b * heads + h)) * Tv + t) * 64;
            *(uint2*)(out + base + d0)      = pack4h(w1);
            *(uint2*)(out + base + d0 + 32) = pack4h(w2);
        }
    }
}

// ---------------- flash attention, full fp16 MMA (causal, GQA 4:1) ----------------
__global__ void __launch_bounds__(256) attn_kernel(const __half* __restrict__ q,
                                                   const __half* __restrict__ k,
                                                   const __half* __restrict__ v,
                                                   __half* __restrict__ ctx)
{
    __shared__ __align__(16) __half Qs[64*64];   // 128B rows, xor-8 swizzle
    __shared__ __align__(16) __half Ks[32*64];
    __shared__ __align__(16) __half Vs[32*64];
    __shared__ __align__(16) float  Ss[64][36];
    __shared__ __align__(16) __half Ph[64*40];   // pitch 40 halves, no swizzle
    __shared__ float mrow[64], lrow[64], rsrow[64];

    unsigned QsB = (unsigned)__cvta_generic_to_shared(Qs);
    unsigned KsB = (unsigned)__cvta_generic_to_shared(Ks);
    unsigned VsB = (unsigned)__cvta_generic_to_shared(Vs);
    unsigned PhB = (unsigned)__cvta_generic_to_shared(Ph);

    int tid = threadIdx.x;
    int bh = blockIdx.y; int b = bh >> 5; int h = bh & 31; int hk = h >> 2;
    int q0 = blockIdx.x * 64;
    int lane = tid & 31, warp = tid >> 5;
    int g = lane >> 2, tig = lane & 3;
    int t4 = lane >> 3;
    int wq = warp >> 1;   // q-row block of 16
    int wn = warp & 1;    // S: key block 16 ; PV: d block 32

    // load Q (64 x 64 halves), swizzled
    const __half* qbase = q + (((size_t)(b * 32 + h)) * Tv + q0) * 64;
    #pragma unroll
    for (int kk = 0; kk < 2; kk++) {
        int lin = tid + kk * 256;
        int row = lin >> 3, c = lin & 7;
        uint4 u = *(const uint4*)(qbase + (size_t)row * 64 + c * 8);
        *(uint4*)((char*)Qs + row * 128 + ((c ^ (row & 7)) << 4)) = u;
    }
    if (tid < 64) { mrow[tid] = -INFINITY; lrow[tid] = 0.f; }

    // fragment offsets
    unsigned aoffQ[4], boffK[4], aoffP[2], voffV[2][2];
    {
        int rowA = wq * 16 + (lane & 7) + (t4 & 1) * 8;
        int rowB = wn * 16 + (lane & 7) + (t4 >> 1) * 8;
        #pragma unroll
        for (int ks = 0; ks < 4; ks++) {
            int ca = 2 * ks + (t4 >> 1);
            int cb = 2 * ks + (t4 & 1);
            aoffQ[ks] = (unsigned)(rowA * 128 + ((ca ^ (rowA & 7)) << 4));
            boffK[ks] = (unsigned)(rowB * 128 + ((cb ^ (rowB & 7)) << 4));
        }
        int rowP = wq * 16 + (lane & 7) + (t4 & 1) * 8;
        #pragma unroll
        for (int ks = 0; ks < 2; ks++) {
            int cp = 2 * ks + (t4 >> 1);
            aoffP[ks] = (unsigned)(rowP * 80 + cp * 16);
            int rowV = ks * 16 + (lane & 7) + (t4 & 1) * 8;
            #pragma unroll
            for (int np = 0; np < 2; np++) {
                int cv = ((wn * 32 + np * 16) >> 3) + (t4 >> 1);
                voffV[ks][np] = (unsigned)(rowV * 128 + ((cv ^ (rowV & 7)) << 4));
            }
        }
    }

    float cacc[4][4];
    #pragma unroll
    for (int ni = 0; ni < 4; ni++)
        #pragma unroll
        for (int c = 0; c < 4; c++) cacc[ni][c] = 0.f;

    const __half* kb0 = k + ((size_t)(b * 8 + hk)) * Tv * 64;
    const __half* vb0 = v + ((size_t)(b * 8 + hk)) * Tv * 64;

    int ntile = (q0 >> 5) + 2;
    for (int kt = 0; kt < ntile; kt++) {
        __syncthreads();
        {   // load K,V tiles (32 x 64 halves each), swizzled
            int row = tid >> 3, c = tid & 7;
            size_t off = ((size_t)(kt * 32 + row)) * 64 + c * 8;
            unsigned d = (unsigned)(row * 128 + ((c ^ (row & 7)) << 4));
            *(uint4*)((char*)Ks + d) = *(const uint4*)(kb0 + off);
            *(uint4*)((char*)Vs + d) = *(const uint4*)(vb0 + off);
        }
        __syncthreads();

        // ---- S = Q K^T ----
        float sacc[2][4] = {};
        #pragma unroll
        for (int ks = 0; ks < 4; ks++) {
            unsigned af[4], bf[4];
            LDSM4(af[0], af[1], af[2], af[3], QsB + aoffQ[ks]);
            LDSM4(bf[0], bf[1], bf[2], bf[3], KsB + boffK[ks]);
            unsigned b0[2] = { bf[0], bf[1] };
            unsigned b1[2] = { bf[2], bf[3] };
            MMA_F16(sacc[0], af, b0);
            MMA_F16(sacc[1], af, b1);
        }
        #pragma unroll
        for (int ni = 0; ni < 2; ni++)
            #pragma unroll
            for (int c = 0; c < 4; c++) {
                int row = wq * 16 + g + ((c >> 1) << 3);
                int col = wn * 16 + ni * 8 + 2 * tig + (c & 1);
                int qi = q0 + row, ki = kt * 32 + col;
                Ss[row][col] = (ki <= qi) ? sacc[ni][c] : -INFINITY;
            }
        __syncthreads();

        // ---- online softmax; write probs to Ph (half) ----
        {
            int row = tid >> 2, part = tid & 3;
            float* sr = &Ss[row][part * 8];
            __half* pr = Ph + row * 40 + part * 8;
            float mo = mrow[row];
            float pv[8];
            float mx = mo;
            #pragma unroll
            for (int j = 0; j < 8; j++) { pv[j] = sr[j]; mx = fmaxf(mx, pv[j]); }
            mx = fmaxf(mx, __shfl_xor_sync(0xffffffffu, mx, 1));
            mx = fmaxf(mx, __shfl_xor_sync(0xffffffffu, mx, 2));
            float sum = 0.f;
            #pragma unroll
            for (int j = 0; j < 8; j++) {
                pv[j] = __expf(pv[j] - mx);
                sum += pv[j];
            }
            #pragma unroll
            for (int j = 0; j < 4; j++)
                *(__half2*)(pr + 2 * j) = __floats2half2_rn(pv[2*j], pv[2*j+1]);
            sum += __shfl_xor_sync(0xffffffffu, sum, 1);
            sum += __shfl_xor_sync(0xffffffffu, sum, 2);
            if (part == 0) {
                float rsc = __expf(mo - mx);
                mrow[row] = mx;
                lrow[row] = lrow[row] * rsc + sum;
                rsrow[row] = rsc;
            }
        }
        __syncthreads();

        // ---- rescale + P V ----
        float r0s = rsrow[wq * 16 + g], r1s = rsrow[wq * 16 + g + 8];
        #pragma unroll
        for (int ni = 0; ni < 4; ni++) {
            cacc[ni][0] *= r0s; cacc[ni][1] *= r0s;
            cacc[ni][2] *= r1s; cacc[ni][3] *= r1s;
        }
        #pragma unroll
        for (int ks = 0; ks < 2; ks++) {
            unsigned af[4];
            LDSM4(af[0], af[1], af[2], af[3], PhB + aoffP[ks]);
            #pragma unroll
            for (int np = 0; np < 2; np++) {
                unsigned vf[4];
                LDSM4T(vf[0], vf[1], vf[2], vf[3], VsB + voffV[ks][np]);
                unsigned b0[2] = { vf[0], vf[1] };
                unsigned b1[2] = { vf[2], vf[3] };
                MMA_F16(cacc[np*2 + 0], af, b0);
                MMA_F16(cacc[np*2 + 1], af, b1);
            }
        }
    }

    // ---- epilogue ----
    int qr0 = wq * 16 + g;
    float inv0 = 1.f / lrow[qr0];
    float inv1 = 1.f / lrow[qr0 + 8];
    #pragma unroll
    for (int ni = 0; ni < 4; ni++) {
        #pragma unroll
        for (int hf = 0; hf < 2; hf++) {
            int row = qr0 + hf * 8;
            float inv = hf ? inv1 : inv0;
            int col = wn * 32 + ni * 8 + 2 * tig;
            size_t addr = ((size_t)(b * Tv + q0 + row)) * Dv + h * 64 + col;
            __half2 o = __floats2half2_rn(cacc[ni][hf * 2 + 0] * inv,
                                          cacc[ni][hf * 2 + 1] * inv);
            *(__half2*)(ctx + addr) = o;
        }
    }
}

// ---------------- launch ----------------
extern "C" void kernel_launch(void* const* d_in, const int* in_sizes, int n_in,
                              void* d_out, int out_size)
{
    const float* x     = (const float*)d_in[0];
    const float* ln1_w = (const float*)d_in[1];
    const float* ln2_w = (const float*)d_in[2];
    const float* q_Us  = (const float*)d_in[3];
    const float* q_V   = (const float*)d_in[4];
    const float* k_Us  = (const float*)d_in[5];
    const float* k_V   = (const float*)d_in[6];
    const float* v_Us  = (const float*)d_in[7];
    const float* v_V   = (const float*)d_in[8];
    const float* o_Us  = (const float*)d_in[9];
    const float* o_V   = (const float*)d_in[10];
    const float* g_Usw = (const float*)d_in[11];
    const float* g_Vw  = (const float*)d_in[12];
    const float* u_Usw = (const float*)d_in[13];
    const float* u_Vw  = (const float*)d_in[14];
    const float* d_Usw = (const float*)d_in[15];
    const float* d_Vw  = (const float*)d_in[16];
    float* out = (float*)d_out;

    __half *h1, *qr, *kr, *vr, *qb, *kb, *vb, *ctx, *orr, *h2, *gr, *ur, *gg, *ff, *dr, *wts;
    float *x1, *rc, *rs;
    cudaGetSymbolAddress((void**)&h1,  g_h1);
    cudaGetSymbolAddress((void**)&qr,  g_qr);
    cudaGetSymbolAddress((void**)&kr,  g_kr);
    cudaGetSymbolAddress((void**)&vr,  g_vr);
    cudaGetSymbolAddress((void**)&qb,  g_q);
    cudaGetSymbolAddress((void**)&kb,  g_k);
    cudaGetSymbolAddress((void**)&vb,  g_v);
    cudaGetSymbolAddress((void**)&ctx, g_ctx);
    cudaGetSymbolAddress((void**)&orr, g_or);
    cudaGetSymbolAddress((void**)&x1,  g_x1);
    cudaGetSymbolAddress((void**)&h2,  g_h2);
    cudaGetSymbolAddress((void**)&gr,  g_gr);
    cudaGetSymbolAddress((void**)&ur,  g_ur);
    cudaGetSymbolAddress((void**)&gg,  g_g);
    cudaGetSymbolAddress((void**)&ff,  g_ff);
    cudaGetSymbolAddress((void**)&dr,  g_dr);
    cudaGetSymbolAddress((void**)&rc,  g_ropec);
    cudaGetSymbolAddress((void**)&rs,  g_ropes);
    cudaGetSymbolAddress((void**)&wts, g_wts);

    static int smem_set = 0;
    if (!smem_set) {
        cudaFuncSetAttribute(gemm_h, cudaFuncAttributeMaxDynamicSharedMemorySize, 98304);
        smem_set = 1;
    }
    const int SM = 98304;
    dim3 blk(256);

    prep_weights<<<W_TOT/1024, blk>>>(wts, q_V, k_V, v_V, o_V, o_Us,
                                      g_Vw, u_Vw, g_Usw, u_Usw, d_Vw, d_Usw);

    rope_table_kernel<<<Tv*32/256, 256>>>(rc, rs);
    rms_kernel<<<BT, blk>>>(x, ln1_w, h1);

    gemm_h<<<dim3(12, 32), blk, SM>>>(h1, Dv, 0, nullptr,
        wts + W_QV, qr, Hv*Rv, 8,  wts + W_KV, kr, HKv*Rv, 2,  wts + W_VV, vr, HKv*Rv, 2);

    usproj_fused<<<dim3(BT/64, 48), blk>>>(qr, kr, vr, q_Us, k_Us, v_Us, qb, kb, vb, rc, rs);

    attn_kernel<<<dim3(Tv/64, Bv*Hv), blk>>>(qb, kb, vb, ctx);

    gemm_h<<<dim3(8, 32), blk, SM>>>(ctx, Dv, 0, nullptr,
        wts + W_OV, orr, ROv, 8,  nullptr, nullptr, 0, 0,  nullptr, nullptr, 0, 0);
    gemm_h<<<dim3(16, 32), blk, SM>>>(orr, ROv, 1, x,
        wts + W_OUS, x1, Dv, 16,  nullptr, nullptr, 0, 0,  nullptr, nullptr, 0, 0);

    rms_kernel<<<BT, blk>>>(x1, ln2_w, h2);

    gemm_h<<<dim3(16, 32), blk, SM>>>(h2, Dv, 0, nullptr,
        wts + W_GV, gr, RFv, 8,  wts + W_UV, ur, RFv, 8,  nullptr, nullptr, 0, 0);

    gemm_h<<<dim3(44, 32), blk, SM>>>(gr, RFv, 0, nullptr,
        wts + W_GUS, gg, Iv, 44,  nullptr, nullptr, 0, 0,  nullptr, nullptr, 0, 0);
    gemm_h<<<dim3(44, 32), blk, SM>>>(ur, RFv, 2, gg,
        wts + W_UUS, ff, Iv, 44,  nullptr, nullptr, 0, 0,  nullptr, nullptr, 0, 0);

    gemm_h<<<dim3(8, 32), blk, SM>>>(ff, Iv, 0, nullptr,
        wts + W_DV, dr, RFv, 8,  nullptr, nullptr, 0, 0,  nullptr, nullptr, 0, 0);
    gemm_h<<<dim3(16, 32), blk, SM>>>(dr, RFv, 1, x1,
        wts + W_DUS, out, Dv, 16,  nullptr, nullptr, 0, 0,  nullptr, nullptr, 0, 0);
}

// round 9
// speedup vs baseline: 3.1531x; 1.0242x over previous
#include <cuda_runtime.h>
#include <cuda_fp16.h>
#include <math.h>

// ---------------- problem constants ----------------
#define Bv   4
#define Tv   1024
#define Dv   2048
#define Hv   32
#define DHv  64
#define HKv  8
#define Rv   32
#define ROv  1024
#define RFv  1024
#define Iv   5632
#define BT   (Bv*Tv)     // 4096

// ---------------- scratch ----------------
__device__ __half g_h1 [BT*Dv];
__device__ __half g_qr [BT*(Hv*Rv)];
__device__ __half g_kr [BT*(HKv*Rv)];
__device__ __half g_vr [BT*(HKv*Rv)];
__device__ __half g_q  [Bv*Hv*Tv*DHv];
__device__ __half g_k  [Bv*HKv*Tv*DHv];
__device__ __half g_v  [Bv*HKv*Tv*DHv];
__device__ __half g_ctx[BT*Dv];
__device__ __half g_or [BT*ROv];
__device__ float  g_x1 [BT*Dv];
__device__ __half g_h2 [BT*Dv];
__device__ __half g_gr [BT*RFv];
__device__ __half g_ur [BT*RFv];
__device__ __half g_g  [BT*Iv];
__device__ __half g_ff [BT*Iv];
__device__ __half g_dr [BT*RFv];
__device__ float  g_ropec[Tv*32];
__device__ float  g_ropes[Tv*32];
// converted (half) weights, concatenated; offsets in elements
#define W_QV   0
#define W_KV   2097152
#define W_VV   2621440
#define W_OV   3145728
#define W_OUS  5242880
#define W_GV   7340032
#define W_UV   9437184
#define W_GUS  11534336
#define W_UUS  17301504
#define W_DV   23068672
#define W_DUS  28835840
#define W_TOT  30932992
#define NWBLK  (W_TOT/1024)     // 30208 weight-prep blocks
__device__ __half g_wts[W_TOT];

// ---------------- helpers ----------------
__device__ __forceinline__ uint2 pack4h(float4 v) {
    __half2 a = __floats2half2_rn(v.x, v.y);
    __half2 b = __floats2half2_rn(v.z, v.w);
    uint2 r;
    r.x = *(unsigned*)&a;
    r.y = *(unsigned*)&b;
    return r;
}

// ---------------- fused front-end: weight f32->f16 + rms1 + rope table ----------------
__global__ void __launch_bounds__(256) prep_all(
    __half* __restrict__ dst,
    const float* __restrict__ s0, const float* __restrict__ s1, const float* __restrict__ s2,
    const float* __restrict__ s3, const float* __restrict__ s4, const float* __restrict__ s5,
    const float* __restrict__ s6, const float* __restrict__ s7, const float* __restrict__ s8,
    const float* __restrict__ s9, const float* __restrict__ s10,
    const float* __restrict__ x, const float* __restrict__ ln1_w, __half* __restrict__ h1,
    float* __restrict__ rc, float* __restrict__ rs)
{
    int bx = blockIdx.x;
    int tid = threadIdx.x;
    if (bx < NWBLK) {
        long i = ((long)bx * 256 + tid) * 4;
        const float* src; long base;
        if (i < W_GUS) {
            if (i < W_OV) {
                if (i < W_KV)        { src = s0; base = W_QV; }
                else if (i < W_VV)   { src = s1; base = W_KV; }
                else                 { src = s2; base = W_VV; }
            } else {
                if (i < W_OUS)       { src = s3; base = W_OV; }
                else if (i < W_GV)   { src = s4; base = W_OUS; }
                else if (i < W_UV)   { src = s5; base = W_GV; }
                else                 { src = s6; base = W_UV; }
            }
        } else {
            if (i < W_UUS)           { src = s7; base = W_GUS; }
            else if (i < W_DV)       { src = s8; base = W_UUS; }
            else if (i < W_DUS)      { src = s9; base = W_DV; }
            else                     { src = s10; base = W_DUS; }
        }
        float4 v = *(const float4*)(src + (i - base));
        *(uint2*)(dst + i) = pack4h(v);
    } else if (bx < NWBLK + BT) {
        // rms1: one block per row
        int row = bx - NWBLK;
        const float4* xr = (const float4*)(x + (size_t)row * Dv);
        float4 v0 = xr[tid];
        float4 v1 = xr[tid + 256];
        float ss = v0.x*v0.x + v0.y*v0.y + v0.z*v0.z + v0.w*v0.w
                 + v1.x*v1.x + v1.y*v1.y + v1.z*v1.z + v1.w*v1.w;
        #pragma unroll
        for (int o = 16; o; o >>= 1) ss += __shfl_xor_sync(0xffffffffu, ss, o);
        __shared__ float red[8];
        if ((tid & 31) == 0) red[tid >> 5] = ss;
        __syncthreads();
        float tot = 0.f;
        #pragma unroll
        for (int i = 0; i < 8; i++) tot += red[i];
        float inv = rsqrtf(tot * (1.0f / Dv) + 1e-5f);
        const float4* wr = (const float4*)ln1_w;
        float4 w0 = wr[tid], w1 = wr[tid + 256];
        float4 o0 = { v0.x*inv*w0.x, v0.y*inv*w0.y, v0.z*inv*w0.z, v0.w*inv*w0.w };
        float4 o1 = { v1.x*inv*w1.x, v1.y*inv*w1.y, v1.z*inv*w1.z, v1.w*inv*w1.w };
        __half* orow = h1 + (size_t)row * Dv;
        *(uint2*)(orow + tid * 4)         = pack4h(o0);
        *(uint2*)(orow + (tid + 256) * 4) = pack4h(o1);
    } else {
        // rope table
        int idx = (bx - NWBLK - BT) * 256 + tid;
        int t = idx >> 5, d = idx & 31;
        float invf = expf(-0.28782313662425572f * (float)d);
        float ang = (float)t * invf;
        rc[idx] = cosf(ang);
        rs[idx] = sinf(ang);
    }
}

// ---------------- RMSNorm (fp32 in, fp16 out) ----------------
__global__ void __launch_bounds__(256) rms_kernel(const float* __restrict__ x,
                                                  const float* __restrict__ w,
                                                  __half* __restrict__ out)
{
    int row = blockIdx.x;
    int tid = threadIdx.x;
    const float4* xr = (const float4*)(x + (size_t)row * Dv);
    float4 v0 = xr[tid];
    float4 v1 = xr[tid + 256];
    float ss = v0.x*v0.x + v0.y*v0.y + v0.z*v0.z + v0.w*v0.w
             + v1.x*v1.x + v1.y*v1.y + v1.z*v1.z + v1.w*v1.w;
    #pragma unroll
    for (int o = 16; o; o >>= 1) ss += __shfl_xor_sync(0xffffffffu, ss, o);
    __shared__ float red[8];
    if ((tid & 31) == 0) red[tid >> 5] = ss;
    __syncthreads();
    float tot = 0.f;
    #pragma unroll
    for (int i = 0; i < 8; i++) tot += red[i];
    float inv = rsqrtf(tot * (1.0f / Dv) + 1e-5f);
    const float4* wr = (const float4*)w;
    float4 w0 = wr[tid], w1 = wr[tid + 256];
    float4 o0 = { v0.x*inv*w0.x, v0.y*inv*w0.y, v0.z*inv*w0.z, v0.w*inv*w0.w };
    float4 o1 = { v1.x*inv*w1.x, v1.y*inv*w1.y, v1.z*inv*w1.z, v1.w*inv*w1.w };
    __half* orow = out + (size_t)row * Dv;
    *(uint2*)(orow + tid * 4)         = pack4h(o0);
    *(uint2*)(orow + (tid + 256) * 4) = pack4h(o1);
}

// ---------------- fp16 tensor-core GEMM (3-stage, TBK=64, ldmatrix) ----------------
#define STAGES 3

#define CP_ASYNC16(dst, src) asm volatile("cp.async.cg.shared.global [%0], [%1], 16;\n" :: "r"(dst), "l"(src))
#define CP_COMMIT() asm volatile("cp.async.commit_group;\n" ::)
#define CP_WAIT(n)  asm volatile("cp.async.wait_group %0;\n" :: "n"(n))

#define LDSM4(r0, r1, r2, r3, addr) \
    asm volatile("ldmatrix.sync.aligned.m8n8.x4.shared.b16 {%0,%1,%2,%3}, [%4];" \
        : "=r"(r0), "=r"(r1), "=r"(r2), "=r"(r3) : "r"(addr))

#define LDSM4T(r0, r1, r2, r3, addr) \
    asm volatile("ldmatrix.sync.aligned.m8n8.x4.trans.shared.b16 {%0,%1,%2,%3}, [%4];" \
        : "=r"(r0), "=r"(r1), "=r"(r2), "=r"(r3) : "r"(addr))

#define MMA_F16(d, a, b) \
    asm volatile("mma.sync.aligned.m16n8k16.row.col.f32.f16.f16.f32 " \
        "{%0,%1,%2,%3}, {%4,%5,%6,%7}, {%8,%9}, {%0,%1,%2,%3};" \
        : "+f"(d[0]), "+f"(d[1]), "+f"(d[2]), "+f"(d[3]) \
        : "r"(a[0]), "r"(a[1]), "r"(a[2]), "r"(a[3]), "r"(b[0]), "r"(b[1]))

__global__ void __launch_bounds__(256, 2) gemm_h(
    const __half* __restrict__ A, int K, int mode, const void* __restrict__ aux,
    const __half* __restrict__ B0, void* __restrict__ C0, int N0, int nb0,
    const __half* __restrict__ B1, void* __restrict__ C1, int N1, int nb1,
    const __half* __restrict__ B2, void* __restrict__ C2, int N2, int nb2)
{
    extern __shared__ __half smem[];
    unsigned sbase = (unsigned)__cvta_generic_to_shared(smem);

    int bx = blockIdx.x;
    const __half* Bw; void* C; int N; int bnb;
    if (bx < nb0)            { Bw = B0; C = C0; N = N0; bnb = bx; }
    else if (bx < nb0 + nb1) { Bw = B1; C = C1; N = N1; bnb = bx - nb0; }
    else                     { Bw = B2; C = C2; N = N2; bnb = bx - nb0 - nb1; }

    int tid  = threadIdx.x;
    int bm = blockIdx.y * 128;
    int bn = bnb * 128;
    int lane = tid & 31, warp = tid >> 5;
    int wm = warp >> 1, wn = warp & 1;
    int g  = lane >> 2, tig = lane & 3;

    unsigned dstoff[4];
    const __half* srcA[4];
    const __half* srcB[4];
    #pragma unroll
    for (int i = 0; i < 4; i++) {
        int lin = tid + i * 256;
        int row = lin >> 3, c = lin & 7;
        dstoff[i] = (unsigned)(row * 128 + ((c ^ (row & 7)) << 4));
        srcA[i] = A  + (size_t)(bm + row) * K + c * 8;
        srcB[i] = Bw + (size_t)(bn + row) * K + c * 8;
    }

    int t4 = lane >> 3;
    unsigned aoff[2][4], boff[4][4];
    #pragma unroll
    for (int mi = 0; mi < 2; mi++) {
        int row = wm * 32 + mi * 16 + (lane & 7) + (t4 & 1) * 8;
        #pragma unroll
        for (int ks = 0; ks < 4; ks++) {
            int chunk = 2 * ks + (t4 >> 1);
            aoff[mi][ks] = (unsigned)(row * 128 + ((chunk ^ (row & 7)) << 4));
        }
    }
    #pragma unroll
    for (int np = 0; np < 4; np++) {
        int row = wn * 64 + np * 16 + (lane & 7) + (t4 >> 1) * 8;
        #pragma unroll
        for (int ks = 0; ks < 4; ks++) {
            int chunk = 2 * ks + (t4 & 1);
            boff[np][ks] = (unsigned)(row * 128 + ((chunk ^ (row & 7)) << 4));
        }
    }

    float acc[2][8][4];
    #pragma unroll
    for (int mi = 0; mi < 2; mi++)
        #pragma unroll
        for (int ni = 0; ni < 8; ni++)
            #pragma unroll
            for (int q = 0; q < 4; q++) acc[mi][ni][q] = 0.f;

    const int NT = K >> 6;

    #pragma unroll
    for (int s = 0; s < STAGES - 1; s++) {
        unsigned da = sbase + (unsigned)s * 32768u;
        unsigned db = da + 16384u;
        #pragma unroll
        for (int i = 0; i < 4; i++) {
            CP_ASYNC16(da + dstoff[i], srcA[i] + (size_t)s * 64);
            CP_ASYNC16(db + dstoff[i], srcB[i] + (size_t)s * 64);
        }
        CP_COMMIT();
    }

    for (int kt = 0; kt < NT; kt++) {
        int st = kt % STAGES;
        CP_WAIT(STAGES - 2);
        __syncthreads();

        int pf = kt + STAGES - 1;
        if (pf < NT) {
            int pst = pf % STAGES;
            unsigned da = sbase + (unsigned)pst * 32768u;
            unsigned db = da + 16384u;
            #pragma unroll
            for (int i = 0; i < 4; i++) {
                CP_ASYNC16(da + dstoff[i], srcA[i] + (size_t)pf * 64);
                CP_ASYNC16(db + dstoff[i], srcB[i] + (size_t)pf * 64);
            }
        }
        CP_COMMIT();

        unsigned AsB = sbase + (unsigned)st * 32768u;
        unsigned BsB = AsB + 16384u;

        #pragma unroll
        for (int ks = 0; ks < 4; ks++) {
            unsigned af[2][4];
            LDSM4(af[0][0], af[0][1], af[0][2], af[0][3], AsB + aoff[0][ks]);
            LDSM4(af[1][0], af[1][1], af[1][2], af[1][3], AsB + aoff[1][ks]);
            unsigned bf[8][2];
            #pragma unroll
            for (int np = 0; np < 4; np++)
                LDSM4(bf[2*np][0], bf[2*np][1], bf[2*np+1][0], bf[2*np+1][1],
                      BsB + boff[np][ks]);
            #pragma unroll
            for (int mi = 0; mi < 2; mi++)
                #pragma unroll
                for (int ni = 0; ni < 8; ni++)
                    MMA_F16(acc[mi][ni], af[mi], bf[ni]);
        }
    }

    #pragma unroll
    for (int mi = 0; mi < 2; mi++) {
        int row0 = bm + wm * 32 + mi * 16 + g;
        #pragma unroll
        for (int half = 0; half < 2; half++) {
            int row = row0 + half * 8;
            size_t rowoff = (size_t)row * N;
            #pragma unroll
            for (int ni = 0; ni < 8; ni++) {
                int col = bn + wn * 64 + ni * 8 + 2 * tig;
                size_t idx = rowoff + col;
                float vx = acc[mi][ni][half * 2 + 0];
                float vy = acc[mi][ni][half * 2 + 1];
                if (mode == 1) {
                    float2 rsd = *(const float2*)((const float*)aux + idx);
                    vx += rsd.x; vy += rsd.y;
                    float2 o = { vx, vy };
                    *(float2*)((float*)C + idx) = o;
                } else {
                    if (mode == 2) {
                        __half2 gh = *(const __half2*)((const __half*)aux + idx);
                        float2 gf = __half22float2(gh);
                        vx *= gf.x / (1.f + __expf(-gf.x));
                        vy *= gf.y / (1.f + __expf(-gf.y));
                    }
                    __half2 o = __floats2half2_rn(vx, vy);
                    *(__half2*)((__half*)C + idx) = o;
                }
            }
        }
    }
}

// ---------------- fused per-head Us projection (+ RoPE); half out; q pre-scaled ----------------
__global__ void __launch_bounds__(256) usproj_fused(
    const __half* __restrict__ qr, const __half* __restrict__ kr, const __half* __restrict__ vr,
    const float* __restrict__ qUs, const float* __restrict__ kUs, const float* __restrict__ vUs,
    __half* __restrict__ qb, __half* __restrict__ kb, __half* __restrict__ vb,
    const float* __restrict__ rc, const float* __restrict__ rs)
{
    __shared__ __align__(16) float inT[32][64];
    __shared__ __align__(16) float UsT[32][64];
    __shared__ __align__(16) float os [64][64];
    int y = blockIdx.y;
    const __half* in; const float* Us; __half* out; int heads, h, rope;
    float osc = 1.0f;
    if (y < 32)      { in = qr; Us = qUs; out = qb; heads = 32; h = y;      rope = 1; osc = 0.125f; }
    else if (y < 40) { in = kr; Us = kUs; out = kb; heads = 8;  h = y - 32; rope = 1; }
    else             { in = vr; Us = vUs; out = vb; heads = 8;  h = y - 40; rope = 0; }

    int bt0 = blockIdx.x * 64;
    int tid = threadIdx.x;
    int ldin = heads * 32;

    {
        int d = tid >> 2; int r0 = (tid & 3) * 8;
        const float* p = Us + ((size_t)h * 64 + d) * 32 + r0;
        float4 u0 = *(const float4*)p;
        float4 u1 = *(const float4*)(p + 4);
        UsT[r0+0][d]=u0.x; UsT[r0+1][d]=u0.y; UsT[r0+2][d]=u0.z; UsT[r0+3][d]=u0.w;
        UsT[r0+4][d]=u1.x; UsT[r0+5][d]=u1.y; UsT[r0+6][d]=u1.z; UsT[r0+7][d]=u1.w;
    }
    {
        int i = tid >> 2; int r0 = (tid & 3) * 8;
        const __half* p = in + (size_t)(bt0 + i) * ldin + h * 32 + r0;
        uint4 u = *(const uint4*)p;
        float2 f0 = __half22float2(*(__half2*)&u.x);
        float2 f1 = __half22float2(*(__half2*)&u.y);
        float2 f2 = __half22float2(*(__half2*)&u.z);
        float2 f3 = __half22float2(*(__half2*)&u.w);
        inT[r0+0][i]=f0.x; inT[r0+1][i]=f0.y; inT[r0+2][i]=f1.x; inT[r0+3][i]=f1.y;
        inT[r0+4][i]=f2.x; inT[r0+5][i]=f2.y; inT[r0+6][i]=f3.x; inT[r0+7][i]=f3.y;
    }
    __syncthreads();

    int tx = tid & 15, ty = tid >> 4;
    float acc[4][4] = {};
    #pragma unroll
    for (int r = 0; r < 32; r++) {
        float4 a = *(const float4*)&inT[r][ty*4];
        float4 b = *(const float4*)&UsT[r][tx*4];
        float av[4] = {a.x,a.y,a.z,a.w};
        float bv[4] = {b.x,b.y,b.z,b.w};
        #pragma unroll
        for (int rr = 0; rr < 4; rr++)
            #pragma unroll
            for (int cc = 0; cc < 4; cc++)
                acc[rr][cc] = fmaf(av[rr], bv[cc], acc[rr][cc]);
    }
    #pragma unroll
    for (int rr = 0; rr < 4; rr++)
        #pragma unroll
        for (int cc = 0; cc < 4; cc++)
            os[ty*4+rr][tx*4+cc] = acc[rr][cc];
    __syncthreads();

    if (!rope) {
        #pragma unroll
        for (int kk = 0; kk < 4; kk++) {
            int lin4 = tid + kk * 256;
            int i = lin4 >> 4; int d0 = (lin4 & 15) * 4;
            int bt = bt0 + i; int b = bt >> 10; int t = bt & 1023;
            float4 vv = *(const float4*)&os[i][d0];
            size_t addr = (((size_t)(b * heads + h)) * Tv + t) * 64 + d0;
            *(uint2*)(out + addr) = pack4h(vv);
        }
    } else {
        #pragma unroll
        for (int kk = 0; kk < 2; kk++) {
            int lin4 = tid + kk * 256;
            int i = lin4 >> 3; int d0 = (lin4 & 7) * 4;
            int bt = bt0 + i; int b = bt >> 10; int t = bt & 1023;
            float4 x1 = *(const float4*)&os[i][d0];
            float4 x2 = *(const float4*)&os[i][d0 + 32];
            float4 cc4 = *(const float4*)(rc + t * 32 + d0);
            float4 ss4 = *(const float4*)(rs + t * 32 + d0);
            float xx1[4] = {x1.x,x1.y,x1.z,x1.w};
            float xx2[4] = {x2.x,x2.y,x2.z,x2.w};
            float ca[4] = {cc4.x,cc4.y,cc4.z,cc4.w};
            float sa[4] = {ss4.x,ss4.y,ss4.z,ss4.w};
            float4 w1, w2;
            float* o1 = &w1.x; float* o2 = &w2.x;
            #pragma unroll
            for (int c = 0; c < 4; c++) {
                o1[c] = (xx1[c] * ca[c] - xx2[c] * sa[c]) * osc;
                o2[c] = (xx2[c] * ca[c] + xx1[c] * sa[c]) * osc;
            }
            size_t base = (((size_t)(b * heads + h)) * Tv + t) * 64;
            *(uint2*)(out + base + d0)      = pack4h(w1);
            *(uint2*)(out + base + d0 + 32) = pack4h(w2);
        }
    }
}

// ---------------- flash attention, fp16 MMA, BQ=64 BK=64 (causal, GQA 4:1) ----------------
// dynamic smem layout (bytes):
//   Qs [0, 8192)      64x64 half, swizzled
//   Ks [8192, 16384)  64x64 half, swizzled
//   Vs [16384, 24576) 64x64 half, swizzled
//   Ss [24576, 41984) 64x68 float
//   Ph [41984, 51200) 64x72 half (pitch 144B)
#define ATTN_SMEM 51200
__global__ void __launch_bounds__(256) attn_kernel(const __half* __restrict__ q,
                                                   const __half* __restrict__ k,
                                                   const __half* __restrict__ v,
                                                   __half* __restrict__ ctx)
{
    extern __shared__ char asmem[];
    float* Ssf = (float*)(asmem + 24576);
    __half* Phh = (__half*)(asmem + 41984);
    __shared__ float mrow[64], lrow[64], rsrow[64];

    unsigned sb  = (unsigned)__cvta_generic_to_shared(asmem);
    unsigned QsB = sb, KsB = sb + 8192, VsB = sb + 16384, PhB = sb + 41984;

    int tid = threadIdx.x;
    int bh = blockIdx.y; int b = bh >> 5; int h = bh & 31; int hk = h >> 2;
    int q0 = blockIdx.x * 64;
    int lane = tid & 31, warp = tid >> 5;
    int g = lane >> 2, tig = lane & 3;
    int t4 = lane >> 3;
    int wq = warp >> 1;   // q-row block of 16
    int wn = warp & 1;    // S: key block of 32 ; PV: d block of 32

    // load Q (64x64 halves), swizzled
    const __half* qbase = q + (((size_t)(b * 32 + h)) * Tv + q0) * 64;
    #pragma unroll
    for (int kk = 0; kk < 2; kk++) {
        int lin = tid + kk * 256;
        int row = lin >> 3, c = lin & 7;
        uint4 u = *(const uint4*)(qbase + (size_t)row * 64 + c * 8);
        *(uint4*)(asmem + row * 128 + ((c ^ (row & 7)) << 4)) = u;
    }
    if (tid < 64) { mrow[tid] = -INFINITY; lrow[tid] = 0.f; }

    // fragment offsets
    unsigned aoffQ[4], boffK[2][4], aoffP[4], voffV[4][2];
    {
        int rowA = wq * 16 + (lane & 7) + (t4 & 1) * 8;
        #pragma unroll
        for (int ks = 0; ks < 4; ks++) {
            int ca = 2 * ks + (t4 >> 1);
            aoffQ[ks] = (unsigned)(rowA * 128 + ((ca ^ (rowA & 7)) << 4));
        }
        #pragma unroll
        for (int nb = 0; nb < 2; nb++) {
            int rowB = wn * 32 + nb * 16 + (lane & 7) + (t4 >> 1) * 8;
            #pragma unroll
            for (int ks = 0; ks < 4; ks++) {
                int cb = 2 * ks + (t4 & 1);
                boffK[nb][ks] = (unsigned)(rowB * 128 + ((cb ^ (rowB & 7)) << 4));
            }
        }
        int rowP = wq * 16 + (lane & 7) + (t4 & 1) * 8;
        #pragma unroll
        for (int ks = 0; ks < 4; ks++) {
            int cp = 2 * ks + (t4 >> 1);
            aoffP[ks] = (unsigned)(rowP * 144 + cp * 16);
            int rowV = ks * 16 + (lane & 7) + (t4 & 1) * 8;
            #pragma unroll
            for (int np = 0; np < 2; np++) {
                int cv = wn * 4 + np * 2 + (t4 >> 1);
                voffV[ks][np] = (unsigned)(rowV * 128 + ((cv ^ (rowV & 7)) << 4));
            }
        }
    }

    float cacc[4][4];
    #pragma unroll
    for (int ni = 0; ni < 4; ni++)
        #pragma unroll
        for (int c = 0; c < 4; c++) cacc[ni][c] = 0.f;

    const __half* kb0 = k + ((size_t)(b * 8 + hk)) * Tv * 64;
    const __half* vb0 = v + ((size_t)(b * 8 + hk)) * Tv * 64;

    int ntile = (q0 >> 6) + 1;
    for (int kt = 0; kt < ntile; kt++) {
        __syncthreads();
        #pragma unroll
        for (int kk = 0; kk < 2; kk++) {   // K,V: 64x64 halves each
            int lin = tid + kk * 256;
            int row = lin >> 3, c = lin & 7;
            size_t off = ((size_t)(kt * 64 + row)) * 64 + c * 8;
            unsigned d = (unsigned)(row * 128 + ((c ^ (row & 7)) << 4));
            *(uint4*)(asmem + 8192 + d)  = *(const uint4*)(kb0 + off);
            *(uint4*)(asmem + 16384 + d) = *(const uint4*)(vb0 + off);
        }
        __syncthreads();

        // ---- S = Q K^T : warp computes 16 rows x 32 keys ----
        float sacc[4][4] = {};
        #pragma unroll
        for (int ks = 0; ks < 4; ks++) {
            unsigned af[4];
            LDSM4(af[0], af[1], af[2], af[3], QsB + aoffQ[ks]);
            #pragma unroll
            for (int nb = 0; nb < 2; nb++) {
                unsigned bf[4];
                LDSM4(bf[0], bf[1], bf[2], bf[3], KsB + boffK[nb][ks]);
                unsigned b0[2] = { bf[0], bf[1] };
                unsigned b1[2] = { bf[2], bf[3] };
                MMA_F16(sacc[nb*2 + 0], af, b0);
                MMA_F16(sacc[nb*2 + 1], af, b1);
            }
        }
        #pragma unroll
        for (int ni = 0; ni < 4; ni++)
            #pragma unroll
            for (int c = 0; c < 4; c++) {
                int row = wq * 16 + g + ((c >> 1) << 3);
                int col = wn * 32 + ni * 8 + 2 * tig + (c & 1);
                int qi = q0 + row, ki = kt * 64 + col;
                Ssf[row * 68 + col] = (ki <= qi) ? sacc[ni][c] : -INFINITY;
            }
        __syncthreads();

        // ---- online softmax over 64 cols; write probs to Ph (half) ----
        {
            int row = tid >> 2, part = tid & 3;
            float* sr = Ssf + row * 68 + part * 16;
            __half* pr = Phh + row * 72 + part * 16;
            float mo = mrow[row];
            float pv[16];
            float mx = mo;
            #pragma unroll
            for (int j = 0; j < 16; j++) { pv[j] = sr[j]; mx = fmaxf(mx, pv[j]); }
            mx = fmaxf(mx, __shfl_xor_sync(0xffffffffu, mx, 1));
            mx = fmaxf(mx, __shfl_xor_sync(0xffffffffu, mx, 2));
            float sum = 0.f;
            #pragma unroll
            for (int j = 0; j < 16; j++) {
                pv[j] = __expf(pv[j] - mx);
                sum += pv[j];
            }
            #pragma unroll
            for (int j = 0; j < 8; j++)
                *(__half2*)(pr + 2 * j) = __floats2half2_rn(pv[2*j], pv[2*j+1]);
            sum += __shfl_xor_sync(0xffffffffu, sum, 1);
            sum += __shfl_xor_sync(0xffffffffu, sum, 2);
            if (part == 0) {
                float rsc = __expf(mo - mx);
                mrow[row] = mx;
                lrow[row] = lrow[row] * rsc + sum;
                rsrow[row] = rsc;
            }
        }
        __syncthreads();

        // ---- rescale + P V : warp computes 16 rows x 32 d-cols over 64 keys ----
        float r0s = rsrow[wq * 16 + g], r1s = rsrow[wq * 16 + g + 8];
        #pragma unroll
        for (int ni = 0; ni < 4; ni++) {
            cacc[ni][0] *= r0s; cacc[ni][1] *= r0s;
            cacc[ni][2] *= r1s; cacc[ni][3] *= r1s;
        }
        #pragma unroll
        for (int ks = 0; ks < 4; ks++) {
            unsigned af[4];
            LDSM4(af[0], af[1], af[2], af[3], PhB + aoffP[ks]);
            #pragma unroll
            for (int np = 0; np < 2; np++) {
                unsigned vf[4];
                LDSM4T(vf[0], vf[1], vf[2], vf[3], VsB + voffV[ks][np]);
                unsigned b0[2] = { vf[0], vf[1] };
                unsigned b1[2] = { vf[2], vf[3] };
                MMA_F16(cacc[np*2 + 0], af, b0);
                MMA_F16(cacc[np*2 + 1], af, b1);
            }
        }
    }

    // ---- epilogue ----
    int qr0 = wq * 16 + g;
    float inv0 = 1.f / lrow[qr0];
    float inv1 = 1.f / lrow[qr0 + 8];
    #pragma unroll
    for (int ni = 0; ni < 4; ni++) {
        #pragma unroll
        for (int hf = 0; hf < 2; hf++) {
            int row = qr0 + hf * 8;
            float inv = hf ? inv1 : inv0;
            int col = wn * 32 + ni * 8 + 2 * tig;
            size_t addr = ((size_t)(b * Tv + q0 + row)) * Dv + h * 64 + col;
            __half2 o = __floats2half2_rn(cacc[ni][hf * 2 + 0] * inv,
                                          cacc[ni][hf * 2 + 1] * inv);
            *(__half2*)(ctx + addr) = o;
        }
    }
}

// ---------------- launch ----------------
extern "C" void kernel_launch(void* const* d_in, const int* in_sizes, int n_in,
                              void* d_out, int out_size)
{
    const float* x     = (const float*)d_in[0];
    const float* ln1_w = (const float*)d_in[1];
    const float* ln2_w = (const float*)d_in[2];
    const float* q_Us  = (const float*)d_in[3];
    const float* q_V   = (const float*)d_in[4];
    const float* k_Us  = (const float*)d_in[5];
    const float* k_V   = (const float*)d_in[6];
    const float* v_Us  = (const float*)d_in[7];
    const float* v_V   = (const float*)d_in[8];
    const float* o_Us  = (const float*)d_in[9];
    const float* o_V   = (const float*)d_in[10];
    const float* g_Usw = (const float*)d_in[11];
    const float* g_Vw  = (const float*)d_in[12];
    const float* u_Usw = (const float*)d_in[13];
    const float* u_Vw  = (const float*)d_in[14];
    const float* d_Usw = (const float*)d_in[15];
    const float* d_Vw  = (const float*)d_in[16];
    float* out = (float*)d_out;

    __half *h1, *qr, *kr, *vr, *qb, *kb, *vb, *ctx, *orr, *h2, *gr, *ur, *gg, *ff, *dr, *wts;
    float *x1, *rc, *rs;
    cudaGetSymbolAddress((void**)&h1,  g_h1);
    cudaGetSymbolAddress((void**)&qr,  g_qr);
    cudaGetSymbolAddress((void**)&kr,  g_kr);
    cudaGetSymbolAddress((void**)&vr,  g_vr);
    cudaGetSymbolAddress((void**)&qb,  g_q);
    cudaGetSymbolAddress((void**)&kb,  g_k);
    cudaGetSymbolAddress((void**)&vb,  g_v);
    cudaGetSymbolAddress((void**)&ctx, g_ctx);
    cudaGetSymbolAddress((void**)&orr, g_or);
    cudaGetSymbolAddress((void**)&x1,  g_x1);
    cudaGetSymbolAddress((void**)&h2,  g_h2);
    cudaGetSymbolAddress((void**)&gr,  g_gr);
    cudaGetSymbolAddress((void**)&ur,  g_ur);
    cudaGetSymbolAddress((void**)&gg,  g_g);
    cudaGetSymbolAddress((void**)&ff,  g_ff);
    cudaGetSymbolAddress((void**)&dr,  g_dr);
    cudaGetSymbolAddress((void**)&rc,  g_ropec);
    cudaGetSymbolAddress((void**)&rs,  g_ropes);
    cudaGetSymbolAddress((void**)&wts, g_wts);

    static int smem_set = 0;
    if (!smem_set) {
        cudaFuncSetAttribute(gemm_h, cudaFuncAttributeMaxDynamicSharedMemorySize, 98304);
        cudaFuncSetAttribute(attn_kernel, cudaFuncAttributeMaxDynamicSharedMemorySize, ATTN_SMEM);
        smem_set = 1;
    }
    const int SM = 98304;
    dim3 blk(256);

    // fused front end: weight conversion + rms1 + rope table in ONE launch
    prep_all<<<NWBLK + BT + Tv*32/256, blk>>>(wts, q_V, k_V, v_V, o_V, o_Us,
                                              g_Vw, u_Vw, g_Usw, u_Usw, d_Vw, d_Usw,
                                              x, ln1_w, h1, rc, rs);

    gemm_h<<<dim3(12, 32), blk, SM>>>(h1, Dv, 0, nullptr,
        wts + W_QV, qr, Hv*Rv, 8,  wts + W_KV, kr, HKv*Rv, 2,  wts + W_VV, vr, HKv*Rv, 2);

    usproj_fused<<<dim3(BT/64, 48), blk>>>(qr, kr, vr, q_Us, k_Us, v_Us, qb, kb, vb, rc, rs);

    attn_kernel<<<dim3(Tv/64, Bv*Hv), blk, ATTN_SMEM>>>(qb, kb, vb, ctx);

    gemm_h<<<dim3(8, 32), blk, SM>>>(ctx, Dv, 0, nullptr,
        wts + W_OV, orr, ROv, 8,  nullptr, nullptr, 0, 0,  nullptr, nullptr, 0, 0);
    gemm_h<<<dim3(16, 32), blk, SM>>>(orr, ROv, 1, x,
        wts + W_OUS, x1, Dv, 16,  nullptr, nullptr, 0, 0,  nullptr, nullptr, 0, 0);

    rms_kernel<<<BT, blk>>>(x1, ln2_w, h2);

    gemm_h<<<dim3(16, 32), blk, SM>>>(h2, Dv, 0, nullptr,
        wts + W_GV, gr, RFv, 8,  wts + W_UV, ur, RFv, 8,  nullptr, nullptr, 0, 0);

    gemm_h<<<dim3(44, 32), blk, SM>>>(gr, RFv, 0, nullptr,
        wts + W_GUS, gg, Iv, 44,  nullptr, nullptr, 0, 0,  nullptr, nullptr, 0, 0);
    gemm_h<<<dim3(44, 32), blk, SM>>>(ur, RFv, 2, gg,
        wts + W_UUS, ff, Iv, 44,  nullptr, nullptr, 0, 0,  nullptr, nullptr, 0, 0);

    gemm_h<<<dim3(8, 32), blk, SM>>>(ff, Iv, 0, nullptr,
        wts + W_DV, dr, RFv, 8,  nullptr, nullptr, 0, 0,  nullptr, nullptr, 0, 0);
    gemm_h<<<dim3(16, 32), blk, SM>>>(dr, RFv, 1, x1,
        wts + W_DUS, out, Dv, 16,  nullptr, nullptr, 0, 0,  nullptr, nullptr, 0, 0);
}

// round 10
// speedup vs baseline: 3.2351x; 1.0260x over previous
#include <cuda_runtime.h>
#include <cuda_fp16.h>
#include <math.h>

// ---------------- problem constants ----------------
#define Bv   4
#define Tv   1024
#define Dv   2048
#define Hv   32
#define DHv  64
#define HKv  8
#define Rv   32
#define ROv  1024
#define RFv  1024
#define Iv   5632
#define BT   (Bv*Tv)     // 4096

// ---------------- scratch ----------------
__device__ __half g_h1 [BT*Dv];
__device__ __half g_qr [BT*(Hv*Rv)];
__device__ __half g_kr [BT*(HKv*Rv)];
__device__ __half g_vr [BT*(HKv*Rv)];
__device__ __half g_q  [Bv*Hv*Tv*DHv];
__device__ __half g_k  [Bv*HKv*Tv*DHv];
__device__ __half g_v  [Bv*HKv*Tv*DHv];
__device__ __half g_ctx[BT*Dv];
__device__ __half g_or [BT*ROv];
__device__ float  g_x1 [BT*Dv];
__device__ __half g_h2 [BT*Dv];
__device__ __half g_gr [BT*RFv];
__device__ __half g_ur [BT*RFv];
__device__ __half g_g  [BT*Iv];
__device__ __half g_ff [BT*Iv];
__device__ __half g_dr [BT*RFv];
__device__ float  g_ropec[Tv*32];
__device__ float  g_ropes[Tv*32];
// converted (half) weights, concatenated; offsets in elements
#define W_QV   0
#define W_KV   2097152
#define W_VV   2621440
#define W_OV   3145728
#define W_OUS  5242880
#define W_GV   7340032
#define W_UV   9437184
#define W_GUS  11534336
#define W_UUS  17301504
#define W_DV   23068672
#define W_DUS  28835840
#define W_TOT  30932992
#define NWBLK  (W_TOT/1024)     // 30208 weight-prep blocks
__device__ __half g_wts[W_TOT];

// ---------------- helpers ----------------
__device__ __forceinline__ uint2 pack4h(float4 v) {
    __half2 a = __floats2half2_rn(v.x, v.y);
    __half2 b = __floats2half2_rn(v.z, v.w);
    uint2 r;
    r.x = *(unsigned*)&a;
    r.y = *(unsigned*)&b;
    return r;
}

// ---------------- fused front-end: weight f32->f16 + rms1 + rope table ----------------
__global__ void __launch_bounds__(256) prep_all(
    __half* __restrict__ dst,
    const float* __restrict__ s0, const float* __restrict__ s1, const float* __restrict__ s2,
    const float* __restrict__ s3, const float* __restrict__ s4, const float* __restrict__ s5,
    const float* __restrict__ s6, const float* __restrict__ s7, const float* __restrict__ s8,
    const float* __restrict__ s9, const float* __restrict__ s10,
    const float* __restrict__ x, const float* __restrict__ ln1_w, __half* __restrict__ h1,
    float* __restrict__ rc, float* __restrict__ rs)
{
    int bx = blockIdx.x;
    int tid = threadIdx.x;
    if (bx < NWBLK) {
        long i = ((long)bx * 256 + tid) * 4;
        const float* src; long base;
        if (i < W_GUS) {
            if (i < W_OV) {
                if (i < W_KV)        { src = s0; base = W_QV; }
                else if (i < W_VV)   { src = s1; base = W_KV; }
                else                 { src = s2; base = W_VV; }
            } else {
                if (i < W_OUS)       { src = s3; base = W_OV; }
                else if (i < W_GV)   { src = s4; base = W_OUS; }
                else if (i < W_UV)   { src = s5; base = W_GV; }
                else                 { src = s6; base = W_UV; }
            }
        } else {
            if (i < W_UUS)           { src = s7; base = W_GUS; }
            else if (i < W_DV)       { src = s8; base = W_UUS; }
            else if (i < W_DUS)      { src = s9; base = W_DV; }
            else                     { src = s10; base = W_DUS; }
        }
        float4 v = *(const float4*)(src + (i - base));
        *(uint2*)(dst + i) = pack4h(v);
    } else if (bx < NWBLK + BT) {
        int row = bx - NWBLK;
        const float4* xr = (const float4*)(x + (size_t)row * Dv);
        float4 v0 = xr[tid];
        float4 v1 = xr[tid + 256];
        float ss = v0.x*v0.x + v0.y*v0.y + v0.z*v0.z + v0.w*v0.w
                 + v1.x*v1.x + v1.y*v1.y + v1.z*v1.z + v1.w*v1.w;
        #pragma unroll
        for (int o = 16; o; o >>= 1) ss += __shfl_xor_sync(0xffffffffu, ss, o);
        __shared__ float red[8];
        if ((tid & 31) == 0) red[tid >> 5] = ss;
        __syncthreads();
        float tot = 0.f;
        #pragma unroll
        for (int i = 0; i < 8; i++) tot += red[i];
        float inv = rsqrtf(tot * (1.0f / Dv) + 1e-5f);
        const float4* wr = (const float4*)ln1_w;
        float4 w0 = wr[tid], w1 = wr[tid + 256];
        float4 o0 = { v0.x*inv*w0.x, v0.y*inv*w0.y, v0.z*inv*w0.z, v0.w*inv*w0.w };
        float4 o1 = { v1.x*inv*w1.x, v1.y*inv*w1.y, v1.z*inv*w1.z, v1.w*inv*w1.w };
        __half* orow = h1 + (size_t)row * Dv;
        *(uint2*)(orow + tid * 4)         = pack4h(o0);
        *(uint2*)(orow + (tid + 256) * 4) = pack4h(o1);
    } else {
        int idx = (bx - NWBLK - BT) * 256 + tid;
        int t = idx >> 5, d = idx & 31;
        float invf = expf(-0.28782313662425572f * (float)d);
        float ang = (float)t * invf;
        rc[idx] = cosf(ang);
        rs[idx] = sinf(ang);
    }
}

// ---------------- RMSNorm (fp32 in, fp16 out) ----------------
__global__ void __launch_bounds__(256) rms_kernel(const float* __restrict__ x,
                                                  const float* __restrict__ w,
                                                  __half* __restrict__ out)
{
    int row = blockIdx.x;
    int tid = threadIdx.x;
    const float4* xr = (const float4*)(x + (size_t)row * Dv);
    float4 v0 = xr[tid];
    float4 v1 = xr[tid + 256];
    float ss = v0.x*v0.x + v0.y*v0.y + v0.z*v0.z + v0.w*v0.w
             + v1.x*v1.x + v1.y*v1.y + v1.z*v1.z + v1.w*v1.w;
    #pragma unroll
    for (int o = 16; o; o >>= 1) ss += __shfl_xor_sync(0xffffffffu, ss, o);
    __shared__ float red[8];
    if ((tid & 31) == 0) red[tid >> 5] = ss;
    __syncthreads();
    float tot = 0.f;
    #pragma unroll
    for (int i = 0; i < 8; i++) tot += red[i];
    float inv = rsqrtf(tot * (1.0f / Dv) + 1e-5f);
    const float4* wr = (const float4*)w;
    float4 w0 = wr[tid], w1 = wr[tid + 256];
    float4 o0 = { v0.x*inv*w0.x, v0.y*inv*w0.y, v0.z*inv*w0.z, v0.w*inv*w0.w };
    float4 o1 = { v1.x*inv*w1.x, v1.y*inv*w1.y, v1.z*inv*w1.z, v1.w*inv*w1.w };
    __half* orow = out + (size_t)row * Dv;
    *(uint2*)(orow + tid * 4)         = pack4h(o0);
    *(uint2*)(orow + (tid + 256) * 4) = pack4h(o1);
}

// ---------------- fp16 tensor-core GEMM (3-stage, TBK=64, ldmatrix) ----------------
#define STAGES 3

#define CP_ASYNC16(dst, src) asm volatile("cp.async.cg.shared.global [%0], [%1], 16;\n" :: "r"(dst), "l"(src))
#define CP_COMMIT() asm volatile("cp.async.commit_group;\n" ::)
#define CP_WAIT(n)  asm volatile("cp.async.wait_group %0;\n" :: "n"(n))

#define LDSM4(r0, r1, r2, r3, addr) \
    asm volatile("ldmatrix.sync.aligned.m8n8.x4.shared.b16 {%0,%1,%2,%3}, [%4];" \
        : "=r"(r0), "=r"(r1), "=r"(r2), "=r"(r3) : "r"(addr))

#define LDSM4T(r0, r1, r2, r3, addr) \
    asm volatile("ldmatrix.sync.aligned.m8n8.x4.trans.shared.b16 {%0,%1,%2,%3}, [%4];" \
        : "=r"(r0), "=r"(r1), "=r"(r2), "=r"(r3) : "r"(addr))

#define MMA_F16(d, a, b) \
    asm volatile("mma.sync.aligned.m16n8k16.row.col.f32.f16.f16.f32 " \
        "{%0,%1,%2,%3}, {%4,%5,%6,%7}, {%8,%9}, {%0,%1,%2,%3};" \
        : "+f"(d[0]), "+f"(d[1]), "+f"(d[2]), "+f"(d[3]) \
        : "r"(a[0]), "r"(a[1]), "r"(a[2]), "r"(a[3]), "r"(b[0]), "r"(b[1]))

__global__ void __launch_bounds__(256, 2) gemm_h(
    const __half* __restrict__ A, int K, int mode, const void* __restrict__ aux,
    const __half* __restrict__ B0, void* __restrict__ C0, int N0, int nb0,
    const __half* __restrict__ B1, void* __restrict__ C1, int N1, int nb1,
    const __half* __restrict__ B2, void* __restrict__ C2, int N2, int nb2)
{
    extern __shared__ __half smem[];
    unsigned sbase = (unsigned)__cvta_generic_to_shared(smem);

    int bx = blockIdx.x;
    const __half* Bw; void* C; int N; int bnb;
    if (bx < nb0)            { Bw = B0; C = C0; N = N0; bnb = bx; }
    else if (bx < nb0 + nb1) { Bw = B1; C = C1; N = N1; bnb = bx - nb0; }
    else                     { Bw = B2; C = C2; N = N2; bnb = bx - nb0 - nb1; }

    int tid  = threadIdx.x;
    int bm = blockIdx.y * 128;
    int bn = bnb * 128;
    int lane = tid & 31, warp = tid >> 5;
    int wm = warp >> 1, wn = warp & 1;
    int g  = lane >> 2, tig = lane & 3;

    unsigned dstoff[4];
    const __half* srcA[4];
    const __half* srcB[4];
    #pragma unroll
    for (int i = 0; i < 4; i++) {
        int lin = tid + i * 256;
        int row = lin >> 3, c = lin & 7;
        dstoff[i] = (unsigned)(row * 128 + ((c ^ (row & 7)) << 4));
        srcA[i] = A  + (size_t)(bm + row) * K + c * 8;
        srcB[i] = Bw + (size_t)(bn + row) * K + c * 8;
    }

    int t4 = lane >> 3;
    unsigned aoff[2][4], boff[4][4];
    #pragma unroll
    for (int mi = 0; mi < 2; mi++) {
        int row = wm * 32 + mi * 16 + (lane & 7) + (t4 & 1) * 8;
        #pragma unroll
        for (int ks = 0; ks < 4; ks++) {
            int chunk = 2 * ks + (t4 >> 1);
            aoff[mi][ks] = (unsigned)(row * 128 + ((chunk ^ (row & 7)) << 4));
        }
    }
    #pragma unroll
    for (int np = 0; np < 4; np++) {
        int row = wn * 64 + np * 16 + (lane & 7) + (t4 >> 1) * 8;
        #pragma unroll
        for (int ks = 0; ks < 4; ks++) {
            int chunk = 2 * ks + (t4 & 1);
            boff[np][ks] = (unsigned)(row * 128 + ((chunk ^ (row & 7)) << 4));
        }
    }

    float acc[2][8][4];
    #pragma unroll
    for (int mi = 0; mi < 2; mi++)
        #pragma unroll
        for (int ni = 0; ni < 8; ni++)
            #pragma unroll
            for (int q = 0; q < 4; q++) acc[mi][ni][q] = 0.f;

    const int NT = K >> 6;

    #pragma unroll
    for (int s = 0; s < STAGES - 1; s++) {
        unsigned da = sbase + (unsigned)s * 32768u;
        unsigned db = da + 16384u;
        #pragma unroll
        for (int i = 0; i < 4; i++) {
            CP_ASYNC16(da + dstoff[i], srcA[i] + (size_t)s * 64);
            CP_ASYNC16(db + dstoff[i], srcB[i] + (size_t)s * 64);
        }
        CP_COMMIT();
    }

    for (int kt = 0; kt < NT; kt++) {
        int st = kt % STAGES;
        CP_WAIT(STAGES - 2);
        __syncthreads();

        int pf = kt + STAGES - 1;
        if (pf < NT) {
            int pst = pf % STAGES;
            unsigned da = sbase + (unsigned)pst * 32768u;
            unsigned db = da + 16384u;
            #pragma unroll
            for (int i = 0; i < 4; i++) {
                CP_ASYNC16(da + dstoff[i], srcA[i] + (size_t)pf * 64);
                CP_ASYNC16(db + dstoff[i], srcB[i] + (size_t)pf * 64);
            }
        }
        CP_COMMIT();

        unsigned AsB = sbase + (unsigned)st * 32768u;
        unsigned BsB = AsB + 16384u;

        #pragma unroll
        for (int ks = 0; ks < 4; ks++) {
            unsigned af[2][4];
            LDSM4(af[0][0], af[0][1], af[0][2], af[0][3], AsB + aoff[0][ks]);
            LDSM4(af[1][0], af[1][1], af[1][2], af[1][3], AsB + aoff[1][ks]);
            unsigned bf[8][2];
            #pragma unroll
            for (int np = 0; np < 4; np++)
                LDSM4(bf[2*np][0], bf[2*np][1], bf[2*np+1][0], bf[2*np+1][1],
                      BsB + boff[np][ks]);
            #pragma unroll
            for (int mi = 0; mi < 2; mi++)
                #pragma unroll
                for (int ni = 0; ni < 8; ni++)
                    MMA_F16(acc[mi][ni], af[mi], bf[ni]);
        }
    }

    #pragma unroll
    for (int mi = 0; mi < 2; mi++) {
        int row0 = bm + wm * 32 + mi * 16 + g;
        #pragma unroll
        for (int half = 0; half < 2; half++) {
            int row = row0 + half * 8;
            size_t rowoff = (size_t)row * N;
            #pragma unroll
            for (int ni = 0; ni < 8; ni++) {
                int col = bn + wn * 64 + ni * 8 + 2 * tig;
                size_t idx = rowoff + col;
                float vx = acc[mi][ni][half * 2 + 0];
                float vy = acc[mi][ni][half * 2 + 1];
                if (mode == 1) {
                    float2 rsd = *(const float2*)((const float*)aux + idx);
                    vx += rsd.x; vy += rsd.y;
                    float2 o = { vx, vy };
                    *(float2*)((float*)C + idx) = o;
                } else {
                    if (mode == 2) {
                        __half2 gh = *(const __half2*)((const __half*)aux + idx);
                        float2 gf = __half22float2(gh);
                        vx *= gf.x / (1.f + __expf(-gf.x));
                        vy *= gf.y / (1.f + __expf(-gf.y));
                    }
                    __half2 o = __floats2half2_rn(vx, vy);
                    *(__half2*)((__half*)C + idx) = o;
                }
            }
        }
    }
}

// ---------------- fused per-head Us projection (+ RoPE); half out; q pre-scaled ----------------
__global__ void __launch_bounds__(256) usproj_fused(
    const __half* __restrict__ qr, const __half* __restrict__ kr, const __half* __restrict__ vr,
    const float* __restrict__ qUs, const float* __restrict__ kUs, const float* __restrict__ vUs,
    __half* __restrict__ qb, __half* __restrict__ kb, __half* __restrict__ vb,
    const float* __restrict__ rc, const float* __restrict__ rs)
{
    __shared__ __align__(16) float inT[32][64];
    __shared__ __align__(16) float UsT[32][64];
    __shared__ __align__(16) float os [64][64];
    int y = blockIdx.y;
    const __half* in; const float* Us; __half* out; int heads, h, rope;
    float osc = 1.0f;
    if (y < 32)      { in = qr; Us = qUs; out = qb; heads = 32; h = y;      rope = 1; osc = 0.125f; }
    else if (y < 40) { in = kr; Us = kUs; out = kb; heads = 8;  h = y - 32; rope = 1; }
    else             { in = vr; Us = vUs; out = vb; heads = 8;  h = y - 40; rope = 0; }

    int bt0 = blockIdx.x * 64;
    int tid = threadIdx.x;
    int ldin = heads * 32;

    {
        int d = tid >> 2; int r0 = (tid & 3) * 8;
        const float* p = Us + ((size_t)h * 64 + d) * 32 + r0;
        float4 u0 = *(const float4*)p;
        float4 u1 = *(const float4*)(p + 4);
        UsT[r0+0][d]=u0.x; UsT[r0+1][d]=u0.y; UsT[r0+2][d]=u0.z; UsT[r0+3][d]=u0.w;
        UsT[r0+4][d]=u1.x; UsT[r0+5][d]=u1.y; UsT[r0+6][d]=u1.z; UsT[r0+7][d]=u1.w;
    }
    {
        int i = tid >> 2; int r0 = (tid & 3) * 8;
        const __half* p = in + (size_t)(bt0 + i) * ldin + h * 32 + r0;
        uint4 u = *(const uint4*)p;
        float2 f0 = __half22float2(*(__half2*)&u.x);
        float2 f1 = __half22float2(*(__half2*)&u.y);
        float2 f2 = __half22float2(*(__half2*)&u.z);
        float2 f3 = __half22float2(*(__half2*)&u.w);
        inT[r0+0][i]=f0.x; inT[r0+1][i]=f0.y; inT[r0+2][i]=f1.x; inT[r0+3][i]=f1.y;
        inT[r0+4][i]=f2.x; inT[r0+5][i]=f2.y; inT[r0+6][i]=f3.x; inT[r0+7][i]=f3.y;
    }
    __syncthreads();

    int tx = tid & 15, ty = tid >> 4;
    float acc[4][4] = {};
    #pragma unroll
    for (int r = 0; r < 32; r++) {
        float4 a = *(const float4*)&inT[r][ty*4];
        float4 b = *(const float4*)&UsT[r][tx*4];
        float av[4] = {a.x,a.y,a.z,a.w};
        float bv[4] = {b.x,b.y,b.z,b.w};
        #pragma unroll
        for (int rr = 0; rr < 4; rr++)
            #pragma unroll
            for (int cc = 0; cc < 4; cc++)
                acc[rr][cc] = fmaf(av[rr], bv[cc], acc[rr][cc]);
    }
    #pragma unroll
    for (int rr = 0; rr < 4; rr++)
        #pragma unroll
        for (int cc = 0; cc < 4; cc++)
            os[ty*4+rr][tx*4+cc] = acc[rr][cc];
    __syncthreads();

    if (!rope) {
        #pragma unroll
        for (int kk = 0; kk < 4; kk++) {
            int lin4 = tid + kk * 256;
            int i = lin4 >> 4; int d0 = (lin4 & 15) * 4;
            int bt = bt0 + i; int b = bt >> 10; int t = bt & 1023;
            float4 vv = *(const float4*)&os[i][d0];
            size_t addr = (((size_t)(b * heads + h)) * Tv + t) * 64 + d0;
            *(uint2*)(out + addr) = pack4h(vv);
        }
    } else {
        #pragma unroll
        for (int kk = 0; kk < 2; kk++) {
            int lin4 = tid + kk * 256;
            int i = lin4 >> 3; int d0 = (lin4 & 7) * 4;
            int bt = bt0 + i; int b = bt >> 10; int t = bt & 1023;
            float4 x1 = *(const float4*)&os[i][d0];
            float4 x2 = *(const float4*)&os[i][d0 + 32];
            float4 cc4 = *(const float4*)(rc + t * 32 + d0);
            float4 ss4 = *(const float4*)(rs + t * 32 + d0);
            float xx1[4] = {x1.x,x1.y,x1.z,x1.w};
            float xx2[4] = {x2.x,x2.y,x2.z,x2.w};
            float ca[4] = {cc4.x,cc4.y,cc4.z,cc4.w};
            float sa[4] = {ss4.x,ss4.y,ss4.z,ss4.w};
            float4 w1, w2;
            float* o1 = &w1.x; float* o2 = &w2.x;
            #pragma unroll
            for (int c = 0; c < 4; c++) {
                o1[c] = (xx1[c] * ca[c] - xx2[c] * sa[c]) * osc;
                o2[c] = (xx2[c] * ca[c] + xx1[c] * sa[c]) * osc;
            }
            size_t base = (((size_t)(b * heads + h)) * Tv + t) * 64;
            *(uint2*)(out + base + d0)      = pack4h(w1);
            *(uint2*)(out + base + d0 + 32) = pack4h(w2);
        }
    }
}

// ---------------- flash attention, fp16 MMA, in-register softmax (causal, GQA 4:1) ----------------
// dynamic smem: Qs [0,8K) Ks [8K,16K) Vs [16K,24K) halves, swizzled.
// Ored (final cross-warp O reduce, 64x68 fp32 = 17408B) overlaps Qs/Ks after mainloop.
#define ATTN_SMEM 24576
__global__ void __launch_bounds__(256, 2) attn_kernel(const __half* __restrict__ q,
                                                      const __half* __restrict__ k,
                                                      const __half* __restrict__ v,
                                                      __half* __restrict__ ctx)
{
    extern __shared__ char asmem[];
    __shared__ float mrow[64], lrow[64];
    __shared__ float pmax[128], psum[128];   // [wn][row]

    unsigned sb  = (unsigned)__cvta_generic_to_shared(asmem);
    unsigned QsB = sb, KsB = sb + 8192, VsB = sb + 16384;

    int tid = threadIdx.x;
    int bh = blockIdx.y; int b = bh >> 5; int h = bh & 31; int hk = h >> 2;
    int q0 = blockIdx.x * 64;
    int lane = tid & 31, warp = tid >> 5;
    int g = lane >> 2, tig = lane & 3;
    int t4 = lane >> 3;
    int wq = warp >> 1;   // q-row block of 16
    int wn = warp & 1;    // key half: keys [wn*32, wn*32+32)

    // load Q (64x64 halves), swizzled
    const __half* qbase = q + (((size_t)(b * 32 + h)) * Tv + q0) * 64;
    #pragma unroll
    for (int kk = 0; kk < 2; kk++) {
        int lin = tid + kk * 256;
        int row = lin >> 3, c = lin & 7;
        uint4 u = *(const uint4*)(qbase + (size_t)row * 64 + c * 8);
        *(uint4*)(asmem + row * 128 + ((c ^ (row & 7)) << 4)) = u;
    }
    if (tid < 64) { mrow[tid] = -INFINITY; lrow[tid] = 0.f; }

    // fragment offsets
    unsigned aoffQ[4], boffK[2][4], voffV[2][4];
    {
        int rowA = wq * 16 + (lane & 7) + (t4 & 1) * 8;
        #pragma unroll
        for (int ks = 0; ks < 4; ks++) {
            int ca = 2 * ks + (t4 >> 1);
            aoffQ[ks] = (unsigned)(rowA * 128 + ((ca ^ (rowA & 7)) << 4));
        }
        #pragma unroll
        for (int nb = 0; nb < 2; nb++) {
            int rowB = wn * 32 + nb * 16 + (lane & 7) + (t4 >> 1) * 8;
            #pragma unroll
            for (int ks = 0; ks < 4; ks++) {
                int cb = 2 * ks + (t4 & 1);
                boffK[nb][ks] = (unsigned)(rowB * 128 + ((cb ^ (rowB & 7)) << 4));
            }
        }
        #pragma unroll
        for (int t = 0; t < 2; t++) {
            int rowV = wn * 32 + t * 16 + (lane & 7) + (t4 & 1) * 8;
            #pragma unroll
            for (int np = 0; np < 4; np++) {
                int cv = np * 2 + (t4 >> 1);
                voffV[t][np] = (unsigned)(rowV * 128 + ((cv ^ (rowV & 7)) << 4));
            }
        }
    }

    int r0 = wq * 16 + g, r1 = r0 + 8;
    float cacc[8][4];
    #pragma unroll
    for (int ni = 0; ni < 8; ni++)
        #pragma unroll
        for (int c = 0; c < 4; c++) cacc[ni][c] = 0.f;

    const __half* kb0 = k + ((size_t)(b * 8 + hk)) * Tv * 64;
    const __half* vb0 = v + ((size_t)(b * 8 + hk)) * Tv * 64;

    int ntile = (q0 >> 6) + 1;
    for (int kt = 0; kt < ntile; kt++) {
        // load K,V tiles (64x64 halves each), swizzled
        #pragma unroll
        for (int kk = 0; kk < 2; kk++) {
            int lin = tid + kk * 256;
            int row = lin >> 3, c = lin & 7;
            size_t off = ((size_t)(kt * 64 + row)) * 64 + c * 8;
            unsigned d = (unsigned)(row * 128 + ((c ^ (row & 7)) << 4));
            *(uint4*)(asmem + 8192 + d)  = *(const uint4*)(kb0 + off);
            *(uint4*)(asmem + 16384 + d) = *(const uint4*)(vb0 + off);
        }
        __syncthreads();

        // ---- S = Q K^T : warp computes 16 rows x its 32 keys ----
        float sacc[4][4] = {};
        #pragma unroll
        for (int ks = 0; ks < 4; ks++) {
            unsigned af[4];
            LDSM4(af[0], af[1], af[2], af[3], QsB + aoffQ[ks]);
            #pragma unroll
            for (int nb = 0; nb < 2; nb++) {
                unsigned bf[4];
                LDSM4(bf[0], bf[1], bf[2], bf[3], KsB + boffK[nb][ks]);
                unsigned b0[2] = { bf[0], bf[1] };
                unsigned b1[2] = { bf[2], bf[3] };
                MMA_F16(sacc[nb*2 + 0], af, b0);
                MMA_F16(sacc[nb*2 + 1], af, b1);
            }
        }

        // ---- causal mask in-register ----
        int qi0 = q0 + r0, qi1 = q0 + r1;
        #pragma unroll
        for (int ni = 0; ni < 4; ni++) {
            int kc = kt * 64 + wn * 32 + ni * 8 + 2 * tig;
            if (kc > qi0)     sacc[ni][0] = -INFINITY;
            if (kc + 1 > qi0) sacc[ni][1] = -INFINITY;
            if (kc > qi1)     sacc[ni][2] = -INFINITY;
            if (kc + 1 > qi1) sacc[ni][3] = -INFINITY;
        }

        // ---- partial row max (quad shuffle), exchange across key-halves ----
        float pm0 = -INFINITY, pm1 = -INFINITY;
        #pragma unroll
        for (int ni = 0; ni < 4; ni++) {
            pm0 = fmaxf(pm0, fmaxf(sacc[ni][0], sacc[ni][1]));
            pm1 = fmaxf(pm1, fmaxf(sacc[ni][2], sacc[ni][3]));
        }
        pm0 = fmaxf(pm0, __shfl_xor_sync(0xffffffffu, pm0, 1));
        pm0 = fmaxf(pm0, __shfl_xor_sync(0xffffffffu, pm0, 2));
        pm1 = fmaxf(pm1, __shfl_xor_sync(0xffffffffu, pm1, 1));
        pm1 = fmaxf(pm1, __shfl_xor_sync(0xffffffffu, pm1, 2));
        if (tig == 0) { pmax[wn * 64 + r0] = pm0; pmax[wn * 64 + r1] = pm1; }
        __syncthreads();

        float mo0 = mrow[r0], mo1 = mrow[r1];
        float mx0 = fmaxf(mo0, fmaxf(pmax[r0], pmax[64 + r0]));
        float mx1 = fmaxf(mo1, fmaxf(pmax[r1], pmax[64 + r1]));
        float rsc0 = __expf(mo0 - mx0);
        float rsc1 = __expf(mo1 - mx1);

        // ---- exp + partial sums; P stays in registers as fp16 A-fragments ----
        unsigned pf[4][2];
        float s0 = 0.f, s1 = 0.f;
        #pragma unroll
        for (int ni = 0; ni < 4; ni++) {
            float p0 = __expf(sacc[ni][0] - mx0);
            float p1 = __expf(sacc[ni][1] - mx0);
            float p2 = __expf(sacc[ni][2] - mx1);
            float p3 = __expf(sacc[ni][3] - mx1);
            s0 += p0 + p1; s1 += p2 + p3;
            __half2 h01 = __floats2half2_rn(p0, p1);
            __half2 h23 = __floats2half2_rn(p2, p3);
            pf[ni][0] = *(unsigned*)&h01;
            pf[ni][1] = *(unsigned*)&h23;
        }
        s0 += __shfl_xor_sync(0xffffffffu, s0, 1);
        s0 += __shfl_xor_sync(0xffffffffu, s0, 2);
        s1 += __shfl_xor_sync(0xffffffffu, s1, 1);
        s1 += __shfl_xor_sync(0xffffffffu, s1, 2);
        if (tig == 0) { psum[wn * 64 + r0] = s0; psum[wn * 64 + r1] = s1; }

        // ---- rescale accumulated O ----
        #pragma unroll
        for (int ni = 0; ni < 8; ni++) {
            cacc[ni][0] *= rsc0; cacc[ni][1] *= rsc0;
            cacc[ni][2] *= rsc1; cacc[ni][3] *= rsc1;
        }

        // ---- P V : partial O over this warp's 32 keys, all 64 d-cols ----
        #pragma unroll
        for (int t = 0; t < 2; t++) {
            unsigned af[4] = { pf[2*t][0], pf[2*t][1], pf[2*t+1][0], pf[2*t+1][1] };
            #pragma unroll
            for (int np = 0; np < 4; np++) {
                unsigned vf[4];
                LDSM4T(vf[0], vf[1], vf[2], vf[3], VsB + voffV[t][np]);
                unsigned b0[2] = { vf[0], vf[1] };
                unsigned b1[2] = { vf[2], vf[3] };
                MMA_F16(cacc[np*2 + 0], af, b0);
                MMA_F16(cacc[np*2 + 1], af, b1);
            }
        }
        __syncthreads();

        // ---- update running stats (single agent per row) ----
        if (wn == 0 && tig == 0) {
            lrow[r0] = lrow[r0] * rsc0 + psum[r0] + psum[64 + r0];
            lrow[r1] = lrow[r1] * rsc1 + psum[r1] + psum[64 + r1];
            mrow[r0] = mx0;
            mrow[r1] = mx1;
        }
    }
    __syncthreads();

    // ---- cross-warp O reduce + epilogue ----
    float* Ored = (float*)asmem;       // 64 x 68 fp32 (overlaps dead Qs/Ks)
    if (wn == 1) {
        #pragma unroll
        for (int ni = 0; ni < 8; ni++) {
            int col = ni * 8 + 2 * tig;
            *(float2*)(Ored + r0 * 68 + col) = make_float2(cacc[ni][0], cacc[ni][1]);
            *(float2*)(Ored + r1 * 68 + col) = make_float2(cacc[ni][2], cacc[ni][3]);
        }
    }
    __syncthreads();
    if (wn == 0) {
        float inv0 = 1.f / lrow[r0];
        float inv1 = 1.f / lrow[r1];
        #pragma unroll
        for (int ni = 0; ni < 8; ni++) {
            int col = ni * 8 + 2 * tig;
            float2 a0 = *(float2*)(Ored + r0 * 68 + col);
            float2 a1 = *(float2*)(Ored + r1 * 68 + col);
            __half2 o0 = __floats2half2_rn((cacc[ni][0] + a0.x) * inv0,
                                           (cacc[ni][1] + a0.y) * inv0);
            __half2 o1 = __floats2half2_rn((cacc[ni][2] + a1.x) * inv1,
                                           (cacc[ni][3] + a1.y) * inv1);
            size_t ad0 = ((size_t)(b * Tv + q0 + r0)) * Dv + h * 64 + col;
            size_t ad1 = ((size_t)(b * Tv + q0 + r1)) * Dv + h * 64 + col;
            *(__half2*)(ctx + ad0) = o0;
            *(__half2*)(ctx + ad1) = o1;
        }
    }
}

// ---------------- launch ----------------
extern "C" void kernel_launch(void* const* d_in, const int* in_sizes, int n_in,
                              void* d_out, int out_size)
{
    const float* x     = (const float*)d_in[0];
    const float* ln1_w = (const float*)d_in[1];
    const float* ln2_w = (const float*)d_in[2];
    const float* q_Us  = (const float*)d_in[3];
    const float* q_V   = (const float*)d_in[4];
    const float* k_Us  = (const float*)d_in[5];
    const float* k_V   = (const float*)d_in[6];
    const float* v_Us  = (const float*)d_in[7];
    const float* v_V   = (const float*)d_in[8];
    const float* o_Us  = (const float*)d_in[9];
    const float* o_V   = (const float*)d_in[10];
    const float* g_Usw = (const float*)d_in[11];
    const float* g_Vw  = (const float*)d_in[12];
    const float* u_Usw = (const float*)d_in[13];
    const float* u_Vw  = (const float*)d_in[14];
    const float* d_Usw = (const float*)d_in[15];
    const float* d_Vw  = (const float*)d_in[16];
    float* out = (float*)d_out;

    __half *h1, *qr, *kr, *vr, *qb, *kb, *vb, *ctx, *orr, *h2, *gr, *ur, *gg, *ff, *dr, *wts;
    float *x1, *rc, *rs;
    cudaGetSymbolAddress((void**)&h1,  g_h1);
    cudaGetSymbolAddress((void**)&qr,  g_qr);
    cudaGetSymbolAddress((void**)&kr,  g_kr);
    cudaGetSymbolAddress((void**)&vr,  g_vr);
    cudaGetSymbolAddress((void**)&qb,  g_q);
    cudaGetSymbolAddress((void**)&kb,  g_k);
    cudaGetSymbolAddress((void**)&vb,  g_v);
    cudaGetSymbolAddress((void**)&ctx, g_ctx);
    cudaGetSymbolAddress((void**)&orr, g_or);
    cudaGetSymbolAddress((void**)&x1,  g_x1);
    cudaGetSymbolAddress((void**)&h2,  g_h2);
    cudaGetSymbolAddress((void**)&gr,  g_gr);
    cudaGetSymbolAddress((void**)&ur,  g_ur);
    cudaGetSymbolAddress((void**)&gg,  g_g);
    cudaGetSymbolAddress((void**)&ff,  g_ff);
    cudaGetSymbolAddress((void**)&dr,  g_dr);
    cudaGetSymbolAddress((void**)&rc,  g_ropec);
    cudaGetSymbolAddress((void**)&rs,  g_ropes);
    cudaGetSymbolAddress((void**)&wts, g_wts);

    static int smem_set = 0;
    if (!smem_set) {
        cudaFuncSetAttribute(gemm_h, cudaFuncAttributeMaxDynamicSharedMemorySize, 98304);
        cudaFuncSetAttribute(attn_kernel, cudaFuncAttributeMaxDynamicSharedMemorySize, ATTN_SMEM);
        smem_set = 1;
    }
    const int SM = 98304;
    dim3 blk(256);

    prep_all<<<NWBLK + BT + Tv*32/256, blk>>>(wts, q_V, k_V, v_V, o_V, o_Us,
                                              g_Vw, u_Vw, g_Usw, u_Usw, d_Vw, d_Usw,
                                              x, ln1_w, h1, rc, rs);

    gemm_h<<<dim3(12, 32), blk, SM>>>(h1, Dv, 0, nullptr,
        wts + W_QV, qr, Hv*Rv, 8,  wts + W_KV, kr, HKv*Rv, 2,  wts + W_VV, vr, HKv*Rv, 2);

    usproj_fused<<<dim3(BT/64, 48), blk>>>(qr, kr, vr, q_Us, k_Us, v_Us, qb, kb, vb, rc, rs);

    attn_kernel<<<dim3(Tv/64, Bv*Hv), blk, ATTN_SMEM>>>(qb, kb, vb, ctx);

    gemm_h<<<dim3(8, 32), blk, SM>>>(ctx, Dv, 0, nullptr,
        wts + W_OV, orr, ROv, 8,  nullptr, nullptr, 0, 0,  nullptr, nullptr, 0, 0);
    gemm_h<<<dim3(16, 32), blk, SM>>>(orr, ROv, 1, x,
        wts + W_OUS, x1, Dv, 16,  nullptr, nullptr, 0, 0,  nullptr, nullptr, 0, 0);

    rms_kernel<<<BT, blk>>>(x1, ln2_w, h2);

    gemm_h<<<dim3(16, 32), blk, SM>>>(h2, Dv, 0, nullptr,
        wts + W_GV, gr, RFv, 8,  wts + W_UV, ur, RFv, 8,  nullptr, nullptr, 0, 0);

    gemm_h<<<dim3(44, 32), blk, SM>>>(gr, RFv, 0, nullptr,
        wts + W_GUS, gg, Iv, 44,  nullptr, nullptr, 0, 0,  nullptr, nullptr, 0, 0);
    gemm_h<<<dim3(44, 32), blk, SM>>>(ur, RFv, 2, gg,
        wts + W_UUS, ff, Iv, 44,  nullptr, nullptr, 0, 0,  nullptr, nullptr, 0, 0);

    gemm_h<<<dim3(8, 32), blk, SM>>>(ff, Iv, 0, nullptr,
        wts + W_DV, dr, RFv, 8,  nullptr, nullptr, 0, 0,  nullptr, nullptr, 0, 0);
    gemm_h<<<dim3(16, 32), blk, SM>>>(dr, RFv, 1, x1,
        wts + W_DUS, out, Dv, 16,  nullptr, nullptr, 0, 0,  nullptr, nullptr, 0, 0);
}

// round 11
// speedup vs baseline: 3.2758x; 1.0126x over previous
#include <cuda_runtime.h>
#include <cuda_fp16.h>
#include <math.h>

// ---------------- problem constants ----------------
#define Bv   4
#define Tv   1024
#define Dv   2048
#define Hv   32
#define DHv  64
#define HKv  8
#define Rv   32
#define ROv  1024
#define RFv  1024
#define Iv   5632
#define BT   (Bv*Tv)     // 4096

// ---------------- scratch ----------------
__device__ __half g_h1 [BT*Dv];
__device__ __half g_qr [BT*(Hv*Rv)];
__device__ __half g_kr [BT*(HKv*Rv)];
__device__ __half g_vr [BT*(HKv*Rv)];
__device__ __half g_q  [Bv*Hv*Tv*DHv];
__device__ __half g_k  [Bv*HKv*Tv*DHv];
__device__ __half g_v  [Bv*HKv*Tv*DHv];
__device__ __half g_ctx[BT*Dv];
__device__ __half g_or [BT*ROv];
__device__ float  g_x1 [BT*Dv];
__device__ __half g_h2 [BT*Dv];
__device__ __half g_gr [BT*RFv];
__device__ __half g_ur [BT*RFv];
__device__ __half g_g  [BT*Iv];
__device__ __half g_ff [BT*Iv];
__device__ __half g_dr [BT*RFv];
__device__ float  g_ropec[Tv*32];
__device__ float  g_ropes[Tv*32];
// converted (half) weights, concatenated; offsets in elements
#define W_QV   0
#define W_KV   2097152
#define W_VV   2621440
#define W_OV   3145728
#define W_OUS  5242880
#define W_GV   7340032
#define W_UV   9437184
#define W_GUS  11534336
#define W_UUS  17301504
#define W_DV   23068672
#define W_DUS  28835840
#define W_TOT  30932992
#define NWBLK  (W_TOT/1024)     // 30208 weight-prep blocks
__device__ __half g_wts[W_TOT];

// ---------------- helpers ----------------
__device__ __forceinline__ uint2 pack4h(float4 v) {
    __half2 a = __floats2half2_rn(v.x, v.y);
    __half2 b = __floats2half2_rn(v.z, v.w);
    uint2 r;
    r.x = *(unsigned*)&a;
    r.y = *(unsigned*)&b;
    return r;
}

// ---------------- fused front-end: weight f32->f16 + rms1 + rope table ----------------
__global__ void __launch_bounds__(256) prep_all(
    __half* __restrict__ dst,
    const float* __restrict__ s0, const float* __restrict__ s1, const float* __restrict__ s2,
    const float* __restrict__ s3, const float* __restrict__ s4, const float* __restrict__ s5,
    const float* __restrict__ s6, const float* __restrict__ s7, const float* __restrict__ s8,
    const float* __restrict__ s9, const float* __restrict__ s10,
    const float* __restrict__ x, const float* __restrict__ ln1_w, __half* __restrict__ h1,
    float* __restrict__ rc, float* __restrict__ rs)
{
    int bx = blockIdx.x;
    int tid = threadIdx.x;
    if (bx < NWBLK) {
        long i = ((long)bx * 256 + tid) * 4;
        const float* src; long base;
        if (i < W_GUS) {
            if (i < W_OV) {
                if (i < W_KV)        { src = s0; base = W_QV; }
                else if (i < W_VV)   { src = s1; base = W_KV; }
                else                 { src = s2; base = W_VV; }
            } else {
                if (i < W_OUS)       { src = s3; base = W_OV; }
                else if (i < W_GV)   { src = s4; base = W_OUS; }
                else if (i < W_UV)   { src = s5; base = W_GV; }
                else                 { src = s6; base = W_UV; }
            }
        } else {
            if (i < W_UUS)           { src = s7; base = W_GUS; }
            else if (i < W_DV)       { src = s8; base = W_UUS; }
            else if (i < W_DUS)      { src = s9; base = W_DV; }
            else                     { src = s10; base = W_DUS; }
        }
        float4 v = *(const float4*)(src + (i - base));
        *(uint2*)(dst + i) = pack4h(v);
    } else if (bx < NWBLK + BT) {
        int row = bx - NWBLK;
        const float4* xr = (const float4*)(x + (size_t)row * Dv);
        float4 v0 = xr[tid];
        float4 v1 = xr[tid + 256];
        float ss = v0.x*v0.x + v0.y*v0.y + v0.z*v0.z + v0.w*v0.w
                 + v1.x*v1.x + v1.y*v1.y + v1.z*v1.z + v1.w*v1.w;
        #pragma unroll
        for (int o = 16; o; o >>= 1) ss += __shfl_xor_sync(0xffffffffu, ss, o);
        __shared__ float red[8];
        if ((tid & 31) == 0) red[tid >> 5] = ss;
        __syncthreads();
        float tot = 0.f;
        #pragma unroll
        for (int i = 0; i < 8; i++) tot += red[i];
        float inv = rsqrtf(tot * (1.0f / Dv) + 1e-5f);
        const float4* wr = (const float4*)ln1_w;
        float4 w0 = wr[tid], w1 = wr[tid + 256];
        float4 o0 = { v0.x*inv*w0.x, v0.y*inv*w0.y, v0.z*inv*w0.z, v0.w*inv*w0.w };
        float4 o1 = { v1.x*inv*w1.x, v1.y*inv*w1.y, v1.z*inv*w1.z, v1.w*inv*w1.w };
        __half* orow = h1 + (size_t)row * Dv;
        *(uint2*)(orow + tid * 4)         = pack4h(o0);
        *(uint2*)(orow + (tid + 256) * 4) = pack4h(o1);
    } else {
        int idx = (bx - NWBLK - BT) * 256 + tid;
        int t = idx >> 5, d = idx & 31;
        float invf = expf(-0.28782313662425572f * (float)d);
        float ang = (float)t * invf;
        rc[idx] = cosf(ang);
        rs[idx] = sinf(ang);
    }
}

// ---------------- RMSNorm (fp32 in, fp16 out) ----------------
__global__ void __launch_bounds__(256) rms_kernel(const float* __restrict__ x,
                                                  const float* __restrict__ w,
                                                  __half* __restrict__ out)
{
    int row = blockIdx.x;
    int tid = threadIdx.x;
    const float4* xr = (const float4*)(x + (size_t)row * Dv);
    float4 v0 = xr[tid];
    float4 v1 = xr[tid + 256];
    float ss = v0.x*v0.x + v0.y*v0.y + v0.z*v0.z + v0.w*v0.w
             + v1.x*v1.x + v1.y*v1.y + v1.z*v1.z + v1.w*v1.w;
    #pragma unroll
    for (int o = 16; o; o >>= 1) ss += __shfl_xor_sync(0xffffffffu, ss, o);
    __shared__ float red[8];
    if ((tid & 31) == 0) red[tid >> 5] = ss;
    __syncthreads();
    float tot = 0.f;
    #pragma unroll
    for (int i = 0; i < 8; i++) tot += red[i];
    float inv = rsqrtf(tot * (1.0f / Dv) + 1e-5f);
    const float4* wr = (const float4*)w;
    float4 w0 = wr[tid], w1 = wr[tid + 256];
    float4 o0 = { v0.x*inv*w0.x, v0.y*inv*w0.y, v0.z*inv*w0.z, v0.w*inv*w0.w };
    float4 o1 = { v1.x*inv*w1.x, v1.y*inv*w1.y, v1.z*inv*w1.z, v1.w*inv*w1.w };
    __half* orow = out + (size_t)row * Dv;
    *(uint2*)(orow + tid * 4)         = pack4h(o0);
    *(uint2*)(orow + (tid + 256) * 4) = pack4h(o1);
}

// ---------------- fp16 tensor-core GEMM (3-stage, TBK=64, ldmatrix) ----------------
#define STAGES 3

#define CP_ASYNC16(dst, src) asm volatile("cp.async.cg.shared.global [%0], [%1], 16;\n" :: "r"(dst), "l"(src))
#define CP_COMMIT() asm volatile("cp.async.commit_group;\n" ::)
#define CP_WAIT(n)  asm volatile("cp.async.wait_group %0;\n" :: "n"(n))

#define LDSM4(r0, r1, r2, r3, addr) \
    asm volatile("ldmatrix.sync.aligned.m8n8.x4.shared.b16 {%0,%1,%2,%3}, [%4];" \
        : "=r"(r0), "=r"(r1), "=r"(r2), "=r"(r3) : "r"(addr))

#define LDSM4T(r0, r1, r2, r3, addr) \
    asm volatile("ldmatrix.sync.aligned.m8n8.x4.trans.shared.b16 {%0,%1,%2,%3}, [%4];" \
        : "=r"(r0), "=r"(r1), "=r"(r2), "=r"(r3) : "r"(addr))

#define MMA_F16(d, a, b) \
    asm volatile("mma.sync.aligned.m16n8k16.row.col.f32.f16.f16.f32 " \
        "{%0,%1,%2,%3}, {%4,%5,%6,%7}, {%8,%9}, {%0,%1,%2,%3};" \
        : "+f"(d[0]), "+f"(d[1]), "+f"(d[2]), "+f"(d[3]) \
        : "r"(a[0]), "r"(a[1]), "r"(a[2]), "r"(a[3]), "r"(b[0]), "r"(b[1]))

__global__ void __launch_bounds__(256, 2) gemm_h(
    const __half* __restrict__ A, int K, int mode, const void* __restrict__ aux,
    const __half* __restrict__ B0, void* __restrict__ C0, int N0, int nb0,
    const __half* __restrict__ B1, void* __restrict__ C1, int N1, int nb1,
    const __half* __restrict__ B2, void* __restrict__ C2, int N2, int nb2)
{
    extern __shared__ __half smem[];
    unsigned sbase = (unsigned)__cvta_generic_to_shared(smem);

    int bx = blockIdx.x;
    const __half* Bw; void* C; int N; int bnb;
    if (bx < nb0)            { Bw = B0; C = C0; N = N0; bnb = bx; }
    else if (bx < nb0 + nb1) { Bw = B1; C = C1; N = N1; bnb = bx - nb0; }
    else                     { Bw = B2; C = C2; N = N2; bnb = bx - nb0 - nb1; }

    int tid  = threadIdx.x;
    int bm = blockIdx.y * 128;
    int bn = bnb * 128;
    int lane = tid & 31, warp = tid >> 5;
    int wm = warp >> 1, wn = warp & 1;
    int g  = lane >> 2, tig = lane & 3;

    unsigned dstoff[4];
    const __half* srcA[4];
    const __half* srcB[4];
    #pragma unroll
    for (int i = 0; i < 4; i++) {
        int lin = tid + i * 256;
        int row = lin >> 3, c = lin & 7;
        dstoff[i] = (unsigned)(row * 128 + ((c ^ (row & 7)) << 4));
        srcA[i] = A  + (size_t)(bm + row) * K + c * 8;
        srcB[i] = Bw + (size_t)(bn + row) * K + c * 8;
    }

    int t4 = lane >> 3;
    unsigned aoff[2][4], boff[4][4];
    #pragma unroll
    for (int mi = 0; mi < 2; mi++) {
        int row = wm * 32 + mi * 16 + (lane & 7) + (t4 & 1) * 8;
        #pragma unroll
        for (int ks = 0; ks < 4; ks++) {
            int chunk = 2 * ks + (t4 >> 1);
            aoff[mi][ks] = (unsigned)(row * 128 + ((chunk ^ (row & 7)) << 4));
        }
    }
    #pragma unroll
    for (int np = 0; np < 4; np++) {
        int row = wn * 64 + np * 16 + (lane & 7) + (t4 >> 1) * 8;
        #pragma unroll
        for (int ks = 0; ks < 4; ks++) {
            int chunk = 2 * ks + (t4 & 1);
            boff[np][ks] = (unsigned)(row * 128 + ((chunk ^ (row & 7)) << 4));
        }
    }

    float acc[2][8][4];
    #pragma unroll
    for (int mi = 0; mi < 2; mi++)
        #pragma unroll
        for (int ni = 0; ni < 8; ni++)
            #pragma unroll
            for (int q = 0; q < 4; q++) acc[mi][ni][q] = 0.f;

    const int NT = K >> 6;

    #pragma unroll
    for (int s = 0; s < STAGES - 1; s++) {
        unsigned da = sbase + (unsigned)s * 32768u;
        unsigned db = da + 16384u;
        #pragma unroll
        for (int i = 0; i < 4; i++) {
            CP_ASYNC16(da + dstoff[i], srcA[i] + (size_t)s * 64);
            CP_ASYNC16(db + dstoff[i], srcB[i] + (size_t)s * 64);
        }
        CP_COMMIT();
    }

    for (int kt = 0; kt < NT; kt++) {
        int st = kt % STAGES;
        CP_WAIT(STAGES - 2);
        __syncthreads();

        int pf = kt + STAGES - 1;
        if (pf < NT) {
            int pst = pf % STAGES;
            unsigned da = sbase + (unsigned)pst * 32768u;
            unsigned db = da + 16384u;
            #pragma unroll
            for (int i = 0; i < 4; i++) {
                CP_ASYNC16(da + dstoff[i], srcA[i] + (size_t)pf * 64);
                CP_ASYNC16(db + dstoff[i], srcB[i] + (size_t)pf * 64);
            }
        }
        CP_COMMIT();

        unsigned AsB = sbase + (unsigned)st * 32768u;
        unsigned BsB = AsB + 16384u;

        #pragma unroll
        for (int ks = 0; ks < 4; ks++) {
            unsigned af[2][4];
            LDSM4(af[0][0], af[0][1], af[0][2], af[0][3], AsB + aoff[0][ks]);
            LDSM4(af[1][0], af[1][1], af[1][2], af[1][3], AsB + aoff[1][ks]);
            unsigned bf[8][2];
            #pragma unroll
            for (int np = 0; np < 4; np++)
                LDSM4(bf[2*np][0], bf[2*np][1], bf[2*np+1][0], bf[2*np+1][1],
                      BsB + boff[np][ks]);
            #pragma unroll
            for (int mi = 0; mi < 2; mi++)
                #pragma unroll
                for (int ni = 0; ni < 8; ni++)
                    MMA_F16(acc[mi][ni], af[mi], bf[ni]);
        }
    }

    #pragma unroll
    for (int mi = 0; mi < 2; mi++) {
        int row0 = bm + wm * 32 + mi * 16 + g;
        #pragma unroll
        for (int half = 0; half < 2; half++) {
            int row = row0 + half * 8;
            size_t rowoff = (size_t)row * N;
            #pragma unroll
            for (int ni = 0; ni < 8; ni++) {
                int col = bn + wn * 64 + ni * 8 + 2 * tig;
                size_t idx = rowoff + col;
                float vx = acc[mi][ni][half * 2 + 0];
                float vy = acc[mi][ni][half * 2 + 1];
                if (mode == 1) {
                    float2 rsd = *(const float2*)((const float*)aux + idx);
                    vx += rsd.x; vy += rsd.y;
                    float2 o = { vx, vy };
                    *(float2*)((float*)C + idx) = o;
                } else {
                    if (mode == 2) {
                        __half2 gh = *(const __half2*)((const __half*)aux + idx);
                        float2 gf = __half22float2(gh);
                        vx *= gf.x / (1.f + __expf(-gf.x));
                        vy *= gf.y / (1.f + __expf(-gf.y));
                    }
                    __half2 o = __floats2half2_rn(vx, vy);
                    *(__half2*)((__half*)C + idx) = o;
                }
            }
        }
    }
}

// ---------------- fused per-head Us projection (+ RoPE); half out; q pre-scaled ----------------
__global__ void __launch_bounds__(256) usproj_fused(
    const __half* __restrict__ qr, const __half* __restrict__ kr, const __half* __restrict__ vr,
    const float* __restrict__ qUs, const float* __restrict__ kUs, const float* __restrict__ vUs,
    __half* __restrict__ qb, __half* __restrict__ kb, __half* __restrict__ vb,
    const float* __restrict__ rc, const float* __restrict__ rs)
{
    __shared__ __align__(16) float inT[32][64];
    __shared__ __align__(16) float UsT[32][64];
    __shared__ __align__(16) float os [64][64];
    int y = blockIdx.y;
    const __half* in; const float* Us; __half* out; int heads, h, rope;
    float osc = 1.0f;
    if (y < 32)      { in = qr; Us = qUs; out = qb; heads = 32; h = y;      rope = 1; osc = 0.125f; }
    else if (y < 40) { in = kr; Us = kUs; out = kb; heads = 8;  h = y - 32; rope = 1; }
    else             { in = vr; Us = vUs; out = vb; heads = 8;  h = y - 40; rope = 0; }

    int bt0 = blockIdx.x * 64;
    int tid = threadIdx.x;
    int ldin = heads * 32;

    {
        int d = tid >> 2; int r0 = (tid & 3) * 8;
        const float* p = Us + ((size_t)h * 64 + d) * 32 + r0;
        float4 u0 = *(const float4*)p;
        float4 u1 = *(const float4*)(p + 4);
        UsT[r0+0][d]=u0.x; UsT[r0+1][d]=u0.y; UsT[r0+2][d]=u0.z; UsT[r0+3][d]=u0.w;
        UsT[r0+4][d]=u1.x; UsT[r0+5][d]=u1.y; UsT[r0+6][d]=u1.z; UsT[r0+7][d]=u1.w;
    }
    {
        int i = tid >> 2; int r0 = (tid & 3) * 8;
        const __half* p = in + (size_t)(bt0 + i) * ldin + h * 32 + r0;
        uint4 u = *(const uint4*)p;
        float2 f0 = __half22float2(*(__half2*)&u.x);
        float2 f1 = __half22float2(*(__half2*)&u.y);
        float2 f2 = __half22float2(*(__half2*)&u.z);
        float2 f3 = __half22float2(*(__half2*)&u.w);
        inT[r0+0][i]=f0.x; inT[r0+1][i]=f0.y; inT[r0+2][i]=f1.x; inT[r0+3][i]=f1.y;
        inT[r0+4][i]=f2.x; inT[r0+5][i]=f2.y; inT[r0+6][i]=f3.x; inT[r0+7][i]=f3.y;
    }
    __syncthreads();

    int tx = tid & 15, ty = tid >> 4;
    float acc[4][4] = {};
    #pragma unroll
    for (int r = 0; r < 32; r++) {
        float4 a = *(const float4*)&inT[r][ty*4];
        float4 b = *(const float4*)&UsT[r][tx*4];
        float av[4] = {a.x,a.y,a.z,a.w};
        float bv[4] = {b.x,b.y,b.z,b.w};
        #pragma unroll
        for (int rr = 0; rr < 4; rr++)
            #pragma unroll
            for (int cc = 0; cc < 4; cc++)
                acc[rr][cc] = fmaf(av[rr], bv[cc], acc[rr][cc]);
    }
    #pragma unroll
    for (int rr = 0; rr < 4; rr++)
        #pragma unroll
        for (int cc = 0; cc < 4; cc++)
            os[ty*4+rr][tx*4+cc] = acc[rr][cc];
    __syncthreads();

    if (!rope) {
        #pragma unroll
        for (int kk = 0; kk < 4; kk++) {
            int lin4 = tid + kk * 256;
            int i = lin4 >> 4; int d0 = (lin4 & 15) * 4;
            int bt = bt0 + i; int b = bt >> 10; int t = bt & 1023;
            float4 vv = *(const float4*)&os[i][d0];
            size_t addr = (((size_t)(b * heads + h)) * Tv + t) * 64 + d0;
            *(uint2*)(out + addr) = pack4h(vv);
        }
    } else {
        #pragma unroll
        for (int kk = 0; kk < 2; kk++) {
            int lin4 = tid + kk * 256;
            int i = lin4 >> 3; int d0 = (lin4 & 7) * 4;
            int bt = bt0 + i; int b = bt >> 10; int t = bt & 1023;
            float4 x1 = *(const float4*)&os[i][d0];
            float4 x2 = *(const float4*)&os[i][d0 + 32];
            float4 cc4 = *(const float4*)(rc + t * 32 + d0);
            float4 ss4 = *(const float4*)(rs + t * 32 + d0);
            float xx1[4] = {x1.x,x1.y,x1.z,x1.w};
            float xx2[4] = {x2.x,x2.y,x2.z,x2.w};
            float ca[4] = {cc4.x,cc4.y,cc4.z,cc4.w};
            float sa[4] = {ss4.x,ss4.y,ss4.z,ss4.w};
            float4 w1, w2;
            float* o1 = &w1.x; float* o2 = &w2.x;
            #pragma unroll
            for (int c = 0; c < 4; c++) {
                o1[c] = (xx1[c] * ca[c] - xx2[c] * sa[c]) * osc;
                o2[c] = (xx2[c] * ca[c] + xx1[c] * sa[c]) * osc;
            }
            size_t base = (((size_t)(b * heads + h)) * Tv + t) * 64;
            *(uint2*)(out + base + d0)      = pack4h(w1);
            *(uint2*)(out + base + d0 + 32) = pack4h(w2);
        }
    }
}

// ---------------- flash attention, fp16 MMA, in-register softmax, cp.async double-buffered KV ----------------
// dynamic smem: Qs [0,8K) | K0 [8K,16K) | V0 [16K,24K) | K1 [24K,32K) | V1 [32K,40K)
// Ored (final cross-warp O reduce, 64x68 fp32) overlaps [0,17408) after mainloop.
#define ATTN_SMEM 40960
__global__ void __launch_bounds__(256, 2) attn_kernel(const __half* __restrict__ q,
                                                      const __half* __restrict__ k,
                                                      const __half* __restrict__ v,
                                                      __half* __restrict__ ctx)
{
    extern __shared__ char asmem[];
    __shared__ float mrow[64], lrow[64];
    __shared__ float pmax[128], psum[128];   // [wn][row]

    unsigned sb  = (unsigned)__cvta_generic_to_shared(asmem);
    unsigned QsB = sb;

    int tid = threadIdx.x;
    int bh = blockIdx.y; int b = bh >> 5; int h = bh & 31; int hk = h >> 2;
    int q0 = blockIdx.x * 64;
    int lane = tid & 31, warp = tid >> 5;
    int g = lane >> 2, tig = lane & 3;
    int t4 = lane >> 3;
    int wq = warp >> 1;   // q-row block of 16
    int wn = warp & 1;    // key half: keys [wn*32, wn*32+32)

    const __half* kb0 = k + ((size_t)(b * 8 + hk)) * Tv * 64;
    const __half* vb0 = v + ((size_t)(b * 8 + hk)) * Tv * 64;

    // per-thread KV copy descriptors (2 x 16B per operand per tile)
    int cprow[2], cpc[2];
    unsigned cpoff[2];
    #pragma unroll
    for (int kk = 0; kk < 2; kk++) {
        int lin = tid + kk * 256;
        cprow[kk] = lin >> 3; cpc[kk] = lin & 7;
        cpoff[kk] = (unsigned)(cprow[kk] * 128 + ((cpc[kk] ^ (cprow[kk] & 7)) << 4));
    }

    // prefetch tile 0 into buffer 0
    {
        unsigned kbB = sb + 8192u, vbB = sb + 16384u;
        #pragma unroll
        for (int kk = 0; kk < 2; kk++) {
            size_t off = ((size_t)cprow[kk]) * 64 + cpc[kk] * 8;
            CP_ASYNC16(kbB + cpoff[kk], kb0 + off);
            CP_ASYNC16(vbB + cpoff[kk], vb0 + off);
        }
        CP_COMMIT();
    }

    // load Q (64x64 halves), swizzled
    const __half* qbase = q + (((size_t)(b * 32 + h)) * Tv + q0) * 64;
    #pragma unroll
    for (int kk = 0; kk < 2; kk++) {
        int lin = tid + kk * 256;
        int row = lin >> 3, c = lin & 7;
        uint4 u = *(const uint4*)(qbase + (size_t)row * 64 + c * 8);
        *(uint4*)(asmem + row * 128 + ((c ^ (row & 7)) << 4)) = u;
    }
    if (tid < 64) { mrow[tid] = -INFINITY; lrow[tid] = 0.f; }

    // fragment offsets (relative to K/V buffer base)
    unsigned aoffQ[4], boffK[2][4], voffV[2][4];
    {
        int rowA = wq * 16 + (lane & 7) + (t4 & 1) * 8;
        #pragma unroll
        for (int ks = 0; ks < 4; ks++) {
            int ca = 2 * ks + (t4 >> 1);
            aoffQ[ks] = (unsigned)(rowA * 128 + ((ca ^ (rowA & 7)) << 4));
        }
        #pragma unroll
        for (int nb = 0; nb < 2; nb++) {
            int rowB = wn * 32 + nb * 16 + (lane & 7) + (t4 >> 1) * 8;
            #pragma unroll
            for (int ks = 0; ks < 4; ks++) {
                int cb = 2 * ks + (t4 & 1);
                boffK[nb][ks] = (unsigned)(rowB * 128 + ((cb ^ (rowB & 7)) << 4));
            }
        }
        #pragma unroll
        for (int t = 0; t < 2; t++) {
            int rowV = wn * 32 + t * 16 + (lane & 7) + (t4 & 1) * 8;
            #pragma unroll
            for (int np = 0; np < 4; np++) {
                int cv = np * 2 + (t4 >> 1);
                voffV[t][np] = (unsigned)(rowV * 128 + ((cv ^ (rowV & 7)) << 4));
            }
        }
    }

    int r0 = wq * 16 + g, r1 = r0 + 8;
    float cacc[8][4];
    #pragma unroll
    for (int ni = 0; ni < 8; ni++)
        #pragma unroll
        for (int c = 0; c < 4; c++) cacc[ni][c] = 0.f;

    int ntile = (q0 >> 6) + 1;
    for (int kt = 0; kt < ntile; kt++) {
        int buf = kt & 1;
        CP_WAIT(0);
        __syncthreads();

        // prefetch tile kt+1 into the other buffer (overlaps compute below)
        if (kt + 1 < ntile) {
            unsigned kbB = sb + 8192u + (unsigned)(buf ^ 1) * 16384u;
            unsigned vbB = kbB + 8192u;
            #pragma unroll
            for (int kk = 0; kk < 2; kk++) {
                size_t off = ((size_t)((kt + 1) * 64 + cprow[kk])) * 64 + cpc[kk] * 8;
                CP_ASYNC16(kbB + cpoff[kk], kb0 + off);
                CP_ASYNC16(vbB + cpoff[kk], vb0 + off);
            }
            CP_COMMIT();
        }

        unsigned KsB = sb + 8192u + (unsigned)buf * 16384u;
        unsigned VsB = KsB + 8192u;

        // ---- S = Q K^T : warp computes 16 rows x its 32 keys ----
        float sacc[4][4] = {};
        #pragma unroll
        for (int ks = 0; ks < 4; ks++) {
            unsigned af[4];
            LDSM4(af[0], af[1], af[2], af[3], QsB + aoffQ[ks]);
            #pragma unroll
            for (int nb = 0; nb < 2; nb++) {
                unsigned bf[4];
                LDSM4(bf[0], bf[1], bf[2], bf[3], KsB + boffK[nb][ks]);
                unsigned b0[2] = { bf[0], bf[1] };
                unsigned b1[2] = { bf[2], bf[3] };
                MMA_F16(sacc[nb*2 + 0], af, b0);
                MMA_F16(sacc[nb*2 + 1], af, b1);
            }
        }

        // ---- causal mask in-register ----
        int qi0 = q0 + r0, qi1 = q0 + r1;
        #pragma unroll
        for (int ni = 0; ni < 4; ni++) {
            int kc = kt * 64 + wn * 32 + ni * 8 + 2 * tig;
            if (kc > qi0)     sacc[ni][0] = -INFINITY;
            if (kc + 1 > qi0) sacc[ni][1] = -INFINITY;
            if (kc > qi1)     sacc[ni][2] = -INFINITY;
            if (kc + 1 > qi1) sacc[ni][3] = -INFINITY;
        }

        // ---- partial row max (quad shuffle), exchange across key-halves ----
        float pm0 = -INFINITY, pm1 = -INFINITY;
        #pragma unroll
        for (int ni = 0; ni < 4; ni++) {
            pm0 = fmaxf(pm0, fmaxf(sacc[ni][0], sacc[ni][1]));
            pm1 = fmaxf(pm1, fmaxf(sacc[ni][2], sacc[ni][3]));
        }
        pm0 = fmaxf(pm0, __shfl_xor_sync(0xffffffffu, pm0, 1));
        pm0 = fmaxf(pm0, __shfl_xor_sync(0xffffffffu, pm0, 2));
        pm1 = fmaxf(pm1, __shfl_xor_sync(0xffffffffu, pm1, 1));
        pm1 = fmaxf(pm1, __shfl_xor_sync(0xffffffffu, pm1, 2));
        if (tig == 0) { pmax[wn * 64 + r0] = pm0; pmax[wn * 64 + r1] = pm1; }
        __syncthreads();

        float mo0 = mrow[r0], mo1 = mrow[r1];
        float mx0 = fmaxf(mo0, fmaxf(pmax[r0], pmax[64 + r0]));
        float mx1 = fmaxf(mo1, fmaxf(pmax[r1], pmax[64 + r1]));
        float rsc0 = __expf(mo0 - mx0);
        float rsc1 = __expf(mo1 - mx1);

        // ---- exp + partial sums; P stays in registers as fp16 A-fragments ----
        unsigned pf[4][2];
        float s0 = 0.f, s1 = 0.f;
        #pragma unroll
        for (int ni = 0; ni < 4; ni++) {
            float p0 = __expf(sacc[ni][0] - mx0);
            float p1 = __expf(sacc[ni][1] - mx0);
            float p2 = __expf(sacc[ni][2] - mx1);
            float p3 = __expf(sacc[ni][3] - mx1);
            s0 += p0 + p1; s1 += p2 + p3;
            __half2 h01 = __floats2half2_rn(p0, p1);
            __half2 h23 = __floats2half2_rn(p2, p3);
            pf[ni][0] = *(unsigned*)&h01;
            pf[ni][1] = *(unsigned*)&h23;
        }
        s0 += __shfl_xor_sync(0xffffffffu, s0, 1);
        s0 += __shfl_xor_sync(0xffffffffu, s0, 2);
        s1 += __shfl_xor_sync(0xffffffffu, s1, 1);
        s1 += __shfl_xor_sync(0xffffffffu, s1, 2);
        if (tig == 0) { psum[wn * 64 + r0] = s0; psum[wn * 64 + r1] = s1; }

        // ---- rescale accumulated O ----
        #pragma unroll
        for (int ni = 0; ni < 8; ni++) {
            cacc[ni][0] *= rsc0; cacc[ni][1] *= rsc0;
            cacc[ni][2] *= rsc1; cacc[ni][3] *= rsc1;
        }

        // ---- P V : partial O over this warp's 32 keys, all 64 d-cols ----
        #pragma unroll
        for (int t = 0; t < 2; t++) {
            unsigned af[4] = { pf[2*t][0], pf[2*t][1], pf[2*t+1][0], pf[2*t+1][1] };
            #pragma unroll
            for (int np = 0; np < 4; np++) {
                unsigned vf[4];
                LDSM4T(vf[0], vf[1], vf[2], vf[3], VsB + voffV[t][np]);
                unsigned b0[2] = { vf[0], vf[1] };
                unsigned b1[2] = { vf[2], vf[3] };
                MMA_F16(cacc[np*2 + 0], af, b0);
                MMA_F16(cacc[np*2 + 1], af, b1);
            }
        }
        __syncthreads();

        // ---- update running stats (single agent per row) ----
        if (wn == 0 && tig == 0) {
            lrow[r0] = lrow[r0] * rsc0 + psum[r0] + psum[64 + r0];
            lrow[r1] = lrow[r1] * rsc1 + psum[r1] + psum[64 + r1];
            mrow[r0] = mx0;
            mrow[r1] = mx1;
        }
    }
    __syncthreads();

    // ---- cross-warp O reduce + epilogue ----
    float* Ored = (float*)asmem;       // 64 x 68 fp32 (overlaps dead Qs/K0)
    if (wn == 1) {
        #pragma unroll
        for (int ni = 0; ni < 8; ni++) {
            int col = ni * 8 + 2 * tig;
            *(float2*)(Ored + r0 * 68 + col) = make_float2(cacc[ni][0], cacc[ni][1]);
            *(float2*)(Ored + r1 * 68 + col) = make_float2(cacc[ni][2], cacc[ni][3]);
        }
    }
    __syncthreads();
    if (wn == 0) {
        float inv0 = 1.f / lrow[r0];
        float inv1 = 1.f / lrow[r1];
        #pragma unroll
        for (int ni = 0; ni < 8; ni++) {
            int col = ni * 8 + 2 * tig;
            float2 a0 = *(float2*)(Ored + r0 * 68 + col);
            float2 a1 = *(float2*)(Ored + r1 * 68 + col);
            __half2 o0 = __floats2half2_rn((cacc[ni][0] + a0.x) * inv0,
                                           (cacc[ni][1] + a0.y) * inv0);
            __half2 o1 = __floats2half2_rn((cacc[ni][2] + a1.x) * inv1,
                                           (cacc[ni][3] + a1.y) * inv1);
            size_t ad0 = ((size_t)(b * Tv + q0 + r0)) * Dv + h * 64 + col;
            size_t ad1 = ((size_t)(b * Tv + q0 + r1)) * Dv + h * 64 + col;
            *(__half2*)(ctx + ad0) = o0;
            *(__half2*)(ctx + ad1) = o1;
        }
    }
}

// ---------------- launch ----------------
extern "C" void kernel_launch(void* const* d_in, const int* in_sizes, int n_in,
                              void* d_out, int out_size)
{
    const float* x     = (const float*)d_in[0];
    const float* ln1_w = (const float*)d_in[1];
    const float* ln2_w = (const float*)d_in[2];
    const float* q_Us  = (const float*)d_in[3];
    const float* q_V   = (const float*)d_in[4];
    const float* k_Us  = (const float*)d_in[5];
    const float* k_V   = (const float*)d_in[6];
    const float* v_Us  = (const float*)d_in[7];
    const float* v_V   = (const float*)d_in[8];
    const float* o_Us  = (const float*)d_in[9];
    const float* o_V   = (const float*)d_in[10];
    const float* g_Usw = (const float*)d_in[11];
    const float* g_Vw  = (const float*)d_in[12];
    const float* u_Usw = (const float*)d_in[13];
    const float* u_Vw  = (const float*)d_in[14];
    const float* d_Usw = (const float*)d_in[15];
    const float* d_Vw  = (const float*)d_in[16];
    float* out = (float*)d_out;

    __half *h1, *qr, *kr, *vr, *qb, *kb, *vb, *ctx, *orr, *h2, *gr, *ur, *gg, *ff, *dr, *wts;
    float *x1, *rc, *rs;
    cudaGetSymbolAddress((void**)&h1,  g_h1);
    cudaGetSymbolAddress((void**)&qr,  g_qr);
    cudaGetSymbolAddress((void**)&kr,  g_kr);
    cudaGetSymbolAddress((void**)&vr,  g_vr);
    cudaGetSymbolAddress((void**)&qb,  g_q);
    cudaGetSymbolAddress((void**)&kb,  g_k);
    cudaGetSymbolAddress((void**)&vb,  g_v);
    cudaGetSymbolAddress((void**)&ctx, g_ctx);
    cudaGetSymbolAddress((void**)&orr, g_or);
    cudaGetSymbolAddress((void**)&x1,  g_x1);
    cudaGetSymbolAddress((void**)&h2,  g_h2);
    cudaGetSymbolAddress((void**)&gr,  g_gr);
    cudaGetSymbolAddress((void**)&ur,  g_ur);
    cudaGetSymbolAddress((void**)&gg,  g_g);
    cudaGetSymbolAddress((void**)&ff,  g_ff);
    cudaGetSymbolAddress((void**)&dr,  g_dr);
    cudaGetSymbolAddress((void**)&rc,  g_ropec);
    cudaGetSymbolAddress((void**)&rs,  g_ropes);
    cudaGetSymbolAddress((void**)&wts, g_wts);

    static int smem_set = 0;
    if (!smem_set) {
        cudaFuncSetAttribute(gemm_h, cudaFuncAttributeMaxDynamicSharedMemorySize, 98304);
        cudaFuncSetAttribute(attn_kernel, cudaFuncAttributeMaxDynamicSharedMemorySize, ATTN_SMEM);
        smem_set = 1;
    }
    const int SM = 98304;
    dim3 blk(256);

    prep_all<<<NWBLK + BT + Tv*32/256, blk>>>(wts, q_V, k_V, v_V, o_V, o_Us,
                                              g_Vw, u_Vw, g_Usw, u_Usw, d_Vw, d_Usw,
                                              x, ln1_w, h1, rc, rs);

    gemm_h<<<dim3(12, 32), blk, SM>>>(h1, Dv, 0, nullptr,
        wts + W_QV, qr, Hv*Rv, 8,  wts + W_KV, kr, HKv*Rv, 2,  wts + W_VV, vr, HKv*Rv, 2);

    usproj_fused<<<dim3(BT/64, 48), blk>>>(qr, kr, vr, q_Us, k_Us, v_Us, qb, kb, vb, rc, rs);

    attn_kernel<<<dim3(Tv/64, Bv*Hv), blk, ATTN_SMEM>>>(qb, kb, vb, ctx);

    gemm_h<<<dim3(8, 32), blk, SM>>>(ctx, Dv, 0, nullptr,
        wts + W_OV, orr, ROv, 8,  nullptr, nullptr, 0, 0,  nullptr, nullptr, 0, 0);
    gemm_h<<<dim3(16, 32), blk, SM>>>(orr, ROv, 1, x,
        wts + W_OUS, x1, Dv, 16,  nullptr, nullptr, 0, 0,  nullptr, nullptr, 0, 0);

    rms_kernel<<<BT, blk>>>(x1, ln2_w, h2);

    gemm_h<<<dim3(16, 32), blk, SM>>>(h2, Dv, 0, nullptr,
        wts + W_GV, gr, RFv, 8,  wts + W_UV, ur, RFv, 8,  nullptr, nullptr, 0, 0);

    gemm_h<<<dim3(44, 32), blk, SM>>>(gr, RFv, 0, nullptr,
        wts + W_GUS, gg, Iv, 44,  nullptr, nullptr, 0, 0,  nullptr, nullptr, 0, 0);
    gemm_h<<<dim3(44, 32), blk, SM>>>(ur, RFv, 2, gg,
        wts + W_UUS, ff, Iv, 44,  nullptr, nullptr, 0, 0,  nullptr, nullptr, 0, 0);

    gemm_h<<<dim3(8, 32), blk, SM>>>(ff, Iv, 0, nullptr,
        wts + W_DV, dr, RFv, 8,  nullptr, nullptr, 0, 0,  nullptr, nullptr, 0, 0);
    gemm_h<<<dim3(16, 32), blk, SM>>>(dr, RFv, 1, x1,
        wts + W_DUS, out, Dv, 16,  nullptr, nullptr, 0, 0,  nullptr, nullptr, 0, 0);
}

// round 12
// speedup vs baseline: 3.3269x; 1.0156x over previous
#include <cuda_runtime.h>
#include <cuda_fp16.h>
#include <math.h>

// ---------------- problem constants ----------------
#define Bv   4
#define Tv   1024
#define Dv   2048
#define Hv   32
#define DHv  64
#define HKv  8
#define Rv   32
#define ROv  1024
#define RFv  1024
#define Iv   5632
#define BT   (Bv*Tv)     // 4096

// ---------------- scratch ----------------
__device__ __half g_h1 [BT*Dv];
__device__ __half g_qr [BT*(Hv*Rv)];
__device__ __half g_kr [BT*(HKv*Rv)];
__device__ __half g_vr [BT*(HKv*Rv)];
__device__ __half g_q  [Bv*Hv*Tv*DHv];
__device__ __half g_k  [Bv*HKv*Tv*DHv];
__device__ __half g_v  [Bv*HKv*Tv*DHv];
__device__ __half g_ctx[BT*Dv];
__device__ __half g_or [BT*ROv];
__device__ float  g_x1 [BT*Dv];
__device__ __half g_h2 [BT*Dv];
__device__ __half g_gr [BT*RFv];
__device__ __half g_ur [BT*RFv];
__device__ __half g_g  [BT*Iv];
__device__ __half g_ff [BT*Iv];
__device__ __half g_dr [BT*RFv];
__device__ float  g_ropec[Tv*32];
__device__ float  g_ropes[Tv*32];
// converted (half) weights, concatenated; offsets in elements
#define W_QV   0
#define W_KV   2097152
#define W_VV   2621440
#define W_OV   3145728
#define W_OUS  5242880
#define W_GV   7340032
#define W_UV   9437184
#define W_GUS  11534336
#define W_UUS  17301504
#define W_DV   23068672
#define W_DUS  28835840
#define W_TOT  30932992
#define NWBLK  (W_TOT/4096)     // 7552 weight-prep blocks (16 elems/thread)
__device__ __half g_wts[W_TOT];

// ---------------- helpers ----------------
__device__ __forceinline__ uint2 pack4h(float4 v) {
    __half2 a = __floats2half2_rn(v.x, v.y);
    __half2 b = __floats2half2_rn(v.z, v.w);
    uint2 r;
    r.x = *(unsigned*)&a;
    r.y = *(unsigned*)&b;
    return r;
}
__device__ __forceinline__ float ex2f(float x) {
    float r;
    asm("ex2.approx.ftz.f32 %0, %1;" : "=f"(r) : "f"(x));
    return r;
}
#define LOG2E 1.4426950408889634f

// ---------------- fused front-end: weight f32->f16 + rms1 + rope table ----------------
__global__ void __launch_bounds__(256) prep_all(
    __half* __restrict__ dst,
    const float* __restrict__ s0, const float* __restrict__ s1, const float* __restrict__ s2,
    const float* __restrict__ s3, const float* __restrict__ s4, const float* __restrict__ s5,
    const float* __restrict__ s6, const float* __restrict__ s7, const float* __restrict__ s8,
    const float* __restrict__ s9, const float* __restrict__ s10,
    const float* __restrict__ x, const float* __restrict__ ln1_w, __half* __restrict__ h1,
    float* __restrict__ rc, float* __restrict__ rs)
{
    int bx = blockIdx.x;
    int tid = threadIdx.x;
    if (bx < NWBLK) {
        long i = ((long)bx * 256 + tid) * 16;
        const float* src; long base;
        if (i < W_GUS) {
            if (i < W_OV) {
                if (i < W_KV)        { src = s0; base = W_QV; }
                else if (i < W_VV)   { src = s1; base = W_KV; }
                else                 { src = s2; base = W_VV; }
            } else {
                if (i < W_OUS)       { src = s3; base = W_OV; }
                else if (i < W_GV)   { src = s4; base = W_OUS; }
                else if (i < W_UV)   { src = s5; base = W_GV; }
                else                 { src = s6; base = W_UV; }
            }
        } else {
            if (i < W_UUS)           { src = s7; base = W_GUS; }
            else if (i < W_DV)       { src = s8; base = W_UUS; }
            else if (i < W_DUS)      { src = s9; base = W_DV; }
            else                     { src = s10; base = W_DUS; }
        }
        const float4* sp = (const float4*)(src + (i - base));
        float4 v0 = sp[0], v1 = sp[1], v2 = sp[2], v3 = sp[3];
        uint2 p0 = pack4h(v0), p1 = pack4h(v1), p2 = pack4h(v2), p3 = pack4h(v3);
        uint4 o0 = { p0.x, p0.y, p1.x, p1.y };
        uint4 o1 = { p2.x, p2.y, p3.x, p3.y };
        *(uint4*)(dst + i)     = o0;
        *(uint4*)(dst + i + 8) = o1;
    } else if (bx < NWBLK + BT) {
        int row = bx - NWBLK;
        const float4* xr = (const float4*)(x + (size_t)row * Dv);
        float4 v0 = xr[tid];
        float4 v1 = xr[tid + 256];
        float ss = v0.x*v0.x + v0.y*v0.y + v0.z*v0.z + v0.w*v0.w
                 + v1.x*v1.x + v1.y*v1.y + v1.z*v1.z + v1.w*v1.w;
        #pragma unroll
        for (int o = 16; o; o >>= 1) ss += __shfl_xor_sync(0xffffffffu, ss, o);
        __shared__ float red[8];
        if ((tid & 31) == 0) red[tid >> 5] = ss;
        __syncthreads();
        float tot = 0.f;
        #pragma unroll
        for (int i = 0; i < 8; i++) tot += red[i];
        float inv = rsqrtf(tot * (1.0f / Dv) + 1e-5f);
        const float4* wr = (const float4*)ln1_w;
        float4 w0 = wr[tid], w1 = wr[tid + 256];
        float4 o0 = { v0.x*inv*w0.x, v0.y*inv*w0.y, v0.z*inv*w0.z, v0.w*inv*w0.w };
        float4 o1 = { v1.x*inv*w1.x, v1.y*inv*w1.y, v1.z*inv*w1.z, v1.w*inv*w1.w };
        __half* orow = h1 + (size_t)row * Dv;
        *(uint2*)(orow + tid * 4)         = pack4h(o0);
        *(uint2*)(orow + (tid + 256) * 4) = pack4h(o1);
    } else {
        int idx = (bx - NWBLK - BT) * 256 + tid;
        int t = idx >> 5, d = idx & 31;
        float invf = expf(-0.28782313662425572f * (float)d);
        float ang = (float)t * invf;
        rc[idx] = cosf(ang);
        rs[idx] = sinf(ang);
    }
}

// ---------------- RMSNorm (fp32 in, fp16 out) ----------------
__global__ void __launch_bounds__(256) rms_kernel(const float* __restrict__ x,
                                                  const float* __restrict__ w,
                                                  __half* __restrict__ out)
{
    int row = blockIdx.x;
    int tid = threadIdx.x;
    const float4* xr = (const float4*)(x + (size_t)row * Dv);
    float4 v0 = xr[tid];
    float4 v1 = xr[tid + 256];
    float ss = v0.x*v0.x + v0.y*v0.y + v0.z*v0.z + v0.w*v0.w
             + v1.x*v1.x + v1.y*v1.y + v1.z*v1.z + v1.w*v1.w;
    #pragma unroll
    for (int o = 16; o; o >>= 1) ss += __shfl_xor_sync(0xffffffffu, ss, o);
    __shared__ float red[8];
    if ((tid & 31) == 0) red[tid >> 5] = ss;
    __syncthreads();
    float tot = 0.f;
    #pragma unroll
    for (int i = 0; i < 8; i++) tot += red[i];
    float inv = rsqrtf(tot * (1.0f / Dv) + 1e-5f);
    const float4* wr = (const float4*)w;
    float4 w0 = wr[tid], w1 = wr[tid + 256];
    float4 o0 = { v0.x*inv*w0.x, v0.y*inv*w0.y, v0.z*inv*w0.z, v0.w*inv*w0.w };
    float4 o1 = { v1.x*inv*w1.x, v1.y*inv*w1.y, v1.z*inv*w1.z, v1.w*inv*w1.w };
    __half* orow = out + (size_t)row * Dv;
    *(uint2*)(orow + tid * 4)         = pack4h(o0);
    *(uint2*)(orow + (tid + 256) * 4) = pack4h(o1);
}

// ---------------- fp16 tensor-core GEMM (3-stage, TBK=64, ldmatrix) ----------------
#define STAGES 3

#define CP_ASYNC16(dst, src) asm volatile("cp.async.cg.shared.global [%0], [%1], 16;\n" :: "r"(dst), "l"(src))
#define CP_COMMIT() asm volatile("cp.async.commit_group;\n" ::)
#define CP_WAIT(n)  asm volatile("cp.async.wait_group %0;\n" :: "n"(n))

#define LDSM4(r0, r1, r2, r3, addr) \
    asm volatile("ldmatrix.sync.aligned.m8n8.x4.shared.b16 {%0,%1,%2,%3}, [%4];" \
        : "=r"(r0), "=r"(r1), "=r"(r2), "=r"(r3) : "r"(addr))

#define LDSM4T(r0, r1, r2, r3, addr) \
    asm volatile("ldmatrix.sync.aligned.m8n8.x4.trans.shared.b16 {%0,%1,%2,%3}, [%4];" \
        : "=r"(r0), "=r"(r1), "=r"(r2), "=r"(r3) : "r"(addr))

#define MMA_F16(d, a, b) \
    asm volatile("mma.sync.aligned.m16n8k16.row.col.f32.f16.f16.f32 " \
        "{%0,%1,%2,%3}, {%4,%5,%6,%7}, {%8,%9}, {%0,%1,%2,%3};" \
        : "+f"(d[0]), "+f"(d[1]), "+f"(d[2]), "+f"(d[3]) \
        : "r"(a[0]), "r"(a[1]), "r"(a[2]), "r"(a[3]), "r"(b[0]), "r"(b[1]))

__global__ void __launch_bounds__(256, 2) gemm_h(
    const __half* __restrict__ A, int K, int mode, const void* __restrict__ aux,
    const __half* __restrict__ B0, void* __restrict__ C0, int N0, int nb0,
    const __half* __restrict__ B1, void* __restrict__ C1, int N1, int nb1,
    const __half* __restrict__ B2, void* __restrict__ C2, int N2, int nb2)
{
    extern __shared__ __half smem[];
    unsigned sbase = (unsigned)__cvta_generic_to_shared(smem);

    int bx = blockIdx.x;
    const __half* Bw; void* C; int N; int bnb;
    if (bx < nb0)            { Bw = B0; C = C0; N = N0; bnb = bx; }
    else if (bx < nb0 + nb1) { Bw = B1; C = C1; N = N1; bnb = bx - nb0; }
    else                     { Bw = B2; C = C2; N = N2; bnb = bx - nb0 - nb1; }

    int tid  = threadIdx.x;
    int bm = blockIdx.y * 128;
    int bn = bnb * 128;
    int lane = tid & 31, warp = tid >> 5;
    int wm = warp >> 1, wn = warp & 1;
    int g  = lane >> 2, tig = lane & 3;

    unsigned dstoff[4];
    const __half* srcA[4];
    const __half* srcB[4];
    #pragma unroll
    for (int i = 0; i < 4; i++) {
        int lin = tid + i * 256;
        int row = lin >> 3, c = lin & 7;
        dstoff[i] = (unsigned)(row * 128 + ((c ^ (row & 7)) << 4));
        srcA[i] = A  + (size_t)(bm + row) * K + c * 8;
        srcB[i] = Bw + (size_t)(bn + row) * K + c * 8;
    }

    int t4 = lane >> 3;
    unsigned aoff[2][4], boff[4][4];
    #pragma unroll
    for (int mi = 0; mi < 2; mi++) {
        int row = wm * 32 + mi * 16 + (lane & 7) + (t4 & 1) * 8;
        #pragma unroll
        for (int ks = 0; ks < 4; ks++) {
            int chunk = 2 * ks + (t4 >> 1);
            aoff[mi][ks] = (unsigned)(row * 128 + ((chunk ^ (row & 7)) << 4));
        }
    }
    #pragma unroll
    for (int np = 0; np < 4; np++) {
        int row = wn * 64 + np * 16 + (lane & 7) + (t4 >> 1) * 8;
        #pragma unroll
        for (int ks = 0; ks < 4; ks++) {
            int chunk = 2 * ks + (t4 & 1);
            boff[np][ks] = (unsigned)(row * 128 + ((chunk ^ (row & 7)) << 4));
        }
    }

    float acc[2][8][4];
    #pragma unroll
    for (int mi = 0; mi < 2; mi++)
        #pragma unroll
        for (int ni = 0; ni < 8; ni++)
            #pragma unroll
            for (int q = 0; q < 4; q++) acc[mi][ni][q] = 0.f;

    const int NT = K >> 6;

    #pragma unroll
    for (int s = 0; s < STAGES - 1; s++) {
        unsigned da = sbase + (unsigned)s * 32768u;
        unsigned db = da + 16384u;
        #pragma unroll
        for (int i = 0; i < 4; i++) {
            CP_ASYNC16(da + dstoff[i], srcA[i] + (size_t)s * 64);
            CP_ASYNC16(db + dstoff[i], srcB[i] + (size_t)s * 64);
        }
        CP_COMMIT();
    }

    for (int kt = 0; kt < NT; kt++) {
        int st = kt % STAGES;
        CP_WAIT(STAGES - 2);
        __syncthreads();

        int pf = kt + STAGES - 1;
        if (pf < NT) {
            int pst = pf % STAGES;
            unsigned da = sbase + (unsigned)pst * 32768u;
            unsigned db = da + 16384u;
            #pragma unroll
            for (int i = 0; i < 4; i++) {
                CP_ASYNC16(da + dstoff[i], srcA[i] + (size_t)pf * 64);
                CP_ASYNC16(db + dstoff[i], srcB[i] + (size_t)pf * 64);
            }
        }
        CP_COMMIT();

        unsigned AsB = sbase + (unsigned)st * 32768u;
        unsigned BsB = AsB + 16384u;

        #pragma unroll
        for (int ks = 0; ks < 4; ks++) {
            unsigned af[2][4];
            LDSM4(af[0][0], af[0][1], af[0][2], af[0][3], AsB + aoff[0][ks]);
            LDSM4(af[1][0], af[1][1], af[1][2], af[1][3], AsB + aoff[1][ks]);
            unsigned bf[8][2];
            #pragma unroll
            for (int np = 0; np < 4; np++)
                LDSM4(bf[2*np][0], bf[2*np][1], bf[2*np+1][0], bf[2*np+1][1],
                      BsB + boff[np][ks]);
            #pragma unroll
            for (int mi = 0; mi < 2; mi++)
                #pragma unroll
                for (int ni = 0; ni < 8; ni++)
                    MMA_F16(acc[mi][ni], af[mi], bf[ni]);
        }
    }

    #pragma unroll
    for (int mi = 0; mi < 2; mi++) {
        int row0 = bm + wm * 32 + mi * 16 + g;
        #pragma unroll
        for (int half = 0; half < 2; half++) {
            int row = row0 + half * 8;
            size_t rowoff = (size_t)row * N;
            #pragma unroll
            for (int ni = 0; ni < 8; ni++) {
                int col = bn + wn * 64 + ni * 8 + 2 * tig;
                size_t idx = rowoff + col;
                float vx = acc[mi][ni][half * 2 + 0];
                float vy = acc[mi][ni][half * 2 + 1];
                if (mode == 1) {
                    float2 rsd = *(const float2*)((const float*)aux + idx);
                    vx += rsd.x; vy += rsd.y;
                    float2 o = { vx, vy };
                    *(float2*)((float*)C + idx) = o;
                } else {
                    if (mode == 2) {
                        __half2 gh = *(const __half2*)((const __half*)aux + idx);
                        float2 gf = __half22float2(gh);
                        vx *= gf.x / (1.f + __expf(-gf.x));
                        vy *= gf.y / (1.f + __expf(-gf.y));
                    }
                    __half2 o = __floats2half2_rn(vx, vy);
                    *(__half2*)((__half*)C + idx) = o;
                }
            }
        }
    }
}

// ---------------- fused per-head Us projection (+ RoPE); half out; q pre-scaled ----------------
__global__ void __launch_bounds__(256) usproj_fused(
    const __half* __restrict__ qr, const __half* __restrict__ kr, const __half* __restrict__ vr,
    const float* __restrict__ qUs, const float* __restrict__ kUs, const float* __restrict__ vUs,
    __half* __restrict__ qb, __half* __restrict__ kb, __half* __restrict__ vb,
    const float* __restrict__ rc, const float* __restrict__ rs)
{
    __shared__ __align__(16) float inT[32][64];
    __shared__ __align__(16) float UsT[32][64];
    __shared__ __align__(16) float os [64][64];
    int y = blockIdx.y;
    const __half* in; const float* Us; __half* out; int heads, h, rope;
    float osc = 1.0f;
    // q is pre-scaled by (1/8) * log2(e) so attention can use exp2
    if (y < 32)      { in = qr; Us = qUs; out = qb; heads = 32; h = y;      rope = 1; osc = 0.125f * LOG2E; }
    else if (y < 40) { in = kr; Us = kUs; out = kb; heads = 8;  h = y - 32; rope = 1; }
    else             { in = vr; Us = vUs; out = vb; heads = 8;  h = y - 40; rope = 0; }

    int bt0 = blockIdx.x * 64;
    int tid = threadIdx.x;
    int ldin = heads * 32;

    {
        int d = tid >> 2; int r0 = (tid & 3) * 8;
        const float* p = Us + ((size_t)h * 64 + d) * 32 + r0;
        float4 u0 = *(const float4*)p;
        float4 u1 = *(const float4*)(p + 4);
        UsT[r0+0][d]=u0.x; UsT[r0+1][d]=u0.y; UsT[r0+2][d]=u0.z; UsT[r0+3][d]=u0.w;
        UsT[r0+4][d]=u1.x; UsT[r0+5][d]=u1.y; UsT[r0+6][d]=u1.z; UsT[r0+7][d]=u1.w;
    }
    {
        int i = tid >> 2; int r0 = (tid & 3) * 8;
        const __half* p = in + (size_t)(bt0 + i) * ldin + h * 32 + r0;
        uint4 u = *(const uint4*)p;
        float2 f0 = __half22float2(*(__half2*)&u.x);
        float2 f1 = __half22float2(*(__half2*)&u.y);
        float2 f2 = __half22float2(*(__half2*)&u.z);
        float2 f3 = __half22float2(*(__half2*)&u.w);
        inT[r0+0][i]=f0.x; inT[r0+1][i]=f0.y; inT[r0+2][i]=f1.x; inT[r0+3][i]=f1.y;
        inT[r0+4][i]=f2.x; inT[r0+5][i]=f2.y; inT[r0+6][i]=f3.x; inT[r0+7][i]=f3.y;
    }
    __syncthreads();

    int tx = tid & 15, ty = tid >> 4;
    float acc[4][4] = {};
    #pragma unroll
    for (int r = 0; r < 32; r++) {
        float4 a = *(const float4*)&inT[r][ty*4];
        float4 b = *(const float4*)&UsT[r][tx*4];
        float av[4] = {a.x,a.y,a.z,a.w};
        float bv[4] = {b.x,b.y,b.z,b.w};
        #pragma unroll
        for (int rr = 0; rr < 4; rr++)
            #pragma unroll
            for (int cc = 0; cc < 4; cc++)
                acc[rr][cc] = fmaf(av[rr], bv[cc], acc[rr][cc]);
    }
    #pragma unroll
    for (int rr = 0; rr < 4; rr++)
        #pragma unroll
        for (int cc = 0; cc < 4; cc++)
            os[ty*4+rr][tx*4+cc] = acc[rr][cc];
    __syncthreads();

    if (!rope) {
        #pragma unroll
        for (int kk = 0; kk < 4; kk++) {
            int lin4 = tid + kk * 256;
            int i = lin4 >> 4; int d0 = (lin4 & 15) * 4;
            int bt = bt0 + i; int b = bt >> 10; int t = bt & 1023;
            float4 vv = *(const float4*)&os[i][d0];
            size_t addr = (((size_t)(b * heads + h)) * Tv + t) * 64 + d0;
            *(uint2*)(out + addr) = pack4h(vv);
        }
    } else {
        #pragma unroll
        for (int kk = 0; kk < 2; kk++) {
            int lin4 = tid + kk * 256;
            int i = lin4 >> 3; int d0 = (lin4 & 7) * 4;
            int bt = bt0 + i; int b = bt >> 10; int t = bt & 1023;
            float4 x1 = *(const float4*)&os[i][d0];
            float4 x2 = *(const float4*)&os[i][d0 + 32];
            float4 cc4 = *(const float4*)(rc + t * 32 + d0);
            float4 ss4 = *(const float4*)(rs + t * 32 + d0);
            float xx1[4] = {x1.x,x1.y,x1.z,x1.w};
            float xx2[4] = {x2.x,x2.y,x2.z,x2.w};
            float ca[4] = {cc4.x,cc4.y,cc4.z,cc4.w};
            float sa[4] = {ss4.x,ss4.y,ss4.z,ss4.w};
            float4 w1, w2;
            float* o1 = &w1.x; float* o2 = &w2.x;
            #pragma unroll
            for (int c = 0; c < 4; c++) {
                o1[c] = (xx1[c] * ca[c] - xx2[c] * sa[c]) * osc;
                o2[c] = (xx2[c] * ca[c] + xx1[c] * sa[c]) * osc;
            }
            size_t base = (((size_t)(b * heads + h)) * Tv + t) * 64;
            *(uint2*)(out + base + d0)      = pack4h(w1);
            *(uint2*)(out + base + d0 + 32) = pack4h(w2);
        }
    }
}

// ---------------- flash attention, fp16 MMA, in-register softmax (base-2), double-buffered KV ----------------
// dynamic smem: Qs [0,8K) | K0 [8K,16K) | V0 [16K,24K) | K1 [24K,32K) | V1 [32K,40K)
#define ATTN_SMEM 40960
__global__ void __launch_bounds__(256, 2) attn_kernel(const __half* __restrict__ q,
                                                      const __half* __restrict__ k,
                                                      const __half* __restrict__ v,
                                                      __half* __restrict__ ctx)
{
    extern __shared__ char asmem[];
    __shared__ float mrow[64], lrow[64];
    __shared__ float pmax[128], psum[128];

    unsigned sb  = (unsigned)__cvta_generic_to_shared(asmem);
    unsigned QsB = sb;

    int tid = threadIdx.x;
    int bh = blockIdx.y; int b = bh >> 5; int h = bh & 31; int hk = h >> 2;
    int q0 = blockIdx.x * 64;
    int lane = tid & 31, warp = tid >> 5;
    int g = lane >> 2, tig = lane & 3;
    int t4 = lane >> 3;
    int wq = warp >> 1;
    int wn = warp & 1;

    const __half* kb0 = k + ((size_t)(b * 8 + hk)) * Tv * 64;
    const __half* vb0 = v + ((size_t)(b * 8 + hk)) * Tv * 64;

    int cprow[2], cpc[2];
    unsigned cpoff[2];
    #pragma unroll
    for (int kk = 0; kk < 2; kk++) {
        int lin = tid + kk * 256;
        cprow[kk] = lin >> 3; cpc[kk] = lin & 7;
        cpoff[kk] = (unsigned)(cprow[kk] * 128 + ((cpc[kk] ^ (cprow[kk] & 7)) << 4));
    }

    {
        unsigned kbB = sb + 8192u, vbB = sb + 16384u;
        #pragma unroll
        for (int kk = 0; kk < 2; kk++) {
            size_t off = ((size_t)cprow[kk]) * 64 + cpc[kk] * 8;
            CP_ASYNC16(kbB + cpoff[kk], kb0 + off);
            CP_ASYNC16(vbB + cpoff[kk], vb0 + off);
        }
        CP_COMMIT();
    }

    const __half* qbase = q + (((size_t)(b * 32 + h)) * Tv + q0) * 64;
    #pragma unroll
    for (int kk = 0; kk < 2; kk++) {
        int lin = tid + kk * 256;
        int row = lin >> 3, c = lin & 7;
        uint4 u = *(const uint4*)(qbase + (size_t)row * 64 + c * 8);
        *(uint4*)(asmem + row * 128 + ((c ^ (row & 7)) << 4)) = u;
    }
    if (tid < 64) { mrow[tid] = -INFINITY; lrow[tid] = 0.f; }

    unsigned aoffQ[4], boffK[2][4], voffV[2][4];
    {
        int rowA = wq * 16 + (lane & 7) + (t4 & 1) * 8;
        #pragma unroll
        for (int ks = 0; ks < 4; ks++) {
            int ca = 2 * ks + (t4 >> 1);
            aoffQ[ks] = (unsigned)(rowA * 128 + ((ca ^ (rowA & 7)) << 4));
        }
        #pragma unroll
        for (int nb = 0; nb < 2; nb++) {
            int rowB = wn * 32 + nb * 16 + (lane & 7) + (t4 >> 1) * 8;
            #pragma unroll
            for (int ks = 0; ks < 4; ks++) {
                int cb = 2 * ks + (t4 & 1);
                boffK[nb][ks] = (unsigned)(rowB * 128 + ((cb ^ (rowB & 7)) << 4));
            }
        }
        #pragma unroll
        for (int t = 0; t < 2; t++) {
            int rowV = wn * 32 + t * 16 + (lane & 7) + (t4 & 1) * 8;
            #pragma unroll
            for (int np = 0; np < 4; np++) {
                int cv = np * 2 + (t4 >> 1);
                voffV[t][np] = (unsigned)(rowV * 128 + ((cv ^ (rowV & 7)) << 4));
            }
        }
    }

    int r0 = wq * 16 + g, r1 = r0 + 8;
    float cacc[8][4];
    #pragma unroll
    for (int ni = 0; ni < 8; ni++)
        #pragma unroll
        for (int c = 0; c < 4; c++) cacc[ni][c] = 0.f;

    int ntile = (q0 >> 6) + 1;
    for (int kt = 0; kt < ntile; kt++) {
        int buf = kt & 1;
        CP_WAIT(0);
        __syncthreads();

        if (kt + 1 < ntile) {
            unsigned kbB = sb + 8192u + (unsigned)(buf ^ 1) * 16384u;
            unsigned vbB = kbB + 8192u;
            #pragma unroll
            for (int kk = 0; kk < 2; kk++) {
                size_t off = ((size_t)((kt + 1) * 64 + cprow[kk])) * 64 + cpc[kk] * 8;
                CP_ASYNC16(kbB + cpoff[kk], kb0 + off);
                CP_ASYNC16(vbB + cpoff[kk], vb0 + off);
            }
            CP_COMMIT();
        }

        unsigned KsB = sb + 8192u + (unsigned)buf * 16384u;
        unsigned VsB = KsB + 8192u;

        // ---- S = Q K^T ----
        float sacc[4][4] = {};
        #pragma unroll
        for (int ks = 0; ks < 4; ks++) {
            unsigned af[4];
            LDSM4(af[0], af[1], af[2], af[3], QsB + aoffQ[ks]);
            #pragma unroll
            for (int nb = 0; nb < 2; nb++) {
                unsigned bf[4];
                LDSM4(bf[0], bf[1], bf[2], bf[3], KsB + boffK[nb][ks]);
                unsigned b0[2] = { bf[0], bf[1] };
                unsigned b1[2] = { bf[2], bf[3] };
                MMA_F16(sacc[nb*2 + 0], af, b0);
                MMA_F16(sacc[nb*2 + 1], af, b1);
            }
        }

        // ---- causal mask: only the diagonal tile needs it ----
        if (kt == ntile - 1) {
            int qi0 = q0 + r0, qi1 = q0 + r1;
            #pragma unroll
            for (int ni = 0; ni < 4; ni++) {
                int kc = kt * 64 + wn * 32 + ni * 8 + 2 * tig;
                if (kc > qi0)     sacc[ni][0] = -INFINITY;
                if (kc + 1 > qi0) sacc[ni][1] = -INFINITY;
                if (kc > qi1)     sacc[ni][2] = -INFINITY;
                if (kc + 1 > qi1) sacc[ni][3] = -INFINITY;
            }
        }

        // ---- partial row max ----
        float pm0 = -INFINITY, pm1 = -INFINITY;
        #pragma unroll
        for (int ni = 0; ni < 4; ni++) {
            pm0 = fmaxf(pm0, fmaxf(sacc[ni][0], sacc[ni][1]));
            pm1 = fmaxf(pm1, fmaxf(sacc[ni][2], sacc[ni][3]));
        }
        pm0 = fmaxf(pm0, __shfl_xor_sync(0xffffffffu, pm0, 1));
        pm0 = fmaxf(pm0, __shfl_xor_sync(0xffffffffu, pm0, 2));
        pm1 = fmaxf(pm1, __shfl_xor_sync(0xffffffffu, pm1, 1));
        pm1 = fmaxf(pm1, __shfl_xor_sync(0xffffffffu, pm1, 2));
        if (tig == 0) { pmax[wn * 64 + r0] = pm0; pmax[wn * 64 + r1] = pm1; }
        __syncthreads();

        float mo0 = mrow[r0], mo1 = mrow[r1];
        float mx0 = fmaxf(mo0, fmaxf(pmax[r0], pmax[64 + r0]));
        float mx1 = fmaxf(mo1, fmaxf(pmax[r1], pmax[64 + r1]));
        float rsc0 = ex2f(mo0 - mx0);
        float rsc1 = ex2f(mo1 - mx1);

        // ---- exp2 + partial sums; P stays in fp16 A-fragments ----
        unsigned pf[4][2];
        float s0 = 0.f, s1 = 0.f;
        #pragma unroll
        for (int ni = 0; ni < 4; ni++) {
            float p0 = ex2f(sacc[ni][0] - mx0);
            float p1 = ex2f(sacc[ni][1] - mx0);
            float p2 = ex2f(sacc[ni][2] - mx1);
            float p3 = ex2f(sacc[ni][3] - mx1);
            s0 += p0 + p1; s1 += p2 + p3;
            __half2 h01 = __floats2half2_rn(p0, p1);
            __half2 h23 = __floats2half2_rn(p2, p3);
            pf[ni][0] = *(unsigned*)&h01;
            pf[ni][1] = *(unsigned*)&h23;
        }
        s0 += __shfl_xor_sync(0xffffffffu, s0, 1);
        s0 += __shfl_xor_sync(0xffffffffu, s0, 2);
        s1 += __shfl_xor_sync(0xffffffffu, s1, 1);
        s1 += __shfl_xor_sync(0xffffffffu, s1, 2);
        if (tig == 0) { psum[wn * 64 + r0] = s0; psum[wn * 64 + r1] = s1; }

        // ---- rescale accumulated O ----
        #pragma unroll
        for (int ni = 0; ni < 8; ni++) {
            cacc[ni][0] *= rsc0; cacc[ni][1] *= rsc0;
            cacc[ni][2] *= rsc1; cacc[ni][3] *= rsc1;
        }

        // ---- P V ----
        #pragma unroll
        for (int t = 0; t < 2; t++) {
            unsigned af[4] = { pf[2*t][0], pf[2*t][1], pf[2*t+1][0], pf[2*t+1][1] };
            #pragma unroll
            for (int np = 0; np < 4; np++) {
                unsigned vf[4];
                LDSM4T(vf[0], vf[1], vf[2], vf[3], VsB + voffV[t][np]);
                unsigned b0[2] = { vf[0], vf[1] };
                unsigned b1[2] = { vf[2], vf[3] };
                MMA_F16(cacc[np*2 + 0], af, b0);
                MMA_F16(cacc[np*2 + 1], af, b1);
            }
        }
        __syncthreads();

        if (wn == 0 && tig == 0) {
            lrow[r0] = lrow[r0] * rsc0 + psum[r0] + psum[64 + r0];
            lrow[r1] = lrow[r1] * rsc1 + psum[r1] + psum[64 + r1];
            mrow[r0] = mx0;
            mrow[r1] = mx1;
        }
    }
    __syncthreads();

    // ---- cross-warp O reduce + epilogue ----
    float* Ored = (float*)asmem;
    if (wn == 1) {
        #pragma unroll
        for (int ni = 0; ni < 8; ni++) {
            int col = ni * 8 + 2 * tig;
            *(float2*)(Ored + r0 * 68 + col) = make_float2(cacc[ni][0], cacc[ni][1]);
            *(float2*)(Ored + r1 * 68 + col) = make_float2(cacc[ni][2], cacc[ni][3]);
        }
    }
    __syncthreads();
    if (wn == 0) {
        float inv0 = 1.f / lrow[r0];
        float inv1 = 1.f / lrow[r1];
        #pragma unroll
        for (int ni = 0; ni < 8; ni++) {
            int col = ni * 8 + 2 * tig;
            float2 a0 = *(float2*)(Ored + r0 * 68 + col);
            float2 a1 = *(float2*)(Ored + r1 * 68 + col);
            __half2 o0 = __floats2half2_rn((cacc[ni][0] + a0.x) * inv0,
                                           (cacc[ni][1] + a0.y) * inv0);
            __half2 o1 = __floats2half2_rn((cacc[ni][2] + a1.x) * inv1,
                                           (cacc[ni][3] + a1.y) * inv1);
            size_t ad0 = ((size_t)(b * Tv + q0 + r0)) * Dv + h * 64 + col;
            size_t ad1 = ((size_t)(b * Tv + q0 + r1)) * Dv + h * 64 + col;
            *(__half2*)(ctx + ad0) = o0;
            *(__half2*)(ctx + ad1) = o1;
        }
    }
}

// ---------------- launch ----------------
extern "C" void kernel_launch(void* const* d_in, const int* in_sizes, int n_in,
                              void* d_out, int out_size)
{
    const float* x     = (const float*)d_in[0];
    const float* ln1_w = (const float*)d_in[1];
    const float* ln2_w = (const float*)d_in[2];
    const float* q_Us  = (const float*)d_in[3];
    const float* q_V   = (const float*)d_in[4];
    const float* k_Us  = (const float*)d_in[5];
    const float* k_V   = (const float*)d_in[6];
    const float* v_Us  = (const float*)d_in[7];
    const float* v_V   = (const float*)d_in[8];
    const float* o_Us  = (const float*)d_in[9];
    const float* o_V   = (const float*)d_in[10];
    const float* g_Usw = (const float*)d_in[11];
    const float* g_Vw  = (const float*)d_in[12];
    const float* u_Usw = (const float*)d_in[13];
    const float* u_Vw  = (const float*)d_in[14];
    const float* d_Usw = (const float*)d_in[15];
    const float* d_Vw  = (const float*)d_in[16];
    float* out = (float*)d_out;

    __half *h1, *qr, *kr, *vr, *qb, *kb, *vb, *ctx, *orr, *h2, *gr, *ur, *gg, *ff, *dr, *wts;
    float *x1, *rc, *rs;
    cudaGetSymbolAddress((void**)&h1,  g_h1);
    cudaGetSymbolAddress((void**)&qr,  g_qr);
    cudaGetSymbolAddress((void**)&kr,  g_kr);
    cudaGetSymbolAddress((void**)&vr,  g_vr);
    cudaGetSymbolAddress((void**)&qb,  g_q);
    cudaGetSymbolAddress((void**)&kb,  g_k);
    cudaGetSymbolAddress((void**)&vb,  g_v);
    cudaGetSymbolAddress((void**)&ctx, g_ctx);
    cudaGetSymbolAddress((void**)&orr, g_or);
    cudaGetSymbolAddress((void**)&x1,  g_x1);
    cudaGetSymbolAddress((void**)&h2,  g_h2);
    cudaGetSymbolAddress((void**)&gr,  g_gr);
    cudaGetSymbolAddress((void**)&ur,  g_ur);
    cudaGetSymbolAddress((void**)&gg,  g_g);
    cudaGetSymbolAddress((void**)&ff,  g_ff);
    cudaGetSymbolAddress((void**)&dr,  g_dr);
    cudaGetSymbolAddress((void**)&rc,  g_ropec);
    cudaGetSymbolAddress((void**)&rs,  g_ropes);
    cudaGetSymbolAddress((void**)&wts, g_wts);

    static int smem_set = 0;
    if (!smem_set) {
        cudaFuncSetAttribute(gemm_h, cudaFuncAttributeMaxDynamicSharedMemorySize, 98304);
        cudaFuncSetAttribute(attn_kernel, cudaFuncAttributeMaxDynamicSharedMemorySize, ATTN_SMEM);
        smem_set = 1;
    }
    const int SM = 98304;
    dim3 blk(256);

    prep_all<<<NWBLK + BT + Tv*32/256, blk>>>(wts, q_V, k_V, v_V, o_V, o_Us,
                                              g_Vw, u_Vw, g_Usw, u_Usw, d_Vw, d_Usw,
                                              x, ln1_w, h1, rc, rs);

    gemm_h<<<dim3(12, 32), blk, SM>>>(h1, Dv, 0, nullptr,
        wts + W_QV, qr, Hv*Rv, 8,  wts + W_KV, kr, HKv*Rv, 2,  wts + W_VV, vr, HKv*Rv, 2);

    usproj_fused<<<dim3(BT/64, 48), blk>>>(qr, kr, vr, q_Us, k_Us, v_Us, qb, kb, vb, rc, rs);

    attn_kernel<<<dim3(Tv/64, Bv*Hv), blk, ATTN_SMEM>>>(qb, kb, vb, ctx);

    gemm_h<<<dim3(8, 32), blk, SM>>>(ctx, Dv, 0, nullptr,
        wts + W_OV, orr, ROv, 8,  nullptr, nullptr, 0, 0,  nullptr, nullptr, 0, 0);
    gemm_h<<<dim3(16, 32), blk, SM>>>(orr, ROv, 1, x,
        wts + W_OUS, x1, Dv, 16,  nullptr, nullptr, 0, 0,  nullptr, nullptr, 0, 0);

    rms_kernel<<<BT, blk>>>(x1, ln2_w, h2);

    gemm_h<<<dim3(16, 32), blk, SM>>>(h2, Dv, 0, nullptr,
        wts + W_GV, gr, RFv, 8,  wts + W_UV, ur, RFv, 8,  nullptr, nullptr, 0, 0);

    gemm_h<<<dim3(44, 32), blk, SM>>>(gr, RFv, 0, nullptr,
        wts + W_GUS, gg, Iv, 44,  nullptr, nullptr, 0, 0,  nullptr, nullptr, 0, 0);
    gemm_h<<<dim3(44, 32), blk, SM>>>(ur, RFv, 2, gg,
        wts + W_UUS, ff, Iv, 44,  nullptr, nullptr, 0, 0,  nullptr, nullptr, 0, 0);

    gemm_h<<<dim3(8, 32), blk, SM>>>(ff, Iv, 0, nullptr,
        wts + W_DV, dr, RFv, 8,  nullptr, nullptr, 0, 0,  nullptr, nullptr, 0, 0);
    gemm_h<<<dim3(16, 32), blk, SM>>>(dr, RFv, 1, x1,
        wts + W_DUS, out, Dv, 16,  nullptr, nullptr, 0, 0,  nullptr, nullptr, 0, 0);
}

// round 13
// speedup vs baseline: 3.3337x; 1.0021x over previous
#include <cuda_runtime.h>
#include <cuda_fp16.h>
#include <math.h>

// ---------------- problem constants ----------------
#define Bv   4
#define Tv   1024
#define Dv   2048
#define Hv   32
#define DHv  64
#define HKv  8
#define Rv   32
#define ROv  1024
#define RFv  1024
#define Iv   5632
#define BT   (Bv*Tv)     // 4096

// ---------------- scratch ----------------
__device__ __half g_h1 [BT*Dv];
__device__ __half g_qr [BT*(Hv*Rv)];
__device__ __half g_kr [BT*(HKv*Rv)];
__device__ __half g_vr [BT*(HKv*Rv)];
__device__ __half g_q  [Bv*Hv*Tv*DHv];
__device__ __half g_k  [Bv*HKv*Tv*DHv];
__device__ __half g_v  [Bv*HKv*Tv*DHv];
__device__ __half g_ctx[BT*Dv];
__device__ __half g_or [BT*ROv];
__device__ float  g_x1 [BT*Dv];
__device__ __half g_h2 [BT*Dv];
__device__ __half g_gr [BT*RFv];
__device__ __half g_ur [BT*RFv];
__device__ __half g_g  [BT*Iv];
__device__ __half g_ff [BT*Iv];
__device__ __half g_dr [BT*RFv];
__device__ float  g_ropec[Tv*32];
__device__ float  g_ropes[Tv*32];
// converted (half) weights, concatenated; offsets in elements
#define W_QV   0
#define W_KV   2097152
#define W_VV   2621440
#define W_OV   3145728
#define W_OUS  5242880
#define W_GV   7340032
#define W_UV   9437184
#define W_GUS  11534336
#define W_UUS  17301504
#define W_DV   23068672
#define W_DUS  28835840
#define W_TOT  30932992
#define NW1BLK (W_OV/4096)              // 768 qkv-weight blocks
#define NW2BLK ((W_TOT-W_OV)/4096)      // 6784 mlp/o-weight blocks
__device__ __half g_wts[W_TOT];

// ---------------- helpers ----------------
__device__ __forceinline__ uint2 pack4h(float4 v) {
    __half2 a = __floats2half2_rn(v.x, v.y);
    __half2 b = __floats2half2_rn(v.z, v.w);
    uint2 r;
    r.x = *(unsigned*)&a;
    r.y = *(unsigned*)&b;
    return r;
}
__device__ __forceinline__ float ex2f(float x) {
    float r;
    asm("ex2.approx.ftz.f32 %0, %1;" : "=f"(r) : "f"(x));
    return r;
}
#define LOG2E 1.4426950408889634f

// ---------------- prep part 1: QKV weights + rms1 + rope table ----------------
__global__ void __launch_bounds__(256) prep_qkv(
    __half* __restrict__ dst,
    const float* __restrict__ s0, const float* __restrict__ s1, const float* __restrict__ s2,
    const float* __restrict__ x, const float* __restrict__ ln1_w, __half* __restrict__ h1,
    float* __restrict__ rc, float* __restrict__ rs)
{
    int bx = blockIdx.x;
    int tid = threadIdx.x;
    if (bx < NW1BLK) {
        long i = ((long)bx * 256 + tid) * 16;
        const float* src; long base;
        if (i < W_KV)      { src = s0; base = W_QV; }
        else if (i < W_VV) { src = s1; base = W_KV; }
        else               { src = s2; base = W_VV; }
        const float4* sp = (const float4*)(src + (i - base));
        float4 v0 = sp[0], v1 = sp[1], v2 = sp[2], v3 = sp[3];
        uint2 p0 = pack4h(v0), p1 = pack4h(v1), p2 = pack4h(v2), p3 = pack4h(v3);
        uint4 o0 = { p0.x, p0.y, p1.x, p1.y };
        uint4 o1 = { p2.x, p2.y, p3.x, p3.y };
        *(uint4*)(dst + i)     = o0;
        *(uint4*)(dst + i + 8) = o1;
    } else if (bx < NW1BLK + BT) {
        int row = bx - NW1BLK;
        const float4* xr = (const float4*)(x + (size_t)row * Dv);
        float4 v0 = xr[tid];
        float4 v1 = xr[tid + 256];
        float ss = v0.x*v0.x + v0.y*v0.y + v0.z*v0.z + v0.w*v0.w
                 + v1.x*v1.x + v1.y*v1.y + v1.z*v1.z + v1.w*v1.w;
        #pragma unroll
        for (int o = 16; o; o >>= 1) ss += __shfl_xor_sync(0xffffffffu, ss, o);
        __shared__ float red[8];
        if ((tid & 31) == 0) red[tid >> 5] = ss;
        __syncthreads();
        float tot = 0.f;
        #pragma unroll
        for (int i = 0; i < 8; i++) tot += red[i];
        float inv = rsqrtf(tot * (1.0f / Dv) + 1e-5f);
        const float4* wr = (const float4*)ln1_w;
        float4 w0 = wr[tid], w1 = wr[tid + 256];
        float4 o0 = { v0.x*inv*w0.x, v0.y*inv*w0.y, v0.z*inv*w0.z, v0.w*inv*w0.w };
        float4 o1 = { v1.x*inv*w1.x, v1.y*inv*w1.y, v1.z*inv*w1.z, v1.w*inv*w1.w };
        __half* orow = h1 + (size_t)row * Dv;
        *(uint2*)(orow + tid * 4)         = pack4h(o0);
        *(uint2*)(orow + (tid + 256) * 4) = pack4h(o1);
    } else {
        int idx = (bx - NW1BLK - BT) * 256 + tid;
        int t = idx >> 5, d = idx & 31;
        float invf = expf(-0.28782313662425572f * (float)d);
        float ang = (float)t * invf;
        rc[idx] = cosf(ang);
        rs[idx] = sinf(ang);
    }
}

// ---------------- prep part 2: O/G/U/D weights (runs on side stream) ----------------
__global__ void __launch_bounds__(256) prep_mlp(
    __half* __restrict__ dst,
    const float* __restrict__ s3, const float* __restrict__ s4, const float* __restrict__ s5,
    const float* __restrict__ s6, const float* __restrict__ s7, const float* __restrict__ s8,
    const float* __restrict__ s9, const float* __restrict__ s10)
{
    long i = W_OV + ((long)blockIdx.x * 256 + threadIdx.x) * 16;
    const float* src; long base;
    if (i < W_GUS) {
        if (i < W_OUS)       { src = s3; base = W_OV; }
        else if (i < W_GV)   { src = s4; base = W_OUS; }
        else if (i < W_UV)   { src = s5; base = W_GV; }
        else                 { src = s6; base = W_UV; }
    } else {
        if (i < W_UUS)       { src = s7; base = W_GUS; }
        else if (i < W_DV)   { src = s8; base = W_UUS; }
        else if (i < W_DUS)  { src = s9; base = W_DV; }
        else                 { src = s10; base = W_DUS; }
    }
    const float4* sp = (const float4*)(src + (i - base));
    float4 v0 = sp[0], v1 = sp[1], v2 = sp[2], v3 = sp[3];
    uint2 p0 = pack4h(v0), p1 = pack4h(v1), p2 = pack4h(v2), p3 = pack4h(v3);
    uint4 o0 = { p0.x, p0.y, p1.x, p1.y };
    uint4 o1 = { p2.x, p2.y, p3.x, p3.y };
    *(uint4*)(dst + i)     = o0;
    *(uint4*)(dst + i + 8) = o1;
}

// ---------------- RMSNorm (fp32 in, fp16 out) ----------------
__global__ void __launch_bounds__(256) rms_kernel(const float* __restrict__ x,
                                                  const float* __restrict__ w,
                                                  __half* __restrict__ out)
{
    int row = blockIdx.x;
    int tid = threadIdx.x;
    const float4* xr = (const float4*)(x + (size_t)row * Dv);
    float4 v0 = xr[tid];
    float4 v1 = xr[tid + 256];
    float ss = v0.x*v0.x + v0.y*v0.y + v0.z*v0.z + v0.w*v0.w
             + v1.x*v1.x + v1.y*v1.y + v1.z*v1.z + v1.w*v1.w;
    #pragma unroll
    for (int o = 16; o; o >>= 1) ss += __shfl_xor_sync(0xffffffffu, ss, o);
    __shared__ float red[8];
    if ((tid & 31) == 0) red[tid >> 5] = ss;
    __syncthreads();
    float tot = 0.f;
    #pragma unroll
    for (int i = 0; i < 8; i++) tot += red[i];
    float inv = rsqrtf(tot * (1.0f / Dv) + 1e-5f);
    const float4* wr = (const float4*)w;
    float4 w0 = wr[tid], w1 = wr[tid + 256];
    float4 o0 = { v0.x*inv*w0.x, v0.y*inv*w0.y, v0.z*inv*w0.z, v0.w*inv*w0.w };
    float4 o1 = { v1.x*inv*w1.x, v1.y*inv*w1.y, v1.z*inv*w1.z, v1.w*inv*w1.w };
    __half* orow = out + (size_t)row * Dv;
    *(uint2*)(orow + tid * 4)         = pack4h(o0);
    *(uint2*)(orow + (tid + 256) * 4) = pack4h(o1);
}

// ---------------- fp16 tensor-core GEMM (3-stage, TBK=64, ldmatrix) ----------------
#define STAGES 3

#define CP_ASYNC16(dst, src) asm volatile("cp.async.cg.shared.global [%0], [%1], 16;\n" :: "r"(dst), "l"(src))
#define CP_COMMIT() asm volatile("cp.async.commit_group;\n" ::)
#define CP_WAIT(n)  asm volatile("cp.async.wait_group %0;\n" :: "n"(n))

#define LDSM4(r0, r1, r2, r3, addr) \
    asm volatile("ldmatrix.sync.aligned.m8n8.x4.shared.b16 {%0,%1,%2,%3}, [%4];" \
        : "=r"(r0), "=r"(r1), "=r"(r2), "=r"(r3) : "r"(addr))

#define LDSM4T(r0, r1, r2, r3, addr) \
    asm volatile("ldmatrix.sync.aligned.m8n8.x4.trans.shared.b16 {%0,%1,%2,%3}, [%4];" \
        : "=r"(r0), "=r"(r1), "=r"(r2), "=r"(r3) : "r"(addr))

#define MMA_F16(d, a, b) \
    asm volatile("mma.sync.aligned.m16n8k16.row.col.f32.f16.f16.f32 " \
        "{%0,%1,%2,%3}, {%4,%5,%6,%7}, {%8,%9}, {%0,%1,%2,%3};" \
        : "+f"(d[0]), "+f"(d[1]), "+f"(d[2]), "+f"(d[3]) \
        : "r"(a[0]), "r"(a[1]), "r"(a[2]), "r"(a[3]), "r"(b[0]), "r"(b[1]))

__global__ void __launch_bounds__(256, 2) gemm_h(
    const __half* __restrict__ A, int K, int mode, const void* __restrict__ aux,
    const __half* __restrict__ B0, void* __restrict__ C0, int N0, int nb0,
    const __half* __restrict__ B1, void* __restrict__ C1, int N1, int nb1,
    const __half* __restrict__ B2, void* __restrict__ C2, int N2, int nb2)
{
    extern __shared__ __half smem[];
    unsigned sbase = (unsigned)__cvta_generic_to_shared(smem);

    int bx = blockIdx.x;
    const __half* Bw; void* C; int N; int bnb;
    if (bx < nb0)            { Bw = B0; C = C0; N = N0; bnb = bx; }
    else if (bx < nb0 + nb1) { Bw = B1; C = C1; N = N1; bnb = bx - nb0; }
    else                     { Bw = B2; C = C2; N = N2; bnb = bx - nb0 - nb1; }

    int tid  = threadIdx.x;
    int bm = blockIdx.y * 128;
    int bn = bnb * 128;
    int lane = tid & 31, warp = tid >> 5;
    int wm = warp >> 1, wn = warp & 1;
    int g  = lane >> 2, tig = lane & 3;

    unsigned dstoff[4];
    const __half* srcA[4];
    const __half* srcB[4];
    #pragma unroll
    for (int i = 0; i < 4; i++) {
        int lin = tid + i * 256;
        int row = lin >> 3, c = lin & 7;
        dstoff[i] = (unsigned)(row * 128 + ((c ^ (row & 7)) << 4));
        srcA[i] = A  + (size_t)(bm + row) * K + c * 8;
        srcB[i] = Bw + (size_t)(bn + row) * K + c * 8;
    }

    int t4 = lane >> 3;
    unsigned aoff[2][4], boff[4][4];
    #pragma unroll
    for (int mi = 0; mi < 2; mi++) {
        int row = wm * 32 + mi * 16 + (lane & 7) + (t4 & 1) * 8;
        #pragma unroll
        for (int ks = 0; ks < 4; ks++) {
            int chunk = 2 * ks + (t4 >> 1);
            aoff[mi][ks] = (unsigned)(row * 128 + ((chunk ^ (row & 7)) << 4));
        }
    }
    #pragma unroll
    for (int np = 0; np < 4; np++) {
        int row = wn * 64 + np * 16 + (lane & 7) + (t4 >> 1) * 8;
        #pragma unroll
        for (int ks = 0; ks < 4; ks++) {
            int chunk = 2 * ks + (t4 & 1);
            boff[np][ks] = (unsigned)(row * 128 + ((chunk ^ (row & 7)) << 4));
        }
    }

    float acc[2][8][4];
    #pragma unroll
    for (int mi = 0; mi < 2; mi++)
        #pragma unroll
        for (int ni = 0; ni < 8; ni++)
            #pragma unroll
            for (int q = 0; q < 4; q++) acc[mi][ni][q] = 0.f;

    const int NT = K >> 6;

    #pragma unroll
    for (int s = 0; s < STAGES - 1; s++) {
        unsigned da = sbase + (unsigned)s * 32768u;
        unsigned db = da + 16384u;
        #pragma unroll
        for (int i = 0; i < 4; i++) {
            CP_ASYNC16(da + dstoff[i], srcA[i] + (size_t)s * 64);
            CP_ASYNC16(db + dstoff[i], srcB[i] + (size_t)s * 64);
        }
        CP_COMMIT();
    }

    for (int kt = 0; kt < NT; kt++) {
        int st = kt % STAGES;
        CP_WAIT(STAGES - 2);
        __syncthreads();

        int pf = kt + STAGES - 1;
        if (pf < NT) {
            int pst = pf % STAGES;
            unsigned da = sbase + (unsigned)pst * 32768u;
            unsigned db = da + 16384u;
            #pragma unroll
            for (int i = 0; i < 4; i++) {
                CP_ASYNC16(da + dstoff[i], srcA[i] + (size_t)pf * 64);
                CP_ASYNC16(db + dstoff[i], srcB[i] + (size_t)pf * 64);
            }
        }
        CP_COMMIT();

        unsigned AsB = sbase + (unsigned)st * 32768u;
        unsigned BsB = AsB + 16384u;

        #pragma unroll
        for (int ks = 0; ks < 4; ks++) {
            unsigned af[2][4];
            LDSM4(af[0][0], af[0][1], af[0][2], af[0][3], AsB + aoff[0][ks]);
            LDSM4(af[1][0], af[1][1], af[1][2], af[1][3], AsB + aoff[1][ks]);
            unsigned bf[8][2];
            #pragma unroll
            for (int np = 0; np < 4; np++)
                LDSM4(bf[2*np][0], bf[2*np][1], bf[2*np+1][0], bf[2*np+1][1],
                      BsB + boff[np][ks]);
            #pragma unroll
            for (int mi = 0; mi < 2; mi++)
                #pragma unroll
                for (int ni = 0; ni < 8; ni++)
                    MMA_F16(acc[mi][ni], af[mi], bf[ni]);
        }
    }

    #pragma unroll
    for (int mi = 0; mi < 2; mi++) {
        int row0 = bm + wm * 32 + mi * 16 + g;
        #pragma unroll
        for (int half = 0; half < 2; half++) {
            int row = row0 + half * 8;
            size_t rowoff = (size_t)row * N;
            #pragma unroll
            for (int ni = 0; ni < 8; ni++) {
                int col = bn + wn * 64 + ni * 8 + 2 * tig;
                size_t idx = rowoff + col;
                float vx = acc[mi][ni][half * 2 + 0];
                float vy = acc[mi][ni][half * 2 + 1];
                if (mode == 1) {
                    float2 rsd = *(const float2*)((const float*)aux + idx);
                    vx += rsd.x; vy += rsd.y;
                    float2 o = { vx, vy };
                    *(float2*)((float*)C + idx) = o;
                } else {
                    if (mode == 2) {
                        __half2 gh = *(const __half2*)((const __half*)aux + idx);
                        float2 gf = __half22float2(gh);
                        vx *= gf.x / (1.f + __expf(-gf.x));
                        vy *= gf.y / (1.f + __expf(-gf.y));
                    }
                    __half2 o = __floats2half2_rn(vx, vy);
                    *(__half2*)((__half*)C + idx) = o;
                }
            }
        }
    }
}

// ---------------- fused per-head Us projection (+ RoPE); half out; q pre-scaled ----------------
__global__ void __launch_bounds__(256) usproj_fused(
    const __half* __restrict__ qr, const __half* __restrict__ kr, const __half* __restrict__ vr,
    const float* __restrict__ qUs, const float* __restrict__ kUs, const float* __restrict__ vUs,
    __half* __restrict__ qb, __half* __restrict__ kb, __half* __restrict__ vb,
    const float* __restrict__ rc, const float* __restrict__ rs)
{
    __shared__ __align__(16) float inT[32][64];
    __shared__ __align__(16) float UsT[32][64];
    __shared__ __align__(16) float os [64][64];
    int y = blockIdx.y;
    const __half* in; const float* Us; __half* out; int heads, h, rope;
    float osc = 1.0f;
    if (y < 32)      { in = qr; Us = qUs; out = qb; heads = 32; h = y;      rope = 1; osc = 0.125f * LOG2E; }
    else if (y < 40) { in = kr; Us = kUs; out = kb; heads = 8;  h = y - 32; rope = 1; }
    else             { in = vr; Us = vUs; out = vb; heads = 8;  h = y - 40; rope = 0; }

    int bt0 = blockIdx.x * 64;
    int tid = threadIdx.x;
    int ldin = heads * 32;

    {
        int d = tid >> 2; int r0 = (tid & 3) * 8;
        const float* p = Us + ((size_t)h * 64 + d) * 32 + r0;
        float4 u0 = *(const float4*)p;
        float4 u1 = *(const float4*)(p + 4);
        UsT[r0+0][d]=u0.x; UsT[r0+1][d]=u0.y; UsT[r0+2][d]=u0.z; UsT[r0+3][d]=u0.w;
        UsT[r0+4][d]=u1.x; UsT[r0+5][d]=u1.y; UsT[r0+6][d]=u1.z; UsT[r0+7][d]=u1.w;
    }
    {
        int i = tid >> 2; int r0 = (tid & 3) * 8;
        const __half* p = in + (size_t)(bt0 + i) * ldin + h * 32 + r0;
        uint4 u = *(const uint4*)p;
        float2 f0 = __half22float2(*(__half2*)&u.x);
        float2 f1 = __half22float2(*(__half2*)&u.y);
        float2 f2 = __half22float2(*(__half2*)&u.z);
        float2 f3 = __half22float2(*(__half2*)&u.w);
        inT[r0+0][i]=f0.x; inT[r0+1][i]=f0.y; inT[r0+2][i]=f1.x; inT[r0+3][i]=f1.y;
        inT[r0+4][i]=f2.x; inT[r0+5][i]=f2.y; inT[r0+6][i]=f3.x; inT[r0+7][i]=f3.y;
    }
    __syncthreads();

    int tx = tid & 15, ty = tid >> 4;
    float acc[4][4] = {};
    #pragma unroll
    for (int r = 0; r < 32; r++) {
        float4 a = *(const float4*)&inT[r][ty*4];
        float4 b = *(const float4*)&UsT[r][tx*4];
        float av[4] = {a.x,a.y,a.z,a.w};
        float bv[4] = {b.x,b.y,b.z,b.w};
        #pragma unroll
        for (int rr = 0; rr < 4; rr++)
            #pragma unroll
            for (int cc = 0; cc < 4; cc++)
                acc[rr][cc] = fmaf(av[rr], bv[cc], acc[rr][cc]);
    }
    #pragma unroll
    for (int rr = 0; rr < 4; rr++)
        #pragma unroll
        for (int cc = 0; cc < 4; cc++)
            os[ty*4+rr][tx*4+cc] = acc[rr][cc];
    __syncthreads();

    if (!rope) {
        #pragma unroll
        for (int kk = 0; kk < 4; kk++) {
            int lin4 = tid + kk * 256;
            int i = lin4 >> 4; int d0 = (lin4 & 15) * 4;
            int bt = bt0 + i; int b = bt >> 10; int t = bt & 1023;
            float4 vv = *(const float4*)&os[i][d0];
            size_t addr = (((size_t)(b * heads + h)) * Tv + t) * 64 + d0;
            *(uint2*)(out + addr) = pack4h(vv);
        }
    } else {
        #pragma unroll
        for (int kk = 0; kk < 2; kk++) {
            int lin4 = tid + kk * 256;
            int i = lin4 >> 3; int d0 = (lin4 & 7) * 4;
            int bt = bt0 + i; int b = bt >> 10; int t = bt & 1023;
            float4 x1 = *(const float4*)&os[i][d0];
            float4 x2 = *(const float4*)&os[i][d0 + 32];
            float4 cc4 = *(const float4*)(rc + t * 32 + d0);
            float4 ss4 = *(const float4*)(rs + t * 32 + d0);
            float xx1[4] = {x1.x,x1.y,x1.z,x1.w};
            float xx2[4] = {x2.x,x2.y,x2.z,x2.w};
            float ca[4] = {cc4.x,cc4.y,cc4.z,cc4.w};
            float sa[4] = {ss4.x,ss4.y,ss4.z,ss4.w};
            float4 w1, w2;
            float* o1 = &w1.x; float* o2 = &w2.x;
            #pragma unroll
            for (int c = 0; c < 4; c++) {
                o1[c] = (xx1[c] * ca[c] - xx2[c] * sa[c]) * osc;
                o2[c] = (xx2[c] * ca[c] + xx1[c] * sa[c]) * osc;
            }
            size_t base = (((size_t)(b * heads + h)) * Tv + t) * 64;
            *(uint2*)(out + base + d0)      = pack4h(w1);
            *(uint2*)(out + base + d0 + 32) = pack4h(w2);
        }
    }
}

// ---------------- flash attention, fp16 MMA, in-register softmax (base-2), double-buffered KV ----------------
#define ATTN_SMEM 40960
__global__ void __launch_bounds__(256, 2) attn_kernel(const __half* __restrict__ q,
                                                      const __half* __restrict__ k,
                                                      const __half* __restrict__ v,
                                                      __half* __restrict__ ctx)
{
    extern __shared__ char asmem[];
    __shared__ float mrow[64], lrow[64];
    __shared__ float pmax[128], psum[128];

    unsigned sb  = (unsigned)__cvta_generic_to_shared(asmem);
    unsigned QsB = sb;

    int tid = threadIdx.x;
    int bh = blockIdx.y; int b = bh >> 5; int h = bh & 31; int hk = h >> 2;
    int q0 = blockIdx.x * 64;
    int lane = tid & 31, warp = tid >> 5;
    int g = lane >> 2, tig = lane & 3;
    int t4 = lane >> 3;
    int wq = warp >> 1;
    int wn = warp & 1;

    const __half* kb0 = k + ((size_t)(b * 8 + hk)) * Tv * 64;
    const __half* vb0 = v + ((size_t)(b * 8 + hk)) * Tv * 64;

    int cprow[2], cpc[2];
    unsigned cpoff[2];
    #pragma unroll
    for (int kk = 0; kk < 2; kk++) {
        int lin = tid + kk * 256;
        cprow[kk] = lin >> 3; cpc[kk] = lin & 7;
        cpoff[kk] = (unsigned)(cprow[kk] * 128 + ((cpc[kk] ^ (cprow[kk] & 7)) << 4));
    }

    {
        unsigned kbB = sb + 8192u, vbB = sb + 16384u;
        #pragma unroll
        for (int kk = 0; kk < 2; kk++) {
            size_t off = ((size_t)cprow[kk]) * 64 + cpc[kk] * 8;
            CP_ASYNC16(kbB + cpoff[kk], kb0 + off);
            CP_ASYNC16(vbB + cpoff[kk], vb0 + off);
        }
        CP_COMMIT();
    }

    const __half* qbase = q + (((size_t)(b * 32 + h)) * Tv + q0) * 64;
    #pragma unroll
    for (int kk = 0; kk < 2; kk++) {
        int lin = tid + kk * 256;
        int row = lin >> 3, c = lin & 7;
        uint4 u = *(const uint4*)(qbase + (size_t)row * 64 + c * 8);
        *(uint4*)(asmem + row * 128 + ((c ^ (row & 7)) << 4)) = u;
    }
    if (tid < 64) { mrow[tid] = -INFINITY; lrow[tid] = 0.f; }

    unsigned aoffQ[4], boffK[2][4], voffV[2][4];
    {
        int rowA = wq * 16 + (lane & 7) + (t4 & 1) * 8;
        #pragma unroll
        for (int ks = 0; ks < 4; ks++) {
            int ca = 2 * ks + (t4 >> 1);
            aoffQ[ks] = (unsigned)(rowA * 128 + ((ca ^ (rowA & 7)) << 4));
        }
        #pragma unroll
        for (int nb = 0; nb < 2; nb++) {
            int rowB = wn * 32 + nb * 16 + (lane & 7) + (t4 >> 1) * 8;
            #pragma unroll
            for (int ks = 0; ks < 4; ks++) {
                int cb = 2 * ks + (t4 & 1);
                boffK[nb][ks] = (unsigned)(rowB * 128 + ((cb ^ (rowB & 7)) << 4));
            }
        }
        #pragma unroll
        for (int t = 0; t < 2; t++) {
            int rowV = wn * 32 + t * 16 + (lane & 7) + (t4 & 1) * 8;
            #pragma unroll
            for (int np = 0; np < 4; np++) {
                int cv = np * 2 + (t4 >> 1);
                voffV[t][np] = (unsigned)(rowV * 128 + ((cv ^ (rowV & 7)) << 4));
            }
        }
    }

    int r0 = wq * 16 + g, r1 = r0 + 8;
    float cacc[8][4];
    #pragma unroll
    for (int ni = 0; ni < 8; ni++)
        #pragma unroll
        for (int c = 0; c < 4; c++) cacc[ni][c] = 0.f;

    int ntile = (q0 >> 6) + 1;
    for (int kt = 0; kt < ntile; kt++) {
        int buf = kt & 1;
        CP_WAIT(0);
        __syncthreads();

        if (kt + 1 < ntile) {
            unsigned kbB = sb + 8192u + (unsigned)(buf ^ 1) * 16384u;
            unsigned vbB = kbB + 8192u;
            #pragma unroll
            for (int kk = 0; kk < 2; kk++) {
                size_t off = ((size_t)((kt + 1) * 64 + cprow[kk])) * 64 + cpc[kk] * 8;
                CP_ASYNC16(kbB + cpoff[kk], kb0 + off);
                CP_ASYNC16(vbB + cpoff[kk], vb0 + off);
            }
            CP_COMMIT();
        }

        unsigned KsB = sb + 8192u + (unsigned)buf * 16384u;
        unsigned VsB = KsB + 8192u;

        float sacc[4][4] = {};
        #pragma unroll
        for (int ks = 0; ks < 4; ks++) {
            unsigned af[4];
            LDSM4(af[0], af[1], af[2], af[3], QsB + aoffQ[ks]);
            #pragma unroll
            for (int nb = 0; nb < 2; nb++) {
                unsigned bf[4];
                LDSM4(bf[0], bf[1], bf[2], bf[3], KsB + boffK[nb][ks]);
                unsigned b0[2] = { bf[0], bf[1] };
                unsigned b1[2] = { bf[2], bf[3] };
                MMA_F16(sacc[nb*2 + 0], af, b0);
                MMA_F16(sacc[nb*2 + 1], af, b1);
            }
        }

        if (kt == ntile - 1) {
            int qi0 = q0 + r0, qi1 = q0 + r1;
            #pragma unroll
            for (int ni = 0; ni < 4; ni++) {
                int kc = kt * 64 + wn * 32 + ni * 8 + 2 * tig;
                if (kc > qi0)     sacc[ni][0] = -INFINITY;
                if (kc + 1 > qi0) sacc[ni][1] = -INFINITY;
                if (kc > qi1)     sacc[ni][2] = -INFINITY;
                if (kc + 1 > qi1) sacc[ni][3] = -INFINITY;
            }
        }

        float pm0 = -INFINITY, pm1 = -INFINITY;
        #pragma unroll
        for (int ni = 0; ni < 4; ni++) {
            pm0 = fmaxf(pm0, fmaxf(sacc[ni][0], sacc[ni][1]));
            pm1 = fmaxf(pm1, fmaxf(sacc[ni][2], sacc[ni][3]));
        }
        pm0 = fmaxf(pm0, __shfl_xor_sync(0xffffffffu, pm0, 1));
        pm0 = fmaxf(pm0, __shfl_xor_sync(0xffffffffu, pm0, 2));
        pm1 = fmaxf(pm1, __shfl_xor_sync(0xffffffffu, pm1, 1));
        pm1 = fmaxf(pm1, __shfl_xor_sync(0xffffffffu, pm1, 2));
        if (tig == 0) { pmax[wn * 64 + r0] = pm0; pmax[wn * 64 + r1] = pm1; }
        __syncthreads();

        float mo0 = mrow[r0], mo1 = mrow[r1];
        float mx0 = fmaxf(mo0, fmaxf(pmax[r0], pmax[64 + r0]));
        float mx1 = fmaxf(mo1, fmaxf(pmax[r1], pmax[64 + r1]));
        float rsc0 = ex2f(mo0 - mx0);
        float rsc1 = ex2f(mo1 - mx1);

        unsigned pf[4][2];
        float s0 = 0.f, s1 = 0.f;
        #pragma unroll
        for (int ni = 0; ni < 4; ni++) {
            float p0 = ex2f(sacc[ni][0] - mx0);
            float p1 = ex2f(sacc[ni][1] - mx0);
            float p2 = ex2f(sacc[ni][2] - mx1);
            float p3 = ex2f(sacc[ni][3] - mx1);
            s0 += p0 + p1; s1 += p2 + p3;
            __half2 h01 = __floats2half2_rn(p0, p1);
            __half2 h23 = __floats2half2_rn(p2, p3);
            pf[ni][0] = *(unsigned*)&h01;
            pf[ni][1] = *(unsigned*)&h23;
        }
        s0 += __shfl_xor_sync(0xffffffffu, s0, 1);
        s0 += __shfl_xor_sync(0xffffffffu, s0, 2);
        s1 += __shfl_xor_sync(0xffffffffu, s1, 1);
        s1 += __shfl_xor_sync(0xffffffffu, s1, 2);
        if (tig == 0) { psum[wn * 64 + r0] = s0; psum[wn * 64 + r1] = s1; }

        #pragma unroll
        for (int ni = 0; ni < 8; ni++) {
            cacc[ni][0] *= rsc0; cacc[ni][1] *= rsc0;
            cacc[ni][2] *= rsc1; cacc[ni][3] *= rsc1;
        }

        #pragma unroll
        for (int t = 0; t < 2; t++) {
            unsigned af[4] = { pf[2*t][0], pf[2*t][1], pf[2*t+1][0], pf[2*t+1][1] };
            #pragma unroll
            for (int np = 0; np < 4; np++) {
                unsigned vf[4];
                LDSM4T(vf[0], vf[1], vf[2], vf[3], VsB + voffV[t][np]);
                unsigned b0[2] = { vf[0], vf[1] };
                unsigned b1[2] = { vf[2], vf[3] };
                MMA_F16(cacc[np*2 + 0], af, b0);
                MMA_F16(cacc[np*2 + 1], af, b1);
            }
        }
        __syncthreads();

        if (wn == 0 && tig == 0) {
            lrow[r0] = lrow[r0] * rsc0 + psum[r0] + psum[64 + r0];
            lrow[r1] = lrow[r1] * rsc1 + psum[r1] + psum[64 + r1];
            mrow[r0] = mx0;
            mrow[r1] = mx1;
        }
    }
    __syncthreads();

    float* Ored = (float*)asmem;
    if (wn == 1) {
        #pragma unroll
        for (int ni = 0; ni < 8; ni++) {
            int col = ni * 8 + 2 * tig;
            *(float2*)(Ored + r0 * 68 + col) = make_float2(cacc[ni][0], cacc[ni][1]);
            *(float2*)(Ored + r1 * 68 + col) = make_float2(cacc[ni][2], cacc[ni][3]);
        }
    }
    __syncthreads();
    if (wn == 0) {
        float inv0 = 1.f / lrow[r0];
        float inv1 = 1.f / lrow[r1];
        #pragma unroll
        for (int ni = 0; ni < 8; ni++) {
            int col = ni * 8 + 2 * tig;
            float2 a0 = *(float2*)(Ored + r0 * 68 + col);
            float2 a1 = *(float2*)(Ored + r1 * 68 + col);
            __half2 o0 = __floats2half2_rn((cacc[ni][0] + a0.x) * inv0,
                                           (cacc[ni][1] + a0.y) * inv0);
            __half2 o1 = __floats2half2_rn((cacc[ni][2] + a1.x) * inv1,
                                           (cacc[ni][3] + a1.y) * inv1);
            size_t ad0 = ((size_t)(b * Tv + q0 + r0)) * Dv + h * 64 + col;
            size_t ad1 = ((size_t)(b * Tv + q0 + r1)) * Dv + h * 64 + col;
            *(__half2*)(ctx + ad0) = o0;
            *(__half2*)(ctx + ad1) = o1;
        }
    }
}

// ---------------- launch ----------------
extern "C" void kernel_launch(void* const* d_in, const int* in_sizes, int n_in,
                              void* d_out, int out_size)
{
    const float* x     = (const float*)d_in[0];
    const float* ln1_w = (const float*)d_in[1];
    const float* ln2_w = (const float*)d_in[2];
    const float* q_Us  = (const float*)d_in[3];
    const float* q_V   = (const float*)d_in[4];
    const float* k_Us  = (const float*)d_in[5];
    const float* k_V   = (const float*)d_in[6];
    const float* v_Us  = (const float*)d_in[7];
    const float* v_V   = (const float*)d_in[8];
    const float* o_Us  = (const float*)d_in[9];
    const float* o_V   = (const float*)d_in[10];
    const float* g_Usw = (const float*)d_in[11];
    const float* g_Vw  = (const float*)d_in[12];
    const float* u_Usw = (const float*)d_in[13];
    const float* u_Vw  = (const float*)d_in[14];
    const float* d_Usw = (const float*)d_in[15];
    const float* d_Vw  = (const float*)d_in[16];
    float* out = (float*)d_out;

    __half *h1, *qr, *kr, *vr, *qb, *kb, *vb, *ctx, *orr, *h2, *gr, *ur, *gg, *ff, *dr, *wts;
    float *x1, *rc, *rs;
    cudaGetSymbolAddress((void**)&h1,  g_h1);
    cudaGetSymbolAddress((void**)&qr,  g_qr);
    cudaGetSymbolAddress((void**)&kr,  g_kr);
    cudaGetSymbolAddress((void**)&vr,  g_vr);
    cudaGetSymbolAddress((void**)&qb,  g_q);
    cudaGetSymbolAddress((void**)&kb,  g_k);
    cudaGetSymbolAddress((void**)&vb,  g_v);
    cudaGetSymbolAddress((void**)&ctx, g_ctx);
    cudaGetSymbolAddress((void**)&orr, g_or);
    cudaGetSymbolAddress((void**)&x1,  g_x1);
    cudaGetSymbolAddress((void**)&h2,  g_h2);
    cudaGetSymbolAddress((void**)&gr,  g_gr);
    cudaGetSymbolAddress((void**)&ur,  g_ur);
    cudaGetSymbolAddress((void**)&gg,  g_g);
    cudaGetSymbolAddress((void**)&ff,  g_ff);
    cudaGetSymbolAddress((void**)&dr,  g_dr);
    cudaGetSymbolAddress((void**)&rc,  g_ropec);
    cudaGetSymbolAddress((void**)&rs,  g_ropes);
    cudaGetSymbolAddress((void**)&wts, g_wts);

    static cudaStream_t s2 = 0;
    static cudaEvent_t evFork = 0, evJoin = 0;
    static int init_done = 0;
    if (!init_done) {
        cudaFuncSetAttribute(gemm_h, cudaFuncAttributeMaxDynamicSharedMemorySize, 98304);
        cudaFuncSetAttribute(attn_kernel, cudaFuncAttributeMaxDynamicSharedMemorySize, ATTN_SMEM);
        cudaStreamCreateWithFlags(&s2, cudaStreamNonBlocking);
        cudaEventCreateWithFlags(&evFork, cudaEventDisableTiming);
        cudaEventCreateWithFlags(&evJoin, cudaEventDisableTiming);
        init_done = 1;
    }
    const int SM = 98304;
    dim3 blk(256);

    // fork: MLP/O weight conversion runs on side stream, overlapped with attention phase
    cudaEventRecord(evFork, 0);
    cudaStreamWaitEvent(s2, evFork, 0);
    prep_mlp<<<NW2BLK, blk, 0, s2>>>(wts, o_V, o_Us, g_Vw, u_Vw, g_Usw, u_Usw, d_Vw, d_Usw);
    cudaEventRecord(evJoin, s2);

    // main stream: QKV weights + rms1 + rope, then attention pipeline
    prep_qkv<<<NW1BLK + BT + Tv*32/256, blk>>>(wts, q_V, k_V, v_V, x, ln1_w, h1, rc, rs);

    gemm_h<<<dim3(12, 32), blk, SM>>>(h1, Dv, 0, nullptr,
        wts + W_QV, qr, Hv*Rv, 8,  wts + W_KV, kr, HKv*Rv, 2,  wts + W_VV, vr, HKv*Rv, 2);

    usproj_fused<<<dim3(BT/64, 48), blk>>>(qr, kr, vr, q_Us, k_Us, v_Us, qb, kb, vb, rc, rs);

    attn_kernel<<<dim3(Tv/64, Bv*Hv), blk, ATTN_SMEM>>>(qb, kb, vb, ctx);

    // join: O/MLP weights must be converted from here on
    cudaStreamWaitEvent(0, evJoin, 0);

    gemm_h<<<dim3(8, 32), blk, SM>>>(ctx, Dv, 0, nullptr,
        wts + W_OV, orr, ROv, 8,  nullptr, nullptr, 0, 0,  nullptr, nullptr, 0, 0);
    gemm_h<<<dim3(16, 32), blk, SM>>>(orr, ROv, 1, x,
        wts + W_OUS, x1, Dv, 16,  nullptr, nullptr, 0, 0,  nullptr, nullptr, 0, 0);

    rms_kernel<<<BT, blk>>>(x1, ln2_w, h2);

    gemm_h<<<dim3(16, 32), blk, SM>>>(h2, Dv, 0, nullptr,
        wts + W_GV, gr, RFv, 8,  wts + W_UV, ur, RFv, 8,  nullptr, nullptr, 0, 0);

    gemm_h<<<dim3(44, 32), blk, SM>>>(gr, RFv, 0, nullptr,
        wts + W_GUS, gg, Iv, 44,  nullptr, nullptr, 0, 0,  nullptr, nullptr, 0, 0);
    gemm_h<<<dim3(44, 32), blk, SM>>>(ur, RFv, 2, gg,
        wts + W_UUS, ff, Iv, 44,  nullptr, nullptr, 0, 0,  nullptr, nullptr, 0, 0);

    gemm_h<<<dim3(8, 32), blk, SM>>>(ff, Iv, 0, nullptr,
        wts + W_DV, dr, RFv, 8,  nullptr, nullptr, 0, 0,  nullptr, nullptr, 0, 0);
    gemm_h<<<dim3(16, 32), blk, SM>>>(dr, RFv, 1, x1,
        wts + W_DUS, out, Dv, 16,  nullptr, nullptr, 0, 0,  nullptr, nullptr, 0, 0);
}

// round 14
// speedup vs baseline: 3.3763x; 1.0128x over previous
#include <cuda_runtime.h>
#include <cuda_fp16.h>
#include <math.h>

// ---------------- problem constants ----------------
#define Bv   4
#define Tv   1024
#define Dv   2048
#define Hv   32
#define DHv  64
#define HKv  8
#define Rv   32
#define ROv  1024
#define RFv  1024
#define Iv   5632
#define BT   (Bv*Tv)     // 4096

// ---------------- scratch ----------------
__device__ __half g_h1 [BT*Dv];
__device__ __half g_qr [BT*(Hv*Rv)];
__device__ __half g_kr [BT*(HKv*Rv)];
__device__ __half g_vr [BT*(HKv*Rv)];
__device__ __half g_q  [Bv*Hv*Tv*DHv];
__device__ __half g_k  [Bv*HKv*Tv*DHv];
__device__ __half g_v  [Bv*HKv*Tv*DHv];
__device__ __half g_ctx[BT*Dv];
__device__ __half g_or [BT*ROv];
__device__ float  g_x1 [BT*Dv];
__device__ __half g_h2 [BT*Dv];
__device__ __half g_gr [BT*RFv];
__device__ __half g_ur [BT*RFv];
__device__ __half g_g  [BT*Iv];
__device__ __half g_ff [BT*Iv];
__device__ __half g_dr [BT*RFv];
__device__ float  g_ropec[Tv*32];
__device__ float  g_ropes[Tv*32];
__device__ __half g_qush[Hv*DHv*Rv];    // 65536
__device__ __half g_kush[HKv*DHv*Rv];   // 16384
__device__ __half g_vush[HKv*DHv*Rv];   // 16384
// converted (half) weights, concatenated; offsets in elements
#define W_QV   0
#define W_KV   2097152
#define W_VV   2621440
#define W_OV   3145728
#define W_OUS  5242880
#define W_GV   7340032
#define W_UV   9437184
#define W_GUS  11534336
#define W_UUS  17301504
#define W_DV   23068672
#define W_DUS  28835840
#define W_TOT  30932992
#define NW1BLK (W_OV/4096)              // 768 qkv-weight blocks
#define NW2BLK ((W_TOT-W_OV)/4096)      // 6784 mlp/o-weight blocks
#define NROPE  (Tv*32/256)              // 128
#define NQUS   (Hv*DHv*Rv/4096)         // 16
#define NKUS   (HKv*DHv*Rv/4096)        // 4
__device__ __half g_wts[W_TOT];

// ---------------- helpers ----------------
__device__ __forceinline__ uint2 pack4h(float4 v) {
    __half2 a = __floats2half2_rn(v.x, v.y);
    __half2 b = __floats2half2_rn(v.z, v.w);
    uint2 r;
    r.x = *(unsigned*)&a;
    r.y = *(unsigned*)&b;
    return r;
}
__device__ __forceinline__ float ex2f(float x) {
    float r;
    asm("ex2.approx.ftz.f32 %0, %1;" : "=f"(r) : "f"(x));
    return r;
}
#define LOG2E 1.4426950408889634f

// ---------------- prep part 1: QKV weights + rms1 + rope table + Us->half ----------------
__global__ void __launch_bounds__(256) prep_qkv(
    __half* __restrict__ dst,
    const float* __restrict__ s0, const float* __restrict__ s1, const float* __restrict__ s2,
    const float* __restrict__ x, const float* __restrict__ ln1_w, __half* __restrict__ h1,
    float* __restrict__ rc, float* __restrict__ rs,
    const float* __restrict__ qUs, const float* __restrict__ kUs, const float* __restrict__ vUs,
    __half* __restrict__ qUh, __half* __restrict__ kUh, __half* __restrict__ vUh)
{
    int bx = blockIdx.x;
    int tid = threadIdx.x;
    if (bx < NW1BLK) {
        long i = ((long)bx * 256 + tid) * 16;
        const float* src; long base;
        if (i < W_KV)      { src = s0; base = W_QV; }
        else if (i < W_VV) { src = s1; base = W_KV; }
        else               { src = s2; base = W_VV; }
        const float4* sp = (const float4*)(src + (i - base));
        float4 v0 = sp[0], v1 = sp[1], v2 = sp[2], v3 = sp[3];
        uint2 p0 = pack4h(v0), p1 = pack4h(v1), p2 = pack4h(v2), p3 = pack4h(v3);
        uint4 o0 = { p0.x, p0.y, p1.x, p1.y };
        uint4 o1 = { p2.x, p2.y, p3.x, p3.y };
        *(uint4*)(dst + i)     = o0;
        *(uint4*)(dst + i + 8) = o1;
    } else if (bx < NW1BLK + BT) {
        int row = bx - NW1BLK;
        const float4* xr = (const float4*)(x + (size_t)row * Dv);
        float4 v0 = xr[tid];
        float4 v1 = xr[tid + 256];
        float ss = v0.x*v0.x + v0.y*v0.y + v0.z*v0.z + v0.w*v0.w
                 + v1.x*v1.x + v1.y*v1.y + v1.z*v1.z + v1.w*v1.w;
        #pragma unroll
        for (int o = 16; o; o >>= 1) ss += __shfl_xor_sync(0xffffffffu, ss, o);
        __shared__ float red[8];
        if ((tid & 31) == 0) red[tid >> 5] = ss;
        __syncthreads();
        float tot = 0.f;
        #pragma unroll
        for (int i = 0; i < 8; i++) tot += red[i];
        float inv = rsqrtf(tot * (1.0f / Dv) + 1e-5f);
        const float4* wr = (const float4*)ln1_w;
        float4 w0 = wr[tid], w1 = wr[tid + 256];
        float4 o0 = { v0.x*inv*w0.x, v0.y*inv*w0.y, v0.z*inv*w0.z, v0.w*inv*w0.w };
        float4 o1 = { v1.x*inv*w1.x, v1.y*inv*w1.y, v1.z*inv*w1.z, v1.w*inv*w1.w };
        __half* orow = h1 + (size_t)row * Dv;
        *(uint2*)(orow + tid * 4)         = pack4h(o0);
        *(uint2*)(orow + (tid + 256) * 4) = pack4h(o1);
    } else if (bx < NW1BLK + BT + NROPE) {
        int idx = (bx - NW1BLK - BT) * 256 + tid;
        int t = idx >> 5, d = idx & 31;
        float invf = expf(-0.28782313662425572f * (float)d);
        float ang = (float)t * invf;
        rc[idx] = cosf(ang);
        rs[idx] = sinf(ang);
    } else {
        // Us fp32 -> fp16
        int ub = bx - NW1BLK - BT - NROPE;
        const float* src; __half* dh;
        long i;
        if (ub < NQUS)            { src = qUs; dh = qUh; i = ((long)ub * 256 + tid) * 16; }
        else if (ub < NQUS+NKUS)  { src = kUs; dh = kUh; i = ((long)(ub-NQUS) * 256 + tid) * 16; }
        else                      { src = vUs; dh = vUh; i = ((long)(ub-NQUS-NKUS) * 256 + tid) * 16; }
        const float4* sp = (const float4*)(src + i);
        float4 v0 = sp[0], v1 = sp[1], v2 = sp[2], v3 = sp[3];
        uint2 p0 = pack4h(v0), p1 = pack4h(v1), p2 = pack4h(v2), p3 = pack4h(v3);
        uint4 o0 = { p0.x, p0.y, p1.x, p1.y };
        uint4 o1 = { p2.x, p2.y, p3.x, p3.y };
        *(uint4*)(dh + i)     = o0;
        *(uint4*)(dh + i + 8) = o1;
    }
}

// ---------------- prep part 2: O/G/U/D weights (side stream) ----------------
__global__ void __launch_bounds__(256) prep_mlp(
    __half* __restrict__ dst,
    const float* __restrict__ s3, const float* __restrict__ s4, const float* __restrict__ s5,
    const float* __restrict__ s6, const float* __restrict__ s7, const float* __restrict__ s8,
    const float* __restrict__ s9, const float* __restrict__ s10)
{
    long i = W_OV + ((long)blockIdx.x * 256 + threadIdx.x) * 16;
    const float* src; long base;
    if (i < W_GUS) {
        if (i < W_OUS)       { src = s3; base = W_OV; }
        else if (i < W_GV)   { src = s4; base = W_OUS; }
        else if (i < W_UV)   { src = s5; base = W_GV; }
        else                 { src = s6; base = W_UV; }
    } else {
        if (i < W_UUS)       { src = s7; base = W_GUS; }
        else if (i < W_DV)   { src = s8; base = W_UUS; }
        else if (i < W_DUS)  { src = s9; base = W_DV; }
        else                 { src = s10; base = W_DUS; }
    }
    const float4* sp = (const float4*)(src + (i - base));
    float4 v0 = sp[0], v1 = sp[1], v2 = sp[2], v3 = sp[3];
    uint2 p0 = pack4h(v0), p1 = pack4h(v1), p2 = pack4h(v2), p3 = pack4h(v3);
    uint4 o0 = { p0.x, p0.y, p1.x, p1.y };
    uint4 o1 = { p2.x, p2.y, p3.x, p3.y };
    *(uint4*)(dst + i)     = o0;
    *(uint4*)(dst + i + 8) = o1;
}

// ---------------- RMSNorm (fp32 in, fp16 out) ----------------
__global__ void __launch_bounds__(256) rms_kernel(const float* __restrict__ x,
                                                  const float* __restrict__ w,
                                                  __half* __restrict__ out)
{
    int row = blockIdx.x;
    int tid = threadIdx.x;
    const float4* xr = (const float4*)(x + (size_t)row * Dv);
    float4 v0 = xr[tid];
    float4 v1 = xr[tid + 256];
    float ss = v0.x*v0.x + v0.y*v0.y + v0.z*v0.z + v0.w*v0.w
             + v1.x*v1.x + v1.y*v1.y + v1.z*v1.z + v1.w*v1.w;
    #pragma unroll
    for (int o = 16; o; o >>= 1) ss += __shfl_xor_sync(0xffffffffu, ss, o);
    __shared__ float red[8];
    if ((tid & 31) == 0) red[tid >> 5] = ss;
    __syncthreads();
    float tot = 0.f;
    #pragma unroll
    for (int i = 0; i < 8; i++) tot += red[i];
    float inv = rsqrtf(tot * (1.0f / Dv) + 1e-5f);
    const float4* wr = (const float4*)w;
    float4 w0 = wr[tid], w1 = wr[tid + 256];
    float4 o0 = { v0.x*inv*w0.x, v0.y*inv*w0.y, v0.z*inv*w0.z, v0.w*inv*w0.w };
    float4 o1 = { v1.x*inv*w1.x, v1.y*inv*w1.y, v1.z*inv*w1.z, v1.w*inv*w1.w };
    __half* orow = out + (size_t)row * Dv;
    *(uint2*)(orow + tid * 4)         = pack4h(o0);
    *(uint2*)(orow + (tid + 256) * 4) = pack4h(o1);
}

// ---------------- fp16 tensor-core GEMM (3-stage, TBK=64, ldmatrix) ----------------
#define STAGES 3

#define CP_ASYNC16(dst, src) asm volatile("cp.async.cg.shared.global [%0], [%1], 16;\n" :: "r"(dst), "l"(src))
#define CP_COMMIT() asm volatile("cp.async.commit_group;\n" ::)
#define CP_WAIT(n)  asm volatile("cp.async.wait_group %0;\n" :: "n"(n))

#define LDSM4(r0, r1, r2, r3, addr) \
    asm volatile("ldmatrix.sync.aligned.m8n8.x4.shared.b16 {%0,%1,%2,%3}, [%4];" \
        : "=r"(r0), "=r"(r1), "=r"(r2), "=r"(r3) : "r"(addr))

#define LDSM4T(r0, r1, r2, r3, addr) \
    asm volatile("ldmatrix.sync.aligned.m8n8.x4.trans.shared.b16 {%0,%1,%2,%3}, [%4];" \
        : "=r"(r0), "=r"(r1), "=r"(r2), "=r"(r3) : "r"(addr))

#define MMA_F16(d, a, b) \
    asm volatile("mma.sync.aligned.m16n8k16.row.col.f32.f16.f16.f32 " \
        "{%0,%1,%2,%3}, {%4,%5,%6,%7}, {%8,%9}, {%0,%1,%2,%3};" \
        : "+f"(d[0]), "+f"(d[1]), "+f"(d[2]), "+f"(d[3]) \
        : "r"(a[0]), "r"(a[1]), "r"(a[2]), "r"(a[3]), "r"(b[0]), "r"(b[1]))

__global__ void __launch_bounds__(256, 2) gemm_h(
    const __half* __restrict__ A, int K, int mode, const void* __restrict__ aux,
    const __half* __restrict__ B0, void* __restrict__ C0, int N0, int nb0,
    const __half* __restrict__ B1, void* __restrict__ C1, int N1, int nb1,
    const __half* __restrict__ B2, void* __restrict__ C2, int N2, int nb2)
{
    extern __shared__ __half smem[];
    unsigned sbase = (unsigned)__cvta_generic_to_shared(smem);

    int bx = blockIdx.x;
    const __half* Bw; void* C; int N; int bnb;
    if (bx < nb0)            { Bw = B0; C = C0; N = N0; bnb = bx; }
    else if (bx < nb0 + nb1) { Bw = B1; C = C1; N = N1; bnb = bx - nb0; }
    else                     { Bw = B2; C = C2; N = N2; bnb = bx - nb0 - nb1; }

    int tid  = threadIdx.x;
    int bm = blockIdx.y * 128;
    int bn = bnb * 128;
    int lane = tid & 31, warp = tid >> 5;
    int wm = warp >> 1, wn = warp & 1;
    int g  = lane >> 2, tig = lane & 3;

    unsigned dstoff[4];
    const __half* srcA[4];
    const __half* srcB[4];
    #pragma unroll
    for (int i = 0; i < 4; i++) {
        int lin = tid + i * 256;
        int row = lin >> 3, c = lin & 7;
        dstoff[i] = (unsigned)(row * 128 + ((c ^ (row & 7)) << 4));
        srcA[i] = A  + (size_t)(bm + row) * K + c * 8;
        srcB[i] = Bw + (size_t)(bn + row) * K + c * 8;
    }

    int t4 = lane >> 3;
    unsigned aoff[2][4], boff[4][4];
    #pragma unroll
    for (int mi = 0; mi < 2; mi++) {
        int row = wm * 32 + mi * 16 + (lane & 7) + (t4 & 1) * 8;
        #pragma unroll
        for (int ks = 0; ks < 4; ks++) {
            int chunk = 2 * ks + (t4 >> 1);
            aoff[mi][ks] = (unsigned)(row * 128 + ((chunk ^ (row & 7)) << 4));
        }
    }
    #pragma unroll
    for (int np = 0; np < 4; np++) {
        int row = wn * 64 + np * 16 + (lane & 7) + (t4 >> 1) * 8;
        #pragma unroll
        for (int ks = 0; ks < 4; ks++) {
            int chunk = 2 * ks + (t4 & 1);
            boff[np][ks] = (unsigned)(row * 128 + ((chunk ^ (row & 7)) << 4));
        }
    }

    float acc[2][8][4];
    #pragma unroll
    for (int mi = 0; mi < 2; mi++)
        #pragma unroll
        for (int ni = 0; ni < 8; ni++)
            #pragma unroll
            for (int q = 0; q < 4; q++) acc[mi][ni][q] = 0.f;

    const int NT = K >> 6;

    #pragma unroll
    for (int s = 0; s < STAGES - 1; s++) {
        unsigned da = sbase + (unsigned)s * 32768u;
        unsigned db = da + 16384u;
        #pragma unroll
        for (int i = 0; i < 4; i++) {
            CP_ASYNC16(da + dstoff[i], srcA[i] + (size_t)s * 64);
            CP_ASYNC16(db + dstoff[i], srcB[i] + (size_t)s * 64);
        }
        CP_COMMIT();
    }

    for (int kt = 0; kt < NT; kt++) {
        int st = kt % STAGES;
        CP_WAIT(STAGES - 2);
        __syncthreads();

        int pf = kt + STAGES - 1;
        if (pf < NT) {
            int pst = pf % STAGES;
            unsigned da = sbase + (unsigned)pst * 32768u;
            unsigned db = da + 16384u;
            #pragma unroll
            for (int i = 0; i < 4; i++) {
                CP_ASYNC16(da + dstoff[i], srcA[i] + (size_t)pf * 64);
                CP_ASYNC16(db + dstoff[i], srcB[i] + (size_t)pf * 64);
            }
        }
        CP_COMMIT();

        unsigned AsB = sbase + (unsigned)st * 32768u;
        unsigned BsB = AsB + 16384u;

        #pragma unroll
        for (int ks = 0; ks < 4; ks++) {
            unsigned af[2][4];
            LDSM4(af[0][0], af[0][1], af[0][2], af[0][3], AsB + aoff[0][ks]);
            LDSM4(af[1][0], af[1][1], af[1][2], af[1][3], AsB + aoff[1][ks]);
            unsigned bf[8][2];
            #pragma unroll
            for (int np = 0; np < 4; np++)
                LDSM4(bf[2*np][0], bf[2*np][1], bf[2*np+1][0], bf[2*np+1][1],
                      BsB + boff[np][ks]);
            #pragma unroll
            for (int mi = 0; mi < 2; mi++)
                #pragma unroll
                for (int ni = 0; ni < 8; ni++)
                    MMA_F16(acc[mi][ni], af[mi], bf[ni]);
        }
    }

    #pragma unroll
    for (int mi = 0; mi < 2; mi++) {
        int row0 = bm + wm * 32 + mi * 16 + g;
        #pragma unroll
        for (int half = 0; half < 2; half++) {
            int row = row0 + half * 8;
            size_t rowoff = (size_t)row * N;
            #pragma unroll
            for (int ni = 0; ni < 8; ni++) {
                int col = bn + wn * 64 + ni * 8 + 2 * tig;
                size_t idx = rowoff + col;
                float vx = acc[mi][ni][half * 2 + 0];
                float vy = acc[mi][ni][half * 2 + 1];
                if (mode == 1) {
                    float2 rsd = *(const float2*)((const float*)aux + idx);
                    vx += rsd.x; vy += rsd.y;
                    float2 o = { vx, vy };
                    *(float2*)((float*)C + idx) = o;
                } else {
                    if (mode == 2) {
                        __half2 gh = *(const __half2*)((const __half*)aux + idx);
                        float2 gf = __half22float2(gh);
                        vx *= gf.x / (1.f + __expf(-gf.x));
                        vy *= gf.y / (1.f + __expf(-gf.y));
                    }
                    __half2 o = __floats2half2_rn(vx, vy);
                    *(__half2*)((__half*)C + idx) = o;
                }
            }
        }
    }
}

// ---------------- usproj via fp16 MMA (+ in-register RoPE) ----------------
// per block: one head h, 64 bt rows. out = in[64x32] @ Us[64x32]^T, RoPE, pack half.
// warp cols: {wn*16+[0,16)} U {wn*16+32+[0,16)} so each thread holds both RoPE halves.
__global__ void __launch_bounds__(256) usproj_mma(
    const __half* __restrict__ qr, const __half* __restrict__ kr, const __half* __restrict__ vr,
    const __half* __restrict__ qUh, const __half* __restrict__ kUh, const __half* __restrict__ vUh,
    __half* __restrict__ qb, __half* __restrict__ kb, __half* __restrict__ vb,
    const float* __restrict__ rc, const float* __restrict__ rs)
{
    __shared__ __align__(16) __half As[64 * 40];   // pitch 40 halves (80B), conflict-free
    __shared__ __align__(16) __half Bs[64 * 40];

    int y = blockIdx.y;
    const __half* in; const __half* Uh; __half* out; int heads, h, rope;
    float scale = 1.0f;
    if (y < 32)      { in = qr; Uh = qUh; out = qb; heads = 32; h = y;      rope = 1; scale = 0.125f * LOG2E; }
    else if (y < 40) { in = kr; Uh = kUh; out = kb; heads = 8;  h = y - 32; rope = 1; }
    else             { in = vr; Uh = vUh; out = vb; heads = 8;  h = y - 40; rope = 0; }

    int bt0 = blockIdx.x * 64;
    int tid = threadIdx.x;
    int ldin = heads * 32;
    int lane = tid & 31, warp = tid >> 5;
    int g = lane >> 2, tig = lane & 3;
    int t4 = lane >> 3;
    int wm = warp >> 1, wn = warp & 1;

    // stage A (activations) and B (Us) : row -> row*40 halves, chunk c (0..3) 8 halves
    {
        int row = tid >> 2, c = tid & 3;
        *(uint4*)(As + row * 40 + c * 8) = *(const uint4*)(in + (size_t)(bt0 + row) * ldin + h * 32 + c * 8);
        *(uint4*)(Bs + row * 40 + c * 8) = *(const uint4*)(Uh + ((size_t)h * 64 + row) * 32 + c * 8);
    }
    __syncthreads();

    unsigned AsB = (unsigned)__cvta_generic_to_shared(As);
    unsigned BsB = (unsigned)__cvta_generic_to_shared(Bs);

    unsigned aoff[2], boff[2][2];
    {
        int rowA = wm * 16 + (lane & 7) + (t4 & 1) * 8;
        #pragma unroll
        for (int ks = 0; ks < 2; ks++)
            aoff[ks] = (unsigned)(rowA * 80 + (2 * ks + (t4 >> 1)) * 16);
        #pragma unroll
        for (int np = 0; np < 2; np++) {
            int rowB = wn * 16 + np * 32 + (lane & 7) + (t4 >> 1) * 8;
            #pragma unroll
            for (int ks = 0; ks < 2; ks++)
                boff[np][ks] = (unsigned)(rowB * 80 + (2 * ks + (t4 & 1)) * 16);
        }
    }

    float acc[4][4];     // [np*2+ni][c]
    #pragma unroll
    for (int i = 0; i < 4; i++)
        #pragma unroll
        for (int c = 0; c < 4; c++) acc[i][c] = 0.f;

    #pragma unroll
    for (int ks = 0; ks < 2; ks++) {
        unsigned af[4];
        LDSM4(af[0], af[1], af[2], af[3], AsB + aoff[ks]);
        #pragma unroll
        for (int np = 0; np < 2; np++) {
            unsigned bf[4];
            LDSM4(bf[0], bf[1], bf[2], bf[3], BsB + boff[np][ks]);
            unsigned b0[2] = { bf[0], bf[1] };
            unsigned b1[2] = { bf[2], bf[3] };
            MMA_F16(acc[np*2 + 0], af, b0);
            MMA_F16(acc[np*2 + 1], af, b1);
        }
    }

    // epilogue: RoPE in-register (np=0 holds d, np=1 holds d+32), pack half
    int r0 = wm * 16 + g;
    #pragma unroll
    for (int hf = 0; hf < 2; hf++) {
        int r = r0 + hf * 8;
        int bt = bt0 + r; int bb = bt >> 10; int t = bt & 1023;
        size_t base = (((size_t)(bb * heads + h)) * Tv + t) * 64;
        #pragma unroll
        for (int ni = 0; ni < 2; ni++) {
            int col = wn * 16 + ni * 8 + 2 * tig;
            float x1a = acc[ni][hf*2 + 0],     x1b = acc[ni][hf*2 + 1];
            float x2a = acc[2 + ni][hf*2 + 0], x2b = acc[2 + ni][hf*2 + 1];
            if (rope) {
                float2 cc = *(const float2*)(rc + t * 32 + col);
                float2 sn = *(const float2*)(rs + t * 32 + col);
                float o1a = (x1a * cc.x - x2a * sn.x) * scale;
                float o1b = (x1b * cc.y - x2b * sn.y) * scale;
                float o2a = (x2a * cc.x + x1a * sn.x) * scale;
                float o2b = (x2b * cc.y + x1b * sn.y) * scale;
                *(__half2*)(out + base + col)      = __floats2half2_rn(o1a, o1b);
                *(__half2*)(out + base + col + 32) = __floats2half2_rn(o2a, o2b);
            } else {
                *(__half2*)(out + base + col)      = __floats2half2_rn(x1a, x1b);
                *(__half2*)(out + base + col + 32) = __floats2half2_rn(x2a, x2b);
            }
        }
    }
}

// ---------------- flash attention, fp16 MMA, in-register softmax (base-2), double-buffered KV ----------------
#define ATTN_SMEM 40960
__global__ void __launch_bounds__(256, 2) attn_kernel(const __half* __restrict__ q,
                                                      const __half* __restrict__ k,
                                                      const __half* __restrict__ v,
                                                      __half* __restrict__ ctx)
{
    extern __shared__ char asmem[];
    __shared__ float mrow[64], lrow[64];
    __shared__ float pmax[128], psum[128];

    unsigned sb  = (unsigned)__cvta_generic_to_shared(asmem);
    unsigned QsB = sb;

    int tid = threadIdx.x;
    int bh = blockIdx.y; int b = bh >> 5; int h = bh & 31; int hk = h >> 2;
    int q0 = blockIdx.x * 64;
    int lane = tid & 31, warp = tid >> 5;
    int g = lane >> 2, tig = lane & 3;
    int t4 = lane >> 3;
    int wq = warp >> 1;
    int wn = warp & 1;

    const __half* kb0 = k + ((size_t)(b * 8 + hk)) * Tv * 64;
    const __half* vb0 = v + ((size_t)(b * 8 + hk)) * Tv * 64;

    int cprow[2], cpc[2];
    unsigned cpoff[2];
    #pragma unroll
    for (int kk = 0; kk < 2; kk++) {
        int lin = tid + kk * 256;
        cprow[kk] = lin >> 3; cpc[kk] = lin & 7;
        cpoff[kk] = (unsigned)(cprow[kk] * 128 + ((cpc[kk] ^ (cprow[kk] & 7)) << 4));
    }

    {
        unsigned kbB = sb + 8192u, vbB = sb + 16384u;
        #pragma unroll
        for (int kk = 0; kk < 2; kk++) {
            size_t off = ((size_t)cprow[kk]) * 64 + cpc[kk] * 8;
            CP_ASYNC16(kbB + cpoff[kk], kb0 + off);
            CP_ASYNC16(vbB + cpoff[kk], vb0 + off);
        }
        CP_COMMIT();
    }

    const __half* qbase = q + (((size_t)(b * 32 + h)) * Tv + q0) * 64;
    #pragma unroll
    for (int kk = 0; kk < 2; kk++) {
        int lin = tid + kk * 256;
        int row = lin >> 3, c = lin & 7;
        uint4 u = *(const uint4*)(qbase + (size_t)row * 64 + c * 8);
        *(uint4*)(asmem + row * 128 + ((c ^ (row & 7)) << 4)) = u;
    }
    if (tid < 64) { mrow[tid] = -INFINITY; lrow[tid] = 0.f; }

    unsigned aoffQ[4], boffK[2][4], voffV[2][4];
    {
        int rowA = wq * 16 + (lane & 7) + (t4 & 1) * 8;
        #pragma unroll
        for (int ks = 0; ks < 4; ks++) {
            int ca = 2 * ks + (t4 >> 1);
            aoffQ[ks] = (unsigned)(rowA * 128 + ((ca ^ (rowA & 7)) << 4));
        }
        #pragma unroll
        for (int nb = 0; nb < 2; nb++) {
            int rowB = wn * 32 + nb * 16 + (lane & 7) + (t4 >> 1) * 8;
            #pragma unroll
            for (int ks = 0; ks < 4; ks++) {
                int cb = 2 * ks + (t4 & 1);
                boffK[nb][ks] = (unsigned)(rowB * 128 + ((cb ^ (rowB & 7)) << 4));
            }
        }
        #pragma unroll
        for (int t = 0; t < 2; t++) {
            int rowV = wn * 32 + t * 16 + (lane & 7) + (t4 & 1) * 8;
            #pragma unroll
            for (int np = 0; np < 4; np++) {
                int cv = np * 2 + (t4 >> 1);
                voffV[t][np] = (unsigned)(rowV * 128 + ((cv ^ (rowV & 7)) << 4));
            }
        }
    }

    int r0 = wq * 16 + g, r1 = r0 + 8;
    float cacc[8][4];
    #pragma unroll
    for (int ni = 0; ni < 8; ni++)
        #pragma unroll
        for (int c = 0; c < 4; c++) cacc[ni][c] = 0.f;

    int ntile = (q0 >> 6) + 1;
    for (int kt = 0; kt < ntile; kt++) {
        int buf = kt & 1;
        CP_WAIT(0);
        __syncthreads();

        if (kt + 1 < ntile) {
            unsigned kbB = sb + 8192u + (unsigned)(buf ^ 1) * 16384u;
            unsigned vbB = kbB + 8192u;
            #pragma unroll
            for (int kk = 0; kk < 2; kk++) {
                size_t off = ((size_t)((kt + 1) * 64 + cprow[kk])) * 64 + cpc[kk] * 8;
                CP_ASYNC16(kbB + cpoff[kk], kb0 + off);
                CP_ASYNC16(vbB + cpoff[kk], vb0 + off);
            }
            CP_COMMIT();
        }

        unsigned KsB = sb + 8192u + (unsigned)buf * 16384u;
        unsigned VsB = KsB + 8192u;

        float sacc[4][4] = {};
        #pragma unroll
        for (int ks = 0; ks < 4; ks++) {
            unsigned af[4];
            LDSM4(af[0], af[1], af[2], af[3], QsB + aoffQ[ks]);
            #pragma unroll
            for (int nb = 0; nb < 2; nb++) {
                unsigned bf[4];
                LDSM4(bf[0], bf[1], bf[2], bf[3], KsB + boffK[nb][ks]);
                unsigned b0[2] = { bf[0], bf[1] };
                unsigned b1[2] = { bf[2], bf[3] };
                MMA_F16(sacc[nb*2 + 0], af, b0);
                MMA_F16(sacc[nb*2 + 1], af, b1);
            }
        }

        if (kt == ntile - 1) {
            int qi0 = q0 + r0, qi1 = q0 + r1;
            #pragma unroll
            for (int ni = 0; ni < 4; ni++) {
                int kc = kt * 64 + wn * 32 + ni * 8 + 2 * tig;
                if (kc > qi0)     sacc[ni][0] = -INFINITY;
                if (kc + 1 > qi0) sacc[ni][1] = -INFINITY;
                if (kc > qi1)     sacc[ni][2] = -INFINITY;
                if (kc + 1 > qi1) sacc[ni][3] = -INFINITY;
            }
        }

        float pm0 = -INFINITY, pm1 = -INFINITY;
        #pragma unroll
        for (int ni = 0; ni < 4; ni++) {
            pm0 = fmaxf(pm0, fmaxf(sacc[ni][0], sacc[ni][1]));
            pm1 = fmaxf(pm1, fmaxf(sacc[ni][2], sacc[ni][3]));
        }
        pm0 = fmaxf(pm0, __shfl_xor_sync(0xffffffffu, pm0, 1));
        pm0 = fmaxf(pm0, __shfl_xor_sync(0xffffffffu, pm0, 2));
        pm1 = fmaxf(pm1, __shfl_xor_sync(0xffffffffu, pm1, 1));
        pm1 = fmaxf(pm1, __shfl_xor_sync(0xffffffffu, pm1, 2));
        if (tig == 0) { pmax[wn * 64 + r0] = pm0; pmax[wn * 64 + r1] = pm1; }
        __syncthreads();

        float mo0 = mrow[r0], mo1 = mrow[r1];
        float mx0 = fmaxf(mo0, fmaxf(pmax[r0], pmax[64 + r0]));
        float mx1 = fmaxf(mo1, fmaxf(pmax[r1], pmax[64 + r1]));
        float rsc0 = ex2f(mo0 - mx0);
        float rsc1 = ex2f(mo1 - mx1);

        unsigned pf[4][2];
        float s0 = 0.f, s1 = 0.f;
        #pragma unroll
        for (int ni = 0; ni < 4; ni++) {
            float p0 = ex2f(sacc[ni][0] - mx0);
            float p1 = ex2f(sacc[ni][1] - mx0);
            float p2 = ex2f(sacc[ni][2] - mx1);
            float p3 = ex2f(sacc[ni][3] - mx1);
            s0 += p0 + p1; s1 += p2 + p3;
            __half2 h01 = __floats2half2_rn(p0, p1);
            __half2 h23 = __floats2half2_rn(p2, p3);
            pf[ni][0] = *(unsigned*)&h01;
            pf[ni][1] = *(unsigned*)&h23;
        }
        s0 += __shfl_xor_sync(0xffffffffu, s0, 1);
        s0 += __shfl_xor_sync(0xffffffffu, s0, 2);
        s1 += __shfl_xor_sync(0xffffffffu, s1, 1);
        s1 += __shfl_xor_sync(0xffffffffu, s1, 2);
        if (tig == 0) { psum[wn * 64 + r0] = s0; psum[wn * 64 + r1] = s1; }

        #pragma unroll
        for (int ni = 0; ni < 8; ni++) {
            cacc[ni][0] *= rsc0; cacc[ni][1] *= rsc0;
            cacc[ni][2] *= rsc1; cacc[ni][3] *= rsc1;
        }

        #pragma unroll
        for (int t = 0; t < 2; t++) {
            unsigned af[4] = { pf[2*t][0], pf[2*t][1], pf[2*t+1][0], pf[2*t+1][1] };
            #pragma unroll
            for (int np = 0; np < 4; np++) {
                unsigned vf[4];
                LDSM4T(vf[0], vf[1], vf[2], vf[3], VsB + voffV[t][np]);
                unsigned b0[2] = { vf[0], vf[1] };
                unsigned b1[2] = { vf[2], vf[3] };
                MMA_F16(cacc[np*2 + 0], af, b0);
                MMA_F16(cacc[np*2 + 1], af, b1);
            }
        }
        __syncthreads();

        if (wn == 0 && tig == 0) {
            lrow[r0] = lrow[r0] * rsc0 + psum[r0] + psum[64 + r0];
            lrow[r1] = lrow[r1] * rsc1 + psum[r1] + psum[64 + r1];
            mrow[r0] = mx0;
            mrow[r1] = mx1;
        }
    }
    __syncthreads();

    float* Ored = (float*)asmem;
    if (wn == 1) {
        #pragma unroll
        for (int ni = 0; ni < 8; ni++) {
            int col = ni * 8 + 2 * tig;
            *(float2*)(Ored + r0 * 68 + col) = make_float2(cacc[ni][0], cacc[ni][1]);
            *(float2*)(Ored + r1 * 68 + col) = make_float2(cacc[ni][2], cacc[ni][3]);
        }
    }
    __syncthreads();
    if (wn == 0) {
        float inv0 = 1.f / lrow[r0];
        float inv1 = 1.f / lrow[r1];
        #pragma unroll
        for (int ni = 0; ni < 8; ni++) {
            int col = ni * 8 + 2 * tig;
            float2 a0 = *(float2*)(Ored + r0 * 68 + col);
            float2 a1 = *(float2*)(Ored + r1 * 68 + col);
            __half2 o0 = __floats2half2_rn((cacc[ni][0] + a0.x) * inv0,
                                           (cacc[ni][1] + a0.y) * inv0);
            __half2 o1 = __floats2half2_rn((cacc[ni][2] + a1.x) * inv1,
                                           (cacc[ni][3] + a1.y) * inv1);
            size_t ad0 = ((size_t)(b * Tv + q0 + r0)) * Dv + h * 64 + col;
            size_t ad1 = ((size_t)(b * Tv + q0 + r1)) * Dv + h * 64 + col;
            *(__half2*)(ctx + ad0) = o0;
            *(__half2*)(ctx + ad1) = o1;
        }
    }
}

// ---------------- launch ----------------
extern "C" void kernel_launch(void* const* d_in, const int* in_sizes, int n_in,
                              void* d_out, int out_size)
{
    const float* x     = (const float*)d_in[0];
    const float* ln1_w = (const float*)d_in[1];
    const float* ln2_w = (const float*)d_in[2];
    const float* q_Us  = (const float*)d_in[3];
    const float* q_V   = (const float*)d_in[4];
    const float* k_Us  = (const float*)d_in[5];
    const float* k_V   = (const float*)d_in[6];
    const float* v_Us  = (const float*)d_in[7];
    const float* v_V   = (const float*)d_in[8];
    const float* o_Us  = (const float*)d_in[9];
    const float* o_V   = (const float*)d_in[10];
    const float* g_Usw = (const float*)d_in[11];
    const float* g_Vw  = (const float*)d_in[12];
    const float* u_Usw = (const float*)d_in[13];
    const float* u_Vw  = (const float*)d_in[14];
    const float* d_Usw = (const float*)d_in[15];
    const float* d_Vw  = (const float*)d_in[16];
    float* out = (float*)d_out;

    __half *h1, *qr, *kr, *vr, *qb, *kb, *vb, *ctx, *orr, *h2, *gr, *ur, *gg, *ff, *dr, *wts;
    __half *qUh, *kUh, *vUh;
    float *x1, *rc, *rs;
    cudaGetSymbolAddress((void**)&h1,  g_h1);
    cudaGetSymbolAddress((void**)&qr,  g_qr);
    cudaGetSymbolAddress((void**)&kr,  g_kr);
    cudaGetSymbolAddress((void**)&vr,  g_vr);
    cudaGetSymbolAddress((void**)&qb,  g_q);
    cudaGetSymbolAddress((void**)&kb,  g_k);
    cudaGetSymbolAddress((void**)&vb,  g_v);
    cudaGetSymbolAddress((void**)&ctx, g_ctx);
    cudaGetSymbolAddress((void**)&orr, g_or);
    cudaGetSymbolAddress((void**)&x1,  g_x1);
    cudaGetSymbolAddress((void**)&h2,  g_h2);
    cudaGetSymbolAddress((void**)&gr,  g_gr);
    cudaGetSymbolAddress((void**)&ur,  g_ur);
    cudaGetSymbolAddress((void**)&gg,  g_g);
    cudaGetSymbolAddress((void**)&ff,  g_ff);
    cudaGetSymbolAddress((void**)&dr,  g_dr);
    cudaGetSymbolAddress((void**)&rc,  g_ropec);
    cudaGetSymbolAddress((void**)&rs,  g_ropes);
    cudaGetSymbolAddress((void**)&wts, g_wts);
    cudaGetSymbolAddress((void**)&qUh, g_qush);
    cudaGetSymbolAddress((void**)&kUh, g_kush);
    cudaGetSymbolAddress((void**)&vUh, g_vush);

    static cudaStream_t s2 = 0;
    static cudaEvent_t evFork = 0, evJoin = 0;
    static int init_done = 0;
    if (!init_done) {
        cudaFuncSetAttribute(gemm_h, cudaFuncAttributeMaxDynamicSharedMemorySize, 98304);
        cudaFuncSetAttribute(attn_kernel, cudaFuncAttributeMaxDynamicSharedMemorySize, ATTN_SMEM);
        cudaStreamCreateWithFlags(&s2, cudaStreamNonBlocking);
        cudaEventCreateWithFlags(&evFork, cudaEventDisableTiming);
        cudaEventCreateWithFlags(&evJoin, cudaEventDisableTiming);
        init_done = 1;
    }
    const int SM = 98304;
    dim3 blk(256);

    // fork: MLP/O weight conversion on side stream
    cudaEventRecord(evFork, 0);
    cudaStreamWaitEvent(s2, evFork, 0);
    prep_mlp<<<NW2BLK, blk, 0, s2>>>(wts, o_V, o_Us, g_Vw, u_Vw, g_Usw, u_Usw, d_Vw, d_Usw);
    cudaEventRecord(evJoin, s2);

    // main stream
    prep_qkv<<<NW1BLK + BT + NROPE + NQUS + 2*NKUS, blk>>>(
        wts, q_V, k_V, v_V, x, ln1_w, h1, rc, rs,
        q_Us, k_Us, v_Us, qUh, kUh, vUh);

    gemm_h<<<dim3(12, 32), blk, SM>>>(h1, Dv, 0, nullptr,
        wts + W_QV, qr, Hv*Rv, 8,  wts + W_KV, kr, HKv*Rv, 2,  wts + W_VV, vr, HKv*Rv, 2);

    usproj_mma<<<dim3(BT/64, 48), blk>>>(qr, kr, vr, qUh, kUh, vUh, qb, kb, vb, rc, rs);

    attn_kernel<<<dim3(Tv/64, Bv*Hv), blk, ATTN_SMEM>>>(qb, kb, vb, ctx);

    cudaStreamWaitEvent(0, evJoin, 0);

    gemm_h<<<dim3(8, 32), blk, SM>>>(ctx, Dv, 0, nullptr,
        wts + W_OV, orr, ROv, 8,  nullptr, nullptr, 0, 0,  nullptr, nullptr, 0, 0);
    gemm_h<<<dim3(16, 32), blk, SM>>>(orr, ROv, 1, x,
        wts + W_OUS, x1, Dv, 16,  nullptr, nullptr, 0, 0,  nullptr, nullptr, 0, 0);

    rms_kernel<<<BT, blk>>>(x1, ln2_w, h2);

    gemm_h<<<dim3(16, 32), blk, SM>>>(h2, Dv, 0, nullptr,
        wts + W_GV, gr, RFv, 8,  wts + W_UV, ur, RFv, 8,  nullptr, nullptr, 0, 0);

    gemm_h<<<dim3(44, 32), blk, SM>>>(gr, RFv, 0, nullptr,
        wts + W_GUS, gg, Iv, 44,  nullptr, nullptr, 0, 0,  nullptr, nullptr, 0, 0);
    gemm_h<<<dim3(44, 32), blk, SM>>>(ur, RFv, 2, gg,
        wts + W_UUS, ff, Iv, 44,  nullptr, nullptr, 0, 0,  nullptr, nullptr, 0, 0);

    gemm_h<<<dim3(8, 32), blk, SM>>>(ff, Iv, 0, nullptr,
        wts + W_DV, dr, RFv, 8,  nullptr, nullptr, 0, 0,  nullptr, nullptr, 0, 0);
    gemm_h<<<dim3(16, 32), blk, SM>>>(dr, RFv, 1, x1,
        wts + W_DUS, out, Dv, 16,  nullptr, nullptr, 0, 0,  nullptr, nullptr, 0, 0);
}